// round 1
// baseline (speedup 1.0000x reference)
#include <cuda_runtime.h>
#include <cstdint>
#include <cstddef>

// ---------------- problem constants ----------------
#define B_    4
#define N_X   4096
#define M_LAT 512
#define D_IN  768
#define D_LAT 1024
#define D_INR 1024
#define HEADS 16
#define DH    64
#define L_TOT (N_X + M_LAT)   // 4608

// ---------------- scratch (no allocs allowed) ----------------
__device__ float g_xn [(size_t)B_ * N_X  * D_IN ];        // 50.3 MB
__device__ float g_ln [(size_t)B_ * M_LAT * D_LAT];       // 8.4 MB
__device__ float g_q  [(size_t)B_ * M_LAT * D_INR];       // 8.4 MB
__device__ float g_kvx[(size_t)B_ * N_X  * 2 * D_INR];    // 134 MB
__device__ float g_kvl[(size_t)B_ * M_LAT * 2 * D_INR];   // 16.8 MB
__device__ float g_att[(size_t)B_ * M_LAT * D_INR];       // 8.4 MB

// ---------------- layernorm: one block per row ----------------
__global__ void layernorm_kernel(const float* __restrict__ in, float* __restrict__ out,
                                 const float* __restrict__ g, const float* __restrict__ b,
                                 int C) {
    const int row = blockIdx.x;
    const float* x = in + (size_t)row * C;
    float* y = out + (size_t)row * C;
    float s = 0.f, ss = 0.f;
    for (int i = threadIdx.x; i < C; i += blockDim.x) {
        float v = x[i]; s += v; ss += v * v;
    }
    __shared__ float red[2][32];
    #pragma unroll
    for (int o = 16; o; o >>= 1) {
        s  += __shfl_xor_sync(0xffffffffu, s,  o);
        ss += __shfl_xor_sync(0xffffffffu, ss, o);
    }
    int warp = threadIdx.x >> 5, lane = threadIdx.x & 31;
    if (lane == 0) { red[0][warp] = s; red[1][warp] = ss; }
    __syncthreads();
    int nw = blockDim.x >> 5;
    if (warp == 0) {
        s  = (lane < nw) ? red[0][lane] : 0.f;
        ss = (lane < nw) ? red[1][lane] : 0.f;
        #pragma unroll
        for (int o = 16; o; o >>= 1) {
            s  += __shfl_xor_sync(0xffffffffu, s,  o);
            ss += __shfl_xor_sync(0xffffffffu, ss, o);
        }
        if (lane == 0) { red[0][0] = s; red[1][0] = ss; }
    }
    __syncthreads();
    float invC = 1.f / (float)C;
    float mu  = red[0][0] * invC;
    float var = red[1][0] * invC - mu * mu;
    float rs  = rsqrtf(var + 1e-5f);
    for (int i = threadIdx.x; i < C; i += blockDim.x)
        y[i] = (x[i] - mu) * rs * g[i] + b[i];
}

// ---------------- per-head rmsnorm: one warp per 64-chunk ----------------
__global__ void rmsnorm_kernel(float* __restrict__ data, const float* __restrict__ g,
                               int nrows, int rowstride, int nchunks, float scale) {
    int wg   = (blockIdx.x * blockDim.x + threadIdx.x) >> 5;
    int lane = threadIdx.x & 31;
    int total = nrows * nchunks;
    if (wg >= total) return;
    int row = wg / nchunks;
    int chunk = wg - row * nchunks;
    float* p = data + (size_t)row * rowstride + chunk * DH;
    float v0 = p[lane], v1 = p[lane + 32];
    float ss = v0 * v0 + v1 * v1;
    #pragma unroll
    for (int o = 16; o; o >>= 1) ss += __shfl_xor_sync(0xffffffffu, ss, o);
    float norm = sqrtf(ss) * 0.125f;               // * 64^(-1/2)
    float r = scale / fmaxf(norm, 1e-8f);
    p[lane]      = v0 * r * g[lane];
    p[lane + 32] = v1 * r * g[lane + 32];
}

// ---------------- SGEMM: C[M,N] = A[M,K] @ W[N,K]^T (+bias) ----------------
// 128x128 tile, BK=8, 256 threads, 8x8 per thread.
__global__ void __launch_bounds__(256) sgemm_nt_kernel(
    const float* __restrict__ A, const float* __restrict__ W,
    const float* __restrict__ bias, float* __restrict__ C,
    int M, int N, int K) {
    __shared__ float As[8][128];
    __shared__ float Bs[8][128];
    const int tid = threadIdx.x;
    const int tx = tid & 15, ty = tid >> 4;
    const float* Ab = A + (size_t)blockIdx.y * 128 * K;
    const float* Wb = W + (size_t)blockIdx.x * 128 * K;
    float acc[8][8] = {};
    const int lr = tid >> 1;
    const int lc = (tid & 1) * 4;
    for (int k0 = 0; k0 < K; k0 += 8) {
        float4 av = *(const float4*)(Ab + (size_t)lr * K + k0 + lc);
        float4 wv = *(const float4*)(Wb + (size_t)lr * K + k0 + lc);
        As[lc + 0][lr] = av.x; As[lc + 1][lr] = av.y; As[lc + 2][lr] = av.z; As[lc + 3][lr] = av.w;
        Bs[lc + 0][lr] = wv.x; Bs[lc + 1][lr] = wv.y; Bs[lc + 2][lr] = wv.z; Bs[lc + 3][lr] = wv.w;
        __syncthreads();
        #pragma unroll
        for (int k = 0; k < 8; k++) {
            float4 a0 = *(const float4*)&As[k][ty * 4];
            float4 a1 = *(const float4*)&As[k][64 + ty * 4];
            float4 b0 = *(const float4*)&Bs[k][tx * 4];
            float4 b1 = *(const float4*)&Bs[k][64 + tx * 4];
            float ra[8] = {a0.x, a0.y, a0.z, a0.w, a1.x, a1.y, a1.z, a1.w};
            float rb[8] = {b0.x, b0.y, b0.z, b0.w, b1.x, b1.y, b1.z, b1.w};
            #pragma unroll
            for (int i = 0; i < 8; i++)
                #pragma unroll
                for (int j = 0; j < 8; j++)
                    acc[i][j] = fmaf(ra[i], rb[j], acc[i][j]);
        }
        __syncthreads();
    }
    const int rowbase = blockIdx.y * 128;
    const int colbase = blockIdx.x * 128;
    #pragma unroll
    for (int i = 0; i < 8; i++) {
        int r = rowbase + ((i < 4) ? (ty * 4 + i) : (64 + ty * 4 + i - 4));
        #pragma unroll
        for (int jj = 0; jj < 2; jj++) {
            int c = colbase + jj * 64 + tx * 4;
            float4 v;
            v.x = acc[i][jj * 4 + 0]; v.y = acc[i][jj * 4 + 1];
            v.z = acc[i][jj * 4 + 2]; v.w = acc[i][jj * 4 + 3];
            if (bias) { v.x += bias[c]; v.y += bias[c + 1]; v.z += bias[c + 2]; v.w += bias[c + 3]; }
            *(float4*)(C + (size_t)r * N + c) = v;
        }
    }
}

// ---------------- flash attention, fp32 ----------------
// Block: 64 queries x full key sweep (72 tiles of 64). 128 threads (16 tx x 8 ty),
// each thread: 8 rows x 4 cols. Smem exactly 48KB: Qs + KPs(K then P) + Vs,
// each 64x64 with bank-conflict-avoiding swizzles.
__device__ __forceinline__ int rotr6(int v) { return ((v >> 1) | ((v & 1) << 5)); }

__global__ void __launch_bounds__(128) attn_kernel(
    const float* __restrict__ q, const float* __restrict__ kvx,
    const float* __restrict__ kvl, const int* __restrict__ mask,
    float* __restrict__ out) {
    __shared__ float Qs [64 * 64];
    __shared__ float KPs[64 * 64];
    __shared__ float Vs [64 * 64];
    const int qt = blockIdx.x, h = blockIdx.y, b = blockIdx.z;
    const int tid = threadIdx.x;
    const int tx = tid & 15, ty = tid >> 4;

    const float* qb = q + ((size_t)(b * M_LAT + qt * 64)) * D_INR + h * DH;
    for (int idx = tid; idx < 4096; idx += 128) {
        int r = idx >> 6, d = idx & 63;
        Qs[(r << 6) + (d ^ r)] = qb[(size_t)r * D_INR + d];
    }

    float m_i[8], l_i[8], acc[8][4];
    #pragma unroll
    for (int i = 0; i < 8; i++) {
        m_i[i] = -3.0e38f; l_i[i] = 0.f;
        #pragma unroll
        for (int j = 0; j < 4; j++) acc[i][j] = 0.f;
    }
    int rot1[4];
    #pragma unroll
    for (int j = 0; j < 4; j++) rot1[j] = rotr6(tx * 4 + j);
    __syncthreads();

    for (int j0 = 0; j0 < L_TOT; j0 += 64) {
        const bool in_x = (j0 < N_X);
        const float* kvb = in_x
            ? kvx + ((size_t)(b * N_X + j0)) * (2 * D_INR) + h * DH
            : kvl + ((size_t)(b * M_LAT + (j0 - N_X))) * (2 * D_INR) + h * DH;
        for (int idx = tid; idx < 4096; idx += 128) {
            int r = idx >> 6, d = idx & 63;
            KPs[(r << 6) + (d ^ rotr6(r))] = kvb[(size_t)r * (2 * D_INR) + d];
            Vs [(r << 6) + rotr6(d)]       = kvb[(size_t)r * (2 * D_INR) + D_INR + d];
        }
        __syncthreads();

        // S = Q @ K^T (q already carries gamma & SCALE)
        float S[8][4];
        #pragma unroll
        for (int i = 0; i < 8; i++) { S[i][0] = 0.f; S[i][1] = 0.f; S[i][2] = 0.f; S[i][3] = 0.f; }
        #pragma unroll 4
        for (int d = 0; d < 64; d++) {
            float ra[8], rb[4];
            #pragma unroll
            for (int i = 0; i < 8; i++) {
                int row = ty * 8 + i;
                ra[i] = Qs[(row << 6) + (d ^ row)];
            }
            #pragma unroll
            for (int j = 0; j < 4; j++) {
                int col = tx * 4 + j;
                rb[j] = KPs[(col << 6) + (d ^ rot1[j])];
            }
            #pragma unroll
            for (int i = 0; i < 8; i++)
                #pragma unroll
                for (int j = 0; j < 4; j++)
                    S[i][j] = fmaf(ra[i], rb[j], S[i][j]);
        }
        if (in_x) {
            const int* mb = mask + b * N_X + j0 + tx * 4;
            #pragma unroll
            for (int j = 0; j < 4; j++)
                if (!mb[j]) {
                    #pragma unroll
                    for (int i = 0; i < 8; i++) S[i][j] = -3.0e38f;
                }
        }
        // online softmax (row groups live on 16-lane shfl groups)
        #pragma unroll
        for (int i = 0; i < 8; i++) {
            float mx = fmaxf(fmaxf(S[i][0], S[i][1]), fmaxf(S[i][2], S[i][3]));
            #pragma unroll
            for (int o = 1; o < 16; o <<= 1) mx = fmaxf(mx, __shfl_xor_sync(0xffffffffu, mx, o));
            float mnew = fmaxf(m_i[i], mx);
            float corr = __expf(m_i[i] - mnew);
            m_i[i] = mnew;
            float rs = 0.f;
            #pragma unroll
            for (int j = 0; j < 4; j++) {
                float p = __expf(S[i][j] - mnew);
                S[i][j] = p; rs += p;
            }
            #pragma unroll
            for (int o = 1; o < 16; o <<= 1) rs += __shfl_xor_sync(0xffffffffu, rs, o);
            l_i[i] = l_i[i] * corr + rs;
            #pragma unroll
            for (int j = 0; j < 4; j++) acc[i][j] *= corr;
        }
        __syncthreads();   // all done reading K before P overwrites KPs
        #pragma unroll
        for (int i = 0; i < 8; i++) {
            int row = ty * 8 + i;
            #pragma unroll
            for (int j = 0; j < 4; j++) {
                int col = tx * 4 + j;
                KPs[(row << 6) + (col ^ row)] = S[i][j];
            }
        }
        __syncthreads();
        // acc += P @ V
        #pragma unroll 4
        for (int jj = 0; jj < 64; jj++) {
            float pa[8], vb[4];
            #pragma unroll
            for (int i = 0; i < 8; i++) {
                int row = ty * 8 + i;
                pa[i] = KPs[(row << 6) + (jj ^ row)];
            }
            #pragma unroll
            for (int j = 0; j < 4; j++)
                vb[j] = Vs[(jj << 6) + rot1[j]];
            #pragma unroll
            for (int i = 0; i < 8; i++)
                #pragma unroll
                for (int j = 0; j < 4; j++)
                    acc[i][j] = fmaf(pa[i], vb[j], acc[i][j]);
        }
        __syncthreads();
    }

    float* ob = out + ((size_t)(b * M_LAT + qt * 64)) * D_INR + h * DH;
    #pragma unroll
    for (int i = 0; i < 8; i++) {
        float inv = 1.f / l_i[i];
        int row = ty * 8 + i;
        #pragma unroll
        for (int j = 0; j < 4; j++)
            ob[(size_t)row * D_INR + tx * 4 + j] = acc[i][j] * inv;
    }
}

// ---------------- launch ----------------
extern "C" void kernel_launch(void* const* d_in, const int* in_sizes, int n_in,
                              void* d_out, int out_size) {
    const float* x      = (const float*)d_in[0];
    const float* lat    = (const float*)d_in[1];
    const int*   mask   = (const int*)  d_in[2];
    const float* ln_x_g = (const float*)d_in[3];
    const float* ln_x_b = (const float*)d_in[4];
    const float* ln_l_g = (const float*)d_in[5];
    const float* ln_l_b = (const float*)d_in[6];
    const float* qn_g   = (const float*)d_in[7];
    const float* kn_g   = (const float*)d_in[8];
    const float* Wq     = (const float*)d_in[9];
    const float* Wkv    = (const float*)d_in[10];
    const float* Wlkv   = (const float*)d_in[11];
    const float* Wo     = (const float*)d_in[12];
    const float* bo     = (const float*)d_in[13];
    float* outp = (float*)d_out;

    float *xn, *ln, *qb, *kvx, *kvl, *att;
    cudaGetSymbolAddress((void**)&xn,  g_xn);
    cudaGetSymbolAddress((void**)&ln,  g_ln);
    cudaGetSymbolAddress((void**)&qb,  g_q);
    cudaGetSymbolAddress((void**)&kvx, g_kvx);
    cudaGetSymbolAddress((void**)&kvl, g_kvl);
    cudaGetSymbolAddress((void**)&att, g_att);

    // 1) layernorms
    layernorm_kernel<<<B_ * N_X,   256>>>(x,   xn, ln_x_g, ln_x_b, D_IN);
    layernorm_kernel<<<B_ * M_LAT, 256>>>(lat, ln, ln_l_g, ln_l_b, D_LAT);

    // 2) projections
    {
        dim3 g(D_INR / 128, (B_ * M_LAT) / 128);
        sgemm_nt_kernel<<<g, 256>>>(ln, Wq, nullptr, qb, B_ * M_LAT, D_INR, D_LAT);
    }
    {
        dim3 g((2 * D_INR) / 128, (B_ * N_X) / 128);
        sgemm_nt_kernel<<<g, 256>>>(xn, Wkv, nullptr, kvx, B_ * N_X, 2 * D_INR, D_IN);
    }
    {
        dim3 g((2 * D_INR) / 128, (B_ * M_LAT) / 128);
        sgemm_nt_kernel<<<g, 256>>>(ln, Wlkv, nullptr, kvl, B_ * M_LAT, 2 * D_INR, D_LAT);
    }

    // 3) head rmsnorms (q gets gamma * SCALE; k in-place inside kv buffers)
    rmsnorm_kernel<<<(B_ * M_LAT * HEADS) / 8, 256>>>(qb,  qn_g, B_ * M_LAT, D_INR,     HEADS, 0.125f);
    rmsnorm_kernel<<<(B_ * N_X  * HEADS) / 8, 256>>>(kvx, kn_g, B_ * N_X,  2 * D_INR, HEADS, 1.0f);
    rmsnorm_kernel<<<(B_ * M_LAT * HEADS) / 8, 256>>>(kvl, kn_g, B_ * M_LAT, 2 * D_INR, HEADS, 1.0f);

    // 4) attention
    {
        dim3 g(M_LAT / 64, HEADS, B_);
        attn_kernel<<<g, 128>>>(qb, kvx, kvl, mask, att);
    }

    // 5) output projection + bias
    {
        dim3 g(D_LAT / 128, (B_ * M_LAT) / 128);
        sgemm_nt_kernel<<<g, 256>>>(att, Wo, bo, outp, B_ * M_LAT, D_LAT, D_INR);
    }
}

// round 4
// speedup vs baseline: 1.2294x; 1.2294x over previous
#include <cuda_runtime.h>
#include <cuda_bf16.h>
#include <cstdint>
#include <cstddef>

// ---------------- problem constants ----------------
#define B_    4
#define N_X   4096
#define M_LAT 512
#define D_IN  768
#define D_LAT 1024
#define D_INR 1024
#define HEADS 16
#define DH    64
#define L_TOT (N_X + M_LAT)   // 4608

// ---------------- scratch (no allocs allowed) ----------------
__device__ float g_xn [(size_t)B_ * N_X  * D_IN ];
__device__ float g_ln [(size_t)B_ * M_LAT * D_LAT];
__device__ float g_q  [(size_t)B_ * M_LAT * D_INR];
__device__ float g_kvx[(size_t)B_ * N_X  * 2 * D_INR];
__device__ float g_kvl[(size_t)B_ * M_LAT * 2 * D_INR];
__device__ float g_att[(size_t)B_ * M_LAT * D_INR];

__device__ __forceinline__ uint32_t smem_u32(const void* p) {
    uint32_t a;
    asm("{ .reg .u64 t; cvta.to.shared.u64 t, %1; cvt.u32.u64 %0, t; }" : "=r"(a) : "l"(p));
    return a;
}

// =======================================================================
// split-bf16 GEMM via mma.sync (sm_80+ path; compiles on base sm_100):
// C[M,N] = A[M,K] @ W[N,K]^T (+bias), fp32 in/out.
// CTA tile 128x128, BK=32, 256 thr = 8 warps (2M x 4N), warp tile 64x32.
// =======================================================================
#define LDSB 40   // smem row stride in bf16 elems (80 bytes -> conflict-free ldmatrix)

__device__ __forceinline__ void cvt_hilo(float4 v, uint32_t& h01, uint32_t& h23,
                                         uint32_t& l01, uint32_t& l23) {
    __nv_bfloat16 h0 = __float2bfloat16_rn(v.x);
    __nv_bfloat16 h1 = __float2bfloat16_rn(v.y);
    __nv_bfloat16 h2 = __float2bfloat16_rn(v.z);
    __nv_bfloat16 h3 = __float2bfloat16_rn(v.w);
    __nv_bfloat16 l0 = __float2bfloat16_rn(v.x - __bfloat162float(h0));
    __nv_bfloat16 l1 = __float2bfloat16_rn(v.y - __bfloat162float(h1));
    __nv_bfloat16 l2 = __float2bfloat16_rn(v.z - __bfloat162float(h2));
    __nv_bfloat16 l3 = __float2bfloat16_rn(v.w - __bfloat162float(h3));
    h01 = ((uint32_t)__bfloat16_as_ushort(h1) << 16) | __bfloat16_as_ushort(h0);
    h23 = ((uint32_t)__bfloat16_as_ushort(h3) << 16) | __bfloat16_as_ushort(h2);
    l01 = ((uint32_t)__bfloat16_as_ushort(l1) << 16) | __bfloat16_as_ushort(l0);
    l23 = ((uint32_t)__bfloat16_as_ushort(l3) << 16) | __bfloat16_as_ushort(l2);
}

__device__ __forceinline__ void stage_tile(const float* __restrict__ G, int K, int k0,
                                           uint32_t sHi, uint32_t sLo, int tid) {
    const int c4 = tid & 7, r0 = tid >> 3;
    #pragma unroll
    for (int p = 0; p < 4; ++p) {
        int row = r0 + p * 32;
        float4 v = *(const float4*)(G + (size_t)row * K + k0 + c4 * 4);
        uint32_t h01, h23, l01, l23;
        cvt_hilo(v, h01, h23, l01, l23);
        uint32_t off = (uint32_t)(row * LDSB + c4 * 4) * 2;
        asm volatile("st.shared.v2.b32 [%0], {%1,%2};" :: "r"(sHi + off), "r"(h01), "r"(h23) : "memory");
        asm volatile("st.shared.v2.b32 [%0], {%1,%2};" :: "r"(sLo + off), "r"(l01), "r"(l23) : "memory");
    }
}

#define LDMX4(r0_, r1_, r2_, r3_, addr_) \
    asm volatile("ldmatrix.sync.aligned.m8n8.x4.shared.b16 {%0,%1,%2,%3}, [%4];" \
        : "=r"(r0_), "=r"(r1_), "=r"(r2_), "=r"(r3_) : "r"(addr_))

#define MMA16816(c_, a_, b0_, b1_) \
    asm volatile("mma.sync.aligned.m16n8k16.row.col.f32.bf16.bf16.f32 " \
        "{%0,%1,%2,%3}, {%4,%5,%6,%7}, {%8,%9}, {%0,%1,%2,%3};" \
        : "+f"((c_)[0]), "+f"((c_)[1]), "+f"((c_)[2]), "+f"((c_)[3]) \
        : "r"((a_)[0]), "r"((a_)[1]), "r"((a_)[2]), "r"((a_)[3]), "r"(b0_), "r"(b1_))

__global__ void __launch_bounds__(256, 1) gemm_mma_kernel(
    const float* __restrict__ A, const float* __restrict__ W,
    const float* __restrict__ bias, float* __restrict__ C,
    int M, int N, int K) {
    __shared__ __align__(16) uint16_t sAh[128 * LDSB], sAl[128 * LDSB];
    __shared__ __align__(16) uint16_t sBh[128 * LDSB], sBl[128 * LDSB];
    const int tid = threadIdx.x;
    const int lane = tid & 31, wid = tid >> 5;
    const int warp_m = wid & 1, warp_n = wid >> 1;

    const uint32_t uAh = smem_u32(sAh), uAl = smem_u32(sAl);
    const uint32_t uBh = smem_u32(sBh), uBl = smem_u32(sBl);

    const float* Ag = A + (size_t)blockIdx.y * 128 * K;
    const float* Wg = W + (size_t)blockIdx.x * 128 * K;

    // ldmatrix lane->address components
    const int a_m = (lane & 7) + ((lane >> 3) & 1) * 8;
    const int a_k = (lane >> 4) * 8;
    const int b_n = (lane & 7) + (lane >> 4) * 8;
    const int b_k = ((lane >> 3) & 1) * 8;

    float acc[4][4][4];
    #pragma unroll
    for (int i = 0; i < 4; i++)
        #pragma unroll
        for (int j = 0; j < 4; j++)
            #pragma unroll
            for (int t = 0; t < 4; t++) acc[i][j][t] = 0.f;

    for (int k0 = 0; k0 < K; k0 += 32) {
        __syncthreads();
        stage_tile(Ag, K, k0, uAh, uAl, tid);
        stage_tile(Wg, K, k0, uBh, uBl, tid);
        __syncthreads();

        #pragma unroll
        for (int ks = 0; ks < 2; ++ks) {
            uint32_t ah[4][4], al[4][4], bh[2][4], bl[2][4];
            #pragma unroll
            for (int mt = 0; mt < 4; ++mt) {
                uint32_t off = (uint32_t)((warp_m * 64 + mt * 16 + a_m) * LDSB + ks * 16 + a_k) * 2;
                LDMX4(ah[mt][0], ah[mt][1], ah[mt][2], ah[mt][3], uAh + off);
                LDMX4(al[mt][0], al[mt][1], al[mt][2], al[mt][3], uAl + off);
            }
            #pragma unroll
            for (int np = 0; np < 2; ++np) {
                uint32_t off = (uint32_t)((warp_n * 32 + np * 16 + b_n) * LDSB + ks * 16 + b_k) * 2;
                LDMX4(bh[np][0], bh[np][1], bh[np][2], bh[np][3], uBh + off);
                LDMX4(bl[np][0], bl[np][1], bl[np][2], bl[np][3], uBl + off);
            }
            #pragma unroll
            for (int mt = 0; mt < 4; ++mt) {
                #pragma unroll
                for (int nt = 0; nt < 4; ++nt) {
                    const int np = nt >> 1, sel = (nt & 1) * 2;
                    uint32_t bh0 = bh[np][sel], bh1 = bh[np][sel + 1];
                    uint32_t bl0 = bl[np][sel], bl1 = bl[np][sel + 1];
                    MMA16816(acc[mt][nt], ah[mt], bh0, bh1);
                    MMA16816(acc[mt][nt], ah[mt], bl0, bl1);
                    MMA16816(acc[mt][nt], al[mt], bh0, bh1);
                }
            }
        }
    }

    // epilogue
    const int g = lane >> 2, c2 = (lane & 3) * 2;
    const int rowb = blockIdx.y * 128 + warp_m * 64;
    const int colb = blockIdx.x * 128 + warp_n * 32;
    #pragma unroll
    for (int mt = 0; mt < 4; ++mt) {
        #pragma unroll
        for (int nt = 0; nt < 4; ++nt) {
            int row = rowb + mt * 16 + g;
            int col = colb + nt * 8 + c2;
            float b0 = 0.f, b1 = 0.f;
            if (bias) { b0 = bias[col]; b1 = bias[col + 1]; }
            float2 v0 = make_float2(acc[mt][nt][0] + b0, acc[mt][nt][1] + b1);
            float2 v1 = make_float2(acc[mt][nt][2] + b0, acc[mt][nt][3] + b1);
            *(float2*)(C + (size_t)row * N + col) = v0;
            *(float2*)(C + (size_t)(row + 8) * N + col) = v1;
        }
    }
}

// ---------------- layernorm: one block per row ----------------
__global__ void layernorm_kernel(const float* __restrict__ in, float* __restrict__ out,
                                 const float* __restrict__ g, const float* __restrict__ b,
                                 int C) {
    const int row = blockIdx.x;
    const float* x = in + (size_t)row * C;
    float* y = out + (size_t)row * C;
    float s = 0.f, ss = 0.f;
    for (int i = threadIdx.x; i < C; i += blockDim.x) {
        float v = x[i]; s += v; ss += v * v;
    }
    __shared__ float red[2][32];
    #pragma unroll
    for (int o = 16; o; o >>= 1) {
        s  += __shfl_xor_sync(0xffffffffu, s,  o);
        ss += __shfl_xor_sync(0xffffffffu, ss, o);
    }
    int warp = threadIdx.x >> 5, lane = threadIdx.x & 31;
    if (lane == 0) { red[0][warp] = s; red[1][warp] = ss; }
    __syncthreads();
    int nw = blockDim.x >> 5;
    if (warp == 0) {
        s  = (lane < nw) ? red[0][lane] : 0.f;
        ss = (lane < nw) ? red[1][lane] : 0.f;
        #pragma unroll
        for (int o = 16; o; o >>= 1) {
            s  += __shfl_xor_sync(0xffffffffu, s,  o);
            ss += __shfl_xor_sync(0xffffffffu, ss, o);
        }
        if (lane == 0) { red[0][0] = s; red[1][0] = ss; }
    }
    __syncthreads();
    float invC = 1.f / (float)C;
    float mu  = red[0][0] * invC;
    float var = red[1][0] * invC - mu * mu;
    float rs  = rsqrtf(var + 1e-5f);
    for (int i = threadIdx.x; i < C; i += blockDim.x)
        y[i] = (x[i] - mu) * rs * g[i] + b[i];
}

// ---------------- per-head rmsnorm: one warp per 64-chunk ----------------
__global__ void rmsnorm_kernel(float* __restrict__ data, const float* __restrict__ g,
                               int nrows, int rowstride, int nchunks, float scale) {
    int wg   = (blockIdx.x * blockDim.x + threadIdx.x) >> 5;
    int lane = threadIdx.x & 31;
    int total = nrows * nchunks;
    if (wg >= total) return;
    int row = wg / nchunks;
    int chunk = wg - row * nchunks;
    float* p = data + (size_t)row * rowstride + chunk * DH;
    float v0 = p[lane], v1 = p[lane + 32];
    float ss = v0 * v0 + v1 * v1;
    #pragma unroll
    for (int o = 16; o; o >>= 1) ss += __shfl_xor_sync(0xffffffffu, ss, o);
    float norm = sqrtf(ss) * 0.125f;
    float r = scale / fmaxf(norm, 1e-8f);
    p[lane]      = v0 * r * g[lane];
    p[lane + 32] = v1 * r * g[lane + 32];
}

// ---------------- flash attention, fp32 ----------------
__device__ __forceinline__ int rotr6(int v) { return ((v >> 1) | ((v & 1) << 5)); }

__global__ void __launch_bounds__(128) attn_kernel(
    const float* __restrict__ q, const float* __restrict__ kvx,
    const float* __restrict__ kvl, const int* __restrict__ mask,
    float* __restrict__ out) {
    __shared__ float Qs [64 * 64];
    __shared__ float KPs[64 * 64];
    __shared__ float Vs [64 * 64];
    const int qt = blockIdx.x, h = blockIdx.y, b = blockIdx.z;
    const int tid = threadIdx.x;
    const int tx = tid & 15, ty = tid >> 4;

    const float* qb = q + ((size_t)(b * M_LAT + qt * 64)) * D_INR + h * DH;
    for (int idx = tid; idx < 4096; idx += 128) {
        int r = idx >> 6, d = idx & 63;
        Qs[(r << 6) + (d ^ r)] = qb[(size_t)r * D_INR + d];
    }

    float m_i[8], l_i[8], acc[8][4];
    #pragma unroll
    for (int i = 0; i < 8; i++) {
        m_i[i] = -3.0e38f; l_i[i] = 0.f;
        #pragma unroll
        for (int j = 0; j < 4; j++) acc[i][j] = 0.f;
    }
    int rot1[4];
    #pragma unroll
    for (int j = 0; j < 4; j++) rot1[j] = rotr6(tx * 4 + j);
    __syncthreads();

    for (int j0 = 0; j0 < L_TOT; j0 += 64) {
        const bool in_x = (j0 < N_X);
        const float* kvb = in_x
            ? kvx + ((size_t)(b * N_X + j0)) * (2 * D_INR) + h * DH
            : kvl + ((size_t)(b * M_LAT + (j0 - N_X))) * (2 * D_INR) + h * DH;
        for (int idx = tid; idx < 4096; idx += 128) {
            int r = idx >> 6, d = idx & 63;
            KPs[(r << 6) + (d ^ rotr6(r))] = kvb[(size_t)r * (2 * D_INR) + d];
            Vs [(r << 6) + rotr6(d)]       = kvb[(size_t)r * (2 * D_INR) + D_INR + d];
        }
        __syncthreads();

        float S[8][4];
        #pragma unroll
        for (int i = 0; i < 8; i++) { S[i][0] = 0.f; S[i][1] = 0.f; S[i][2] = 0.f; S[i][3] = 0.f; }
        #pragma unroll 4
        for (int d = 0; d < 64; d++) {
            float ra[8], rb[4];
            #pragma unroll
            for (int i = 0; i < 8; i++) {
                int row = ty * 8 + i;
                ra[i] = Qs[(row << 6) + (d ^ row)];
            }
            #pragma unroll
            for (int j = 0; j < 4; j++) {
                int col = tx * 4 + j;
                rb[j] = KPs[(col << 6) + (d ^ rot1[j])];
            }
            #pragma unroll
            for (int i = 0; i < 8; i++)
                #pragma unroll
                for (int j = 0; j < 4; j++)
                    S[i][j] = fmaf(ra[i], rb[j], S[i][j]);
        }
        if (in_x) {
            const int* mb = mask + b * N_X + j0 + tx * 4;
            #pragma unroll
            for (int j = 0; j < 4; j++)
                if (!mb[j]) {
                    #pragma unroll
                    for (int i = 0; i < 8; i++) S[i][j] = -3.0e38f;
                }
        }
        #pragma unroll
        for (int i = 0; i < 8; i++) {
            float mx = fmaxf(fmaxf(S[i][0], S[i][1]), fmaxf(S[i][2], S[i][3]));
            #pragma unroll
            for (int o = 1; o < 16; o <<= 1) mx = fmaxf(mx, __shfl_xor_sync(0xffffffffu, mx, o));
            float mnew = fmaxf(m_i[i], mx);
            float corr = __expf(m_i[i] - mnew);
            m_i[i] = mnew;
            float rs = 0.f;
            #pragma unroll
            for (int j = 0; j < 4; j++) {
                float p = __expf(S[i][j] - mnew);
                S[i][j] = p; rs += p;
            }
            #pragma unroll
            for (int o = 1; o < 16; o <<= 1) rs += __shfl_xor_sync(0xffffffffu, rs, o);
            l_i[i] = l_i[i] * corr + rs;
            #pragma unroll
            for (int j = 0; j < 4; j++) acc[i][j] *= corr;
        }
        __syncthreads();
        #pragma unroll
        for (int i = 0; i < 8; i++) {
            int row = ty * 8 + i;
            #pragma unroll
            for (int j = 0; j < 4; j++) {
                int col = tx * 4 + j;
                KPs[(row << 6) + (col ^ row)] = S[i][j];
            }
        }
        __syncthreads();
        #pragma unroll 4
        for (int jj = 0; jj < 64; jj++) {
            float pa[8], vb[4];
            #pragma unroll
            for (int i = 0; i < 8; i++) {
                int row = ty * 8 + i;
                pa[i] = KPs[(row << 6) + (jj ^ row)];
            }
            #pragma unroll
            for (int j = 0; j < 4; j++)
                vb[j] = Vs[(jj << 6) + rot1[j]];
            #pragma unroll
            for (int i = 0; i < 8; i++)
                #pragma unroll
                for (int j = 0; j < 4; j++)
                    acc[i][j] = fmaf(pa[i], vb[j], acc[i][j]);
        }
        __syncthreads();
    }

    float* ob = out + ((size_t)(b * M_LAT + qt * 64)) * D_INR + h * DH;
    #pragma unroll
    for (int i = 0; i < 8; i++) {
        float inv = 1.f / l_i[i];
        int row = ty * 8 + i;
        #pragma unroll
        for (int j = 0; j < 4; j++)
            ob[(size_t)row * D_INR + tx * 4 + j] = acc[i][j] * inv;
    }
}

// ---------------- launch ----------------
extern "C" void kernel_launch(void* const* d_in, const int* in_sizes, int n_in,
                              void* d_out, int out_size) {
    const float* x      = (const float*)d_in[0];
    const float* lat    = (const float*)d_in[1];
    const int*   mask   = (const int*)  d_in[2];
    const float* ln_x_g = (const float*)d_in[3];
    const float* ln_x_b = (const float*)d_in[4];
    const float* ln_l_g = (const float*)d_in[5];
    const float* ln_l_b = (const float*)d_in[6];
    const float* qn_g   = (const float*)d_in[7];
    const float* kn_g   = (const float*)d_in[8];
    const float* Wq     = (const float*)d_in[9];
    const float* Wkv    = (const float*)d_in[10];
    const float* Wlkv   = (const float*)d_in[11];
    const float* Wo     = (const float*)d_in[12];
    const float* bo     = (const float*)d_in[13];
    float* outp = (float*)d_out;

    float *xn, *ln, *qb, *kvx, *kvl, *att;
    cudaGetSymbolAddress((void**)&xn,  g_xn);
    cudaGetSymbolAddress((void**)&ln,  g_ln);
    cudaGetSymbolAddress((void**)&qb,  g_q);
    cudaGetSymbolAddress((void**)&kvx, g_kvx);
    cudaGetSymbolAddress((void**)&kvl, g_kvl);
    cudaGetSymbolAddress((void**)&att, g_att);

    // 1) layernorms
    layernorm_kernel<<<B_ * N_X,   256>>>(x,   xn, ln_x_g, ln_x_b, D_IN);
    layernorm_kernel<<<B_ * M_LAT, 256>>>(lat, ln, ln_l_g, ln_l_b, D_LAT);

    // 2) projections (tensor-core split-bf16 mma.sync)
    {
        dim3 g(D_INR / 128, (B_ * M_LAT) / 128);
        gemm_mma_kernel<<<g, 256>>>(ln, Wq, nullptr, qb, B_ * M_LAT, D_INR, D_LAT);
    }
    {
        dim3 g((2 * D_INR) / 128, (B_ * N_X) / 128);
        gemm_mma_kernel<<<g, 256>>>(xn, Wkv, nullptr, kvx, B_ * N_X, 2 * D_INR, D_IN);
    }
    {
        dim3 g((2 * D_INR) / 128, (B_ * M_LAT) / 128);
        gemm_mma_kernel<<<g, 256>>>(ln, Wlkv, nullptr, kvl, B_ * M_LAT, 2 * D_INR, D_LAT);
    }

    // 3) head rmsnorms
    rmsnorm_kernel<<<(B_ * M_LAT * HEADS) / 8, 256>>>(qb,  qn_g, B_ * M_LAT, D_INR,     HEADS, 0.125f);
    rmsnorm_kernel<<<(B_ * N_X  * HEADS) / 8, 256>>>(kvx, kn_g, B_ * N_X,  2 * D_INR, HEADS, 1.0f);
    rmsnorm_kernel<<<(B_ * M_LAT * HEADS) / 8, 256>>>(kvl, kn_g, B_ * M_LAT, 2 * D_INR, HEADS, 1.0f);

    // 4) attention
    {
        dim3 g(M_LAT / 64, HEADS, B_);
        attn_kernel<<<g, 128>>>(qb, kvx, kvl, mask, att);
    }

    // 5) output projection + bias
    {
        dim3 g(D_LAT / 128, (B_ * M_LAT) / 128);
        gemm_mma_kernel<<<g, 256>>>(att, Wo, bo, outp, B_ * M_LAT, D_LAT, D_INR);
    }
}

// round 5
// speedup vs baseline: 2.8368x; 2.3075x over previous
#include <cuda_runtime.h>
#include <cuda_bf16.h>
#include <cstdint>
#include <cstddef>

// ---------------- problem constants ----------------
#define B_    4
#define N_X   4096
#define M_LAT 512
#define D_IN  768
#define D_LAT 1024
#define D_INR 1024
#define HEADS 16
#define DH    64
#define L_TOT (N_X + M_LAT)   // 4608

// ---------------- scratch (no allocs allowed) ----------------
__device__ float g_xn [(size_t)B_ * N_X  * D_IN ];
__device__ float g_ln [(size_t)B_ * M_LAT * D_LAT];
__device__ float g_q  [(size_t)B_ * M_LAT * D_INR];
__device__ float g_kvx[(size_t)B_ * N_X  * 2 * D_INR];
__device__ float g_kvl[(size_t)B_ * M_LAT * 2 * D_INR];
__device__ float g_att[(size_t)B_ * M_LAT * D_INR];

__device__ __forceinline__ uint32_t smem_u32(const void* p) {
    uint32_t a;
    asm("{ .reg .u64 t; cvta.to.shared.u64 t, %1; cvt.u32.u64 %0, t; }" : "=r"(a) : "l"(p));
    return a;
}

__device__ __forceinline__ void cvt_hilo(float4 v, uint32_t& h01, uint32_t& h23,
                                         uint32_t& l01, uint32_t& l23) {
    __nv_bfloat16 h0 = __float2bfloat16_rn(v.x);
    __nv_bfloat16 h1 = __float2bfloat16_rn(v.y);
    __nv_bfloat16 h2 = __float2bfloat16_rn(v.z);
    __nv_bfloat16 h3 = __float2bfloat16_rn(v.w);
    __nv_bfloat16 l0 = __float2bfloat16_rn(v.x - __bfloat162float(h0));
    __nv_bfloat16 l1 = __float2bfloat16_rn(v.y - __bfloat162float(h1));
    __nv_bfloat16 l2 = __float2bfloat16_rn(v.z - __bfloat162float(h2));
    __nv_bfloat16 l3 = __float2bfloat16_rn(v.w - __bfloat162float(h3));
    h01 = ((uint32_t)__bfloat16_as_ushort(h1) << 16) | __bfloat16_as_ushort(h0);
    h23 = ((uint32_t)__bfloat16_as_ushort(h3) << 16) | __bfloat16_as_ushort(h2);
    l01 = ((uint32_t)__bfloat16_as_ushort(l1) << 16) | __bfloat16_as_ushort(l0);
    l23 = ((uint32_t)__bfloat16_as_ushort(l3) << 16) | __bfloat16_as_ushort(l2);
}

__device__ __forceinline__ uint32_t pack_bf16(float a, float b) {
    __nv_bfloat162 t = __floats2bfloat162_rn(a, b);   // .x=a (low), .y=b (high)
    return *(uint32_t*)&t;
}

#define STS64(addr_, r0_, r1_) \
    asm volatile("st.shared.v2.b32 [%0], {%1,%2};" :: "r"(addr_), "r"(r0_), "r"(r1_) : "memory")
#define LDMX4(r0_, r1_, r2_, r3_, addr_) \
    asm volatile("ldmatrix.sync.aligned.m8n8.x4.shared.b16 {%0,%1,%2,%3}, [%4];" \
        : "=r"(r0_), "=r"(r1_), "=r"(r2_), "=r"(r3_) : "r"(addr_))
#define LDMX4T(r0_, r1_, r2_, r3_, addr_) \
    asm volatile("ldmatrix.sync.aligned.m8n8.x4.trans.shared.b16 {%0,%1,%2,%3}, [%4];" \
        : "=r"(r0_), "=r"(r1_), "=r"(r2_), "=r"(r3_) : "r"(addr_))
#define MMA16816(c_, a_, b0_, b1_) \
    asm volatile("mma.sync.aligned.m16n8k16.row.col.f32.bf16.bf16.f32 " \
        "{%0,%1,%2,%3}, {%4,%5,%6,%7}, {%8,%9}, {%0,%1,%2,%3};" \
        : "+f"((c_)[0]), "+f"((c_)[1]), "+f"((c_)[2]), "+f"((c_)[3]) \
        : "r"((a_)[0]), "r"((a_)[1]), "r"((a_)[2]), "r"((a_)[3]), "r"(b0_), "r"(b1_))

// =======================================================================
// split-bf16 GEMM, double-buffered: C[M,N] = A[M,K] @ W[N,K]^T (+bias)
// CTA 128x128, BK=32, 256 thr (8 warps 2Mx4N), warp tile 64x32.
// =======================================================================
#define LDSB 40
#define GT_ELEMS (128 * LDSB)          // 5120 bf16 per tile
#define GT_BYTES (GT_ELEMS * 2)        // 10240
#define GEMM_SMEM (8 * GT_BYTES)       // 81920

__device__ __forceinline__ void g_load_regs(const float* __restrict__ G, int K, int k0,
                                            int tid, float4 r[4]) {
    const int c4 = tid & 7, r0 = tid >> 3;
    #pragma unroll
    for (int p = 0; p < 4; ++p)
        r[p] = *(const float4*)(G + (size_t)(r0 + p * 32) * K + k0 + c4 * 4);
}
__device__ __forceinline__ void g_store_regs(const float4 r[4], uint32_t sHi, uint32_t sLo,
                                             int tid) {
    const int c4 = tid & 7, r0 = tid >> 3;
    #pragma unroll
    for (int p = 0; p < 4; ++p) {
        uint32_t h01, h23, l01, l23;
        cvt_hilo(r[p], h01, h23, l01, l23);
        uint32_t off = (uint32_t)((r0 + p * 32) * LDSB + c4 * 4) * 2;
        STS64(sHi + off, h01, h23);
        STS64(sLo + off, l01, l23);
    }
}

__global__ void __launch_bounds__(256, 1) gemm_mma_kernel(
    const float* __restrict__ A, const float* __restrict__ W,
    const float* __restrict__ bias, float* __restrict__ C,
    int M, int N, int K) {
    extern __shared__ __align__(16) char gsm[];
    const uint32_t u0 = smem_u32(gsm);
    const uint32_t uAh = u0, uAl = u0 + 2 * GT_BYTES, uBh = u0 + 4 * GT_BYTES, uBl = u0 + 6 * GT_BYTES;
    const int tid = threadIdx.x;
    const int lane = tid & 31, wid = tid >> 5;
    const int warp_m = wid & 1, warp_n = wid >> 1;

    const float* Ag = A + (size_t)blockIdx.y * 128 * K;
    const float* Wg = W + (size_t)blockIdx.x * 128 * K;

    const int a_m = (lane & 7) + ((lane >> 3) & 1) * 8;
    const int a_k = (lane >> 4) * 8;
    const int b_n = (lane & 7) + (lane >> 4) * 8;
    const int b_k = ((lane >> 3) & 1) * 8;

    float acc[4][4][4];
    #pragma unroll
    for (int i = 0; i < 4; i++)
        #pragma unroll
        for (int j = 0; j < 4; j++)
            #pragma unroll
            for (int t = 0; t < 4; t++) acc[i][j][t] = 0.f;

    float4 pa[4], pw[4];
    g_load_regs(Ag, K, 0, tid, pa);
    g_load_regs(Wg, K, 0, tid, pw);
    g_store_regs(pa, uAh, uAl, tid);
    g_store_regs(pw, uBh, uBl, tid);
    __syncthreads();

    const int NK = K / 32;
    for (int c = 0; c < NK; ++c) {
        const uint32_t co = (uint32_t)(c & 1) * GT_BYTES;
        if (c + 1 < NK) {            // issue prefetch LDGs before MMAs
            g_load_regs(Ag, K, (c + 1) * 32, tid, pa);
            g_load_regs(Wg, K, (c + 1) * 32, tid, pw);
        }
        #pragma unroll
        for (int ks = 0; ks < 2; ++ks) {
            uint32_t ah[4][4], al[4][4], bh[2][4], bl[2][4];
            #pragma unroll
            for (int mt = 0; mt < 4; ++mt) {
                uint32_t off = co + (uint32_t)((warp_m * 64 + mt * 16 + a_m) * LDSB + ks * 16 + a_k) * 2;
                LDMX4(ah[mt][0], ah[mt][1], ah[mt][2], ah[mt][3], uAh + off);
                LDMX4(al[mt][0], al[mt][1], al[mt][2], al[mt][3], uAl + off);
            }
            #pragma unroll
            for (int np = 0; np < 2; ++np) {
                uint32_t off = co + (uint32_t)((warp_n * 32 + np * 16 + b_n) * LDSB + ks * 16 + b_k) * 2;
                LDMX4(bh[np][0], bh[np][1], bh[np][2], bh[np][3], uBh + off);
                LDMX4(bl[np][0], bl[np][1], bl[np][2], bl[np][3], uBl + off);
            }
            #pragma unroll
            for (int mt = 0; mt < 4; ++mt) {
                #pragma unroll
                for (int nt = 0; nt < 4; ++nt) {
                    const int np = nt >> 1, sel = (nt & 1) * 2;
                    uint32_t bh0 = bh[np][sel], bh1 = bh[np][sel + 1];
                    uint32_t bl0 = bl[np][sel], bl1 = bl[np][sel + 1];
                    MMA16816(acc[mt][nt], ah[mt], bh0, bh1);
                    MMA16816(acc[mt][nt], ah[mt], bl0, bl1);
                    MMA16816(acc[mt][nt], al[mt], bh0, bh1);
                }
            }
        }
        if (c + 1 < NK) {
            const uint32_t no = (uint32_t)((c + 1) & 1) * GT_BYTES;
            g_store_regs(pa, uAh + no, uAl + no, tid);
            g_store_regs(pw, uBh + no, uBl + no, tid);
        }
        __syncthreads();
    }

    const int g = lane >> 2, c2 = (lane & 3) * 2;
    const int rowb = blockIdx.y * 128 + warp_m * 64;
    const int colb = blockIdx.x * 128 + warp_n * 32;
    #pragma unroll
    for (int mt = 0; mt < 4; ++mt) {
        #pragma unroll
        for (int nt = 0; nt < 4; ++nt) {
            int row = rowb + mt * 16 + g;
            int col = colb + nt * 8 + c2;
            float b0 = 0.f, b1 = 0.f;
            if (bias) { b0 = bias[col]; b1 = bias[col + 1]; }
            *(float2*)(C + (size_t)row * N + col) =
                make_float2(acc[mt][nt][0] + b0, acc[mt][nt][1] + b1);
            *(float2*)(C + (size_t)(row + 8) * N + col) =
                make_float2(acc[mt][nt][2] + b0, acc[mt][nt][3] + b1);
        }
    }
}

// =======================================================================
// flash attention via mma.sync split-bf16.
// Block: 128 q-rows, 8 warps x (16 rows x 64 cols). 72 kv tiles of 64.
// =======================================================================
#define QTILE 128
#define LDA 72
#define ATT_SMEM 73984
// smem byte offsets: Qh 0, Ql 18432, Kh 36864, Kl 46080, Vh 55296, Vl 64512, mask 73728

__global__ void __launch_bounds__(256, 1) attn_mma_kernel(
    const float* __restrict__ q, const float* __restrict__ kvx,
    const float* __restrict__ kvl, const int* __restrict__ mask,
    float* __restrict__ out) {
    extern __shared__ __align__(16) char asmem[];
    const uint32_t u0 = smem_u32(asmem);
    const uint32_t uQh = u0, uQl = u0 + 18432;
    const uint32_t uKh = u0 + 36864, uKl = u0 + 46080;
    const uint32_t uVh = u0 + 55296, uVl = u0 + 64512;
    float* mkf = (float*)(asmem + 73728);

    const int qt = blockIdx.x, h = blockIdx.y, b = blockIdx.z;
    const int tid = threadIdx.x, lane = tid & 31, wid = tid >> 5;

    // stage Q (128x64) hi/lo
    const float* qg = q + ((size_t)(b * M_LAT + qt * QTILE)) * D_INR + h * DH;
    #pragma unroll
    for (int i = 0; i < 8; ++i) {
        int id = tid + i * 256;
        int row = id >> 4, c4 = id & 15;
        float4 v = *(const float4*)(qg + (size_t)row * D_INR + c4 * 4);
        uint32_t h01, h23, l01, l23; cvt_hilo(v, h01, h23, l01, l23);
        uint32_t off = (uint32_t)(row * LDA + c4 * 4) * 2;
        STS64(uQh + off, h01, h23);
        STS64(uQl + off, l01, l23);
    }
    __syncthreads();

    const int a_m = (lane & 7) + ((lane >> 3) & 1) * 8;
    const int a_k = (lane >> 4) * 8;
    uint32_t qh[4][4], ql[4][4];
    #pragma unroll
    for (int kc = 0; kc < 4; ++kc) {
        uint32_t off = (uint32_t)((wid * 16 + a_m) * LDA + kc * 16 + a_k) * 2;
        LDMX4(qh[kc][0], qh[kc][1], qh[kc][2], qh[kc][3], uQh + off);
        LDMX4(ql[kc][0], ql[kc][1], ql[kc][2], ql[kc][3], uQl + off);
    }

    float m0 = -3.0e38f, m8 = -3.0e38f, l0 = 0.f, l8 = 0.f;
    float O[8][4];
    #pragma unroll
    for (int i = 0; i < 8; ++i)
        #pragma unroll
        for (int j = 0; j < 4; ++j) O[i][j] = 0.f;

    const int b_n = (lane & 7) + (lane >> 4) * 8;   // K ldmatrix rows (n), col group
    const int b_k = ((lane >> 3) & 1) * 8;
    const int v_r = a_m;                            // V trans rows (k)
    const int v_c = (lane >> 4) * 8;                // V col group (n=d)
    const int cq = (lane & 3) * 2;

    for (int j0 = 0; j0 < L_TOT; j0 += 64) {
        const bool in_x = (j0 < N_X);
        const float* kvb = in_x
            ? kvx + ((size_t)(b * N_X + j0)) * (2 * D_INR) + h * DH
            : kvl + ((size_t)(b * M_LAT + (j0 - N_X))) * (2 * D_INR) + h * DH;
        __syncthreads();   // previous tile fully consumed before overwrite
        #pragma unroll
        for (int i = 0; i < 4; ++i) {
            int id = tid + i * 256;
            int row = id >> 4, c4 = id & 15;
            float4 kv4 = *(const float4*)(kvb + (size_t)row * (2 * D_INR) + c4 * 4);
            float4 vv4 = *(const float4*)(kvb + (size_t)row * (2 * D_INR) + D_INR + c4 * 4);
            uint32_t off = (uint32_t)(row * LDA + c4 * 4) * 2;
            uint32_t h01, h23, l01, l23;
            cvt_hilo(kv4, h01, h23, l01, l23);
            STS64(uKh + off, h01, h23); STS64(uKl + off, l01, l23);
            cvt_hilo(vv4, h01, h23, l01, l23);
            STS64(uVh + off, h01, h23); STS64(uVl + off, l01, l23);
        }
        if (tid < 64) mkf[tid] = (!in_x || mask[b * N_X + j0 + tid]) ? 0.f : -3.0e38f;
        __syncthreads();

        // S = Q K^T (split-bf16, 3 products)
        float S[8][4];
        #pragma unroll
        for (int i = 0; i < 8; ++i) { S[i][0] = S[i][1] = S[i][2] = S[i][3] = 0.f; }
        #pragma unroll
        for (int kc = 0; kc < 4; ++kc) {
            #pragma unroll
            for (int ng = 0; ng < 4; ++ng) {
                uint32_t kh4[4], kl4[4];
                uint32_t off = (uint32_t)((ng * 16 + b_n) * LDA + kc * 16 + b_k) * 2;
                LDMX4(kh4[0], kh4[1], kh4[2], kh4[3], uKh + off);
                LDMX4(kl4[0], kl4[1], kl4[2], kl4[3], uKl + off);
                MMA16816(S[2 * ng],     qh[kc], kh4[0], kh4[1]);
                MMA16816(S[2 * ng],     qh[kc], kl4[0], kl4[1]);
                MMA16816(S[2 * ng],     ql[kc], kh4[0], kh4[1]);
                MMA16816(S[2 * ng + 1], qh[kc], kh4[2], kh4[3]);
                MMA16816(S[2 * ng + 1], qh[kc], kl4[2], kl4[3]);
                MMA16816(S[2 * ng + 1], ql[kc], kh4[2], kh4[3]);
            }
        }
        // mask add
        #pragma unroll
        for (int nt = 0; nt < 8; ++nt) {
            float a0 = mkf[nt * 8 + cq], a1 = mkf[nt * 8 + cq + 1];
            S[nt][0] += a0; S[nt][1] += a1; S[nt][2] += a0; S[nt][3] += a1;
        }
        // online softmax (rows g and g+8; quad = lanes sharing lane>>2)
        float mx0 = -3.0e38f, mx8 = -3.0e38f;
        #pragma unroll
        for (int nt = 0; nt < 8; ++nt) {
            mx0 = fmaxf(mx0, fmaxf(S[nt][0], S[nt][1]));
            mx8 = fmaxf(mx8, fmaxf(S[nt][2], S[nt][3]));
        }
        mx0 = fmaxf(mx0, __shfl_xor_sync(0xffffffffu, mx0, 1));
        mx0 = fmaxf(mx0, __shfl_xor_sync(0xffffffffu, mx0, 2));
        mx8 = fmaxf(mx8, __shfl_xor_sync(0xffffffffu, mx8, 1));
        mx8 = fmaxf(mx8, __shfl_xor_sync(0xffffffffu, mx8, 2));
        float mn0 = fmaxf(m0, mx0), mn8 = fmaxf(m8, mx8);
        float c0r = __expf(m0 - mn0), c8r = __expf(m8 - mn8);
        m0 = mn0; m8 = mn8;
        float rs0 = 0.f, rs8 = 0.f;
        uint32_t ph[4][4], pl[4][4];
        #pragma unroll
        for (int nt = 0; nt < 8; ++nt) {
            float p0 = __expf(S[nt][0] - m0), p1 = __expf(S[nt][1] - m0);
            float p2 = __expf(S[nt][2] - m8), p3 = __expf(S[nt][3] - m8);
            rs0 += p0 + p1; rs8 += p2 + p3;
            uint32_t hA = pack_bf16(p0, p1), hB = pack_bf16(p2, p3);
            float r0 = p0 - __bfloat162float(__float2bfloat16_rn(p0));
            float r1 = p1 - __bfloat162float(__float2bfloat16_rn(p1));
            float r2 = p2 - __bfloat162float(__float2bfloat16_rn(p2));
            float r3 = p3 - __bfloat162float(__float2bfloat16_rn(p3));
            uint32_t lA = pack_bf16(r0, r1), lB = pack_bf16(r2, r3);
            const int kcI = nt >> 1, ap = (nt & 1) * 2;
            ph[kcI][ap] = hA; ph[kcI][ap + 1] = hB;
            pl[kcI][ap] = lA; pl[kcI][ap + 1] = lB;
        }
        rs0 += __shfl_xor_sync(0xffffffffu, rs0, 1);
        rs0 += __shfl_xor_sync(0xffffffffu, rs0, 2);
        rs8 += __shfl_xor_sync(0xffffffffu, rs8, 1);
        rs8 += __shfl_xor_sync(0xffffffffu, rs8, 2);
        l0 = l0 * c0r + rs0;
        l8 = l8 * c8r + rs8;
        #pragma unroll
        for (int dt = 0; dt < 8; ++dt) {
            O[dt][0] *= c0r; O[dt][1] *= c0r;
            O[dt][2] *= c8r; O[dt][3] *= c8r;
        }
        // O += P V (split-bf16, 3 products)
        #pragma unroll
        for (int kc = 0; kc < 4; ++kc) {
            #pragma unroll
            for (int dg = 0; dg < 4; ++dg) {
                uint32_t vh4[4], vl4[4];
                uint32_t off = (uint32_t)((kc * 16 + v_r) * LDA + dg * 16 + v_c) * 2;
                LDMX4T(vh4[0], vh4[1], vh4[2], vh4[3], uVh + off);
                LDMX4T(vl4[0], vl4[1], vl4[2], vl4[3], uVl + off);
                MMA16816(O[2 * dg],     ph[kc], vh4[0], vh4[1]);
                MMA16816(O[2 * dg],     ph[kc], vl4[0], vl4[1]);
                MMA16816(O[2 * dg],     pl[kc], vh4[0], vh4[1]);
                MMA16816(O[2 * dg + 1], ph[kc], vh4[2], vh4[3]);
                MMA16816(O[2 * dg + 1], ph[kc], vl4[2], vl4[3]);
                MMA16816(O[2 * dg + 1], pl[kc], vh4[2], vh4[3]);
            }
        }
    }

    const float inv0 = 1.f / l0, inv8 = 1.f / l8;
    const int g = lane >> 2;
    float* ob = out + ((size_t)(b * M_LAT + qt * QTILE + wid * 16 + g)) * D_INR + h * DH;
    #pragma unroll
    for (int dt = 0; dt < 8; ++dt) {
        int col = dt * 8 + cq;
        *(float2*)(ob + col) = make_float2(O[dt][0] * inv0, O[dt][1] * inv0);
        *(float2*)(ob + (size_t)8 * D_INR + col) = make_float2(O[dt][2] * inv8, O[dt][3] * inv8);
    }
}

// ---------------- layernorm ----------------
__global__ void layernorm_kernel(const float* __restrict__ in, float* __restrict__ out,
                                 const float* __restrict__ g, const float* __restrict__ b,
                                 int C) {
    const int row = blockIdx.x;
    const float* x = in + (size_t)row * C;
    float* y = out + (size_t)row * C;
    float s = 0.f, ss = 0.f;
    for (int i = threadIdx.x; i < C; i += blockDim.x) {
        float v = x[i]; s += v; ss += v * v;
    }
    __shared__ float red[2][32];
    #pragma unroll
    for (int o = 16; o; o >>= 1) {
        s  += __shfl_xor_sync(0xffffffffu, s,  o);
        ss += __shfl_xor_sync(0xffffffffu, ss, o);
    }
    int warp = threadIdx.x >> 5, lane = threadIdx.x & 31;
    if (lane == 0) { red[0][warp] = s; red[1][warp] = ss; }
    __syncthreads();
    int nw = blockDim.x >> 5;
    if (warp == 0) {
        s  = (lane < nw) ? red[0][lane] : 0.f;
        ss = (lane < nw) ? red[1][lane] : 0.f;
        #pragma unroll
        for (int o = 16; o; o >>= 1) {
            s  += __shfl_xor_sync(0xffffffffu, s,  o);
            ss += __shfl_xor_sync(0xffffffffu, ss, o);
        }
        if (lane == 0) { red[0][0] = s; red[1][0] = ss; }
    }
    __syncthreads();
    float invC = 1.f / (float)C;
    float mu  = red[0][0] * invC;
    float var = red[1][0] * invC - mu * mu;
    float rs  = rsqrtf(var + 1e-5f);
    for (int i = threadIdx.x; i < C; i += blockDim.x)
        y[i] = (x[i] - mu) * rs * g[i] + b[i];
}

// ---------------- per-head rmsnorm ----------------
__global__ void rmsnorm_kernel(float* __restrict__ data, const float* __restrict__ g,
                               int nrows, int rowstride, int nchunks, float scale) {
    int wg   = (blockIdx.x * blockDim.x + threadIdx.x) >> 5;
    int lane = threadIdx.x & 31;
    int total = nrows * nchunks;
    if (wg >= total) return;
    int row = wg / nchunks;
    int chunk = wg - row * nchunks;
    float* p = data + (size_t)row * rowstride + chunk * DH;
    float v0 = p[lane], v1 = p[lane + 32];
    float ss = v0 * v0 + v1 * v1;
    #pragma unroll
    for (int o = 16; o; o >>= 1) ss += __shfl_xor_sync(0xffffffffu, ss, o);
    float norm = sqrtf(ss) * 0.125f;
    float r = scale / fmaxf(norm, 1e-8f);
    p[lane]      = v0 * r * g[lane];
    p[lane + 32] = v1 * r * g[lane + 32];
}

// ---------------- launch ----------------
extern "C" void kernel_launch(void* const* d_in, const int* in_sizes, int n_in,
                              void* d_out, int out_size) {
    const float* x      = (const float*)d_in[0];
    const float* lat    = (const float*)d_in[1];
    const int*   mask   = (const int*)  d_in[2];
    const float* ln_x_g = (const float*)d_in[3];
    const float* ln_x_b = (const float*)d_in[4];
    const float* ln_l_g = (const float*)d_in[5];
    const float* ln_l_b = (const float*)d_in[6];
    const float* qn_g   = (const float*)d_in[7];
    const float* kn_g   = (const float*)d_in[8];
    const float* Wq     = (const float*)d_in[9];
    const float* Wkv    = (const float*)d_in[10];
    const float* Wlkv   = (const float*)d_in[11];
    const float* Wo     = (const float*)d_in[12];
    const float* bo     = (const float*)d_in[13];
    float* outp = (float*)d_out;

    float *xn, *ln, *qb, *kvx, *kvl, *att;
    cudaGetSymbolAddress((void**)&xn,  g_xn);
    cudaGetSymbolAddress((void**)&ln,  g_ln);
    cudaGetSymbolAddress((void**)&qb,  g_q);
    cudaGetSymbolAddress((void**)&kvx, g_kvx);
    cudaGetSymbolAddress((void**)&kvl, g_kvl);
    cudaGetSymbolAddress((void**)&att, g_att);

    cudaFuncSetAttribute(gemm_mma_kernel, cudaFuncAttributeMaxDynamicSharedMemorySize, GEMM_SMEM);
    cudaFuncSetAttribute(attn_mma_kernel, cudaFuncAttributeMaxDynamicSharedMemorySize, ATT_SMEM);

    // 1) layernorms
    layernorm_kernel<<<B_ * N_X,   256>>>(x,   xn, ln_x_g, ln_x_b, D_IN);
    layernorm_kernel<<<B_ * M_LAT, 256>>>(lat, ln, ln_l_g, ln_l_b, D_LAT);

    // 2) projections
    {
        dim3 g(D_INR / 128, (B_ * M_LAT) / 128);
        gemm_mma_kernel<<<g, 256, GEMM_SMEM>>>(ln, Wq, nullptr, qb, B_ * M_LAT, D_INR, D_LAT);
    }
    {
        dim3 g((2 * D_INR) / 128, (B_ * N_X) / 128);
        gemm_mma_kernel<<<g, 256, GEMM_SMEM>>>(xn, Wkv, nullptr, kvx, B_ * N_X, 2 * D_INR, D_IN);
    }
    {
        dim3 g((2 * D_INR) / 128, (B_ * M_LAT) / 128);
        gemm_mma_kernel<<<g, 256, GEMM_SMEM>>>(ln, Wlkv, nullptr, kvl, B_ * M_LAT, 2 * D_INR, D_LAT);
    }

    // 3) head rmsnorms (q carries gamma * SCALE)
    rmsnorm_kernel<<<(B_ * M_LAT * HEADS) / 8, 256>>>(qb,  qn_g, B_ * M_LAT, D_INR,     HEADS, 0.125f);
    rmsnorm_kernel<<<(B_ * N_X  * HEADS) / 8, 256>>>(kvx, kn_g, B_ * N_X,  2 * D_INR, HEADS, 1.0f);
    rmsnorm_kernel<<<(B_ * M_LAT * HEADS) / 8, 256>>>(kvl, kn_g, B_ * M_LAT, 2 * D_INR, HEADS, 1.0f);

    // 4) attention (tensor-core flash)
    {
        dim3 g(M_LAT / QTILE, HEADS, B_);
        attn_mma_kernel<<<g, 256, ATT_SMEM>>>(qb, kvx, kvl, mask, att);
    }

    // 5) output projection + bias
    {
        dim3 g(D_LAT / 128, (B_ * M_LAT) / 128);
        gemm_mma_kernel<<<g, 256, GEMM_SMEM>>>(att, Wo, bo, outp, B_ * M_LAT, D_LAT, D_INR);
    }
}

// round 6
// speedup vs baseline: 3.6893x; 1.3005x over previous
#include <cuda_runtime.h>
#include <cuda_bf16.h>
#include <cuda_fp16.h>
#include <cstdint>
#include <cstddef>

// ---------------- problem constants ----------------
#define B_    4
#define N_X   4096
#define M_LAT 512
#define D_IN  768
#define D_LAT 1024
#define D_INR 1024
#define HEADS 16
#define DH    64
#define L_TOT (N_X + M_LAT)   // 4608

// ---------------- scratch (no allocs allowed) ----------------
__device__ __half g_xn_h [(size_t)B_ * N_X  * D_IN ];
__device__ __half g_ln_h [(size_t)B_ * M_LAT * D_LAT];
__device__ __half g_att_h[(size_t)B_ * M_LAT * D_INR];
__device__ float  g_q  [(size_t)B_ * M_LAT * D_INR];
__device__ float  g_kvx[(size_t)B_ * N_X  * 2 * D_INR];
__device__ float  g_kvl[(size_t)B_ * M_LAT * 2 * D_INR];
__device__ __half g_wq_h [(size_t)D_INR * D_LAT],     g_wq_l [(size_t)D_INR * D_LAT];
__device__ __half g_wkv_h[(size_t)2 * D_INR * D_IN],  g_wkv_l[(size_t)2 * D_INR * D_IN];
__device__ __half g_wlkv_h[(size_t)2 * D_INR * D_LAT], g_wlkv_l[(size_t)2 * D_INR * D_LAT];
__device__ __half g_wo_h [(size_t)D_LAT * D_INR],     g_wo_l [(size_t)D_LAT * D_INR];

__device__ __forceinline__ uint32_t smem_u32(const void* p) {
    uint32_t a;
    asm("{ .reg .u64 t; cvta.to.shared.u64 t, %1; cvt.u32.u64 %0, t; }" : "=r"(a) : "l"(p));
    return a;
}
__device__ __forceinline__ uint32_t pack_bf16(float a, float b) {
    __nv_bfloat162 t = __floats2bfloat162_rn(a, b);
    return *(uint32_t*)&t;
}
__device__ __forceinline__ void cvt_hilo_bf(float4 v, uint32_t& h01, uint32_t& h23,
                                            uint32_t& l01, uint32_t& l23) {
    __nv_bfloat16 h0 = __float2bfloat16_rn(v.x);
    __nv_bfloat16 h1 = __float2bfloat16_rn(v.y);
    __nv_bfloat16 h2 = __float2bfloat16_rn(v.z);
    __nv_bfloat16 h3 = __float2bfloat16_rn(v.w);
    __nv_bfloat16 l0 = __float2bfloat16_rn(v.x - __bfloat162float(h0));
    __nv_bfloat16 l1 = __float2bfloat16_rn(v.y - __bfloat162float(h1));
    __nv_bfloat16 l2 = __float2bfloat16_rn(v.z - __bfloat162float(h2));
    __nv_bfloat16 l3 = __float2bfloat16_rn(v.w - __bfloat162float(h3));
    h01 = ((uint32_t)__bfloat16_as_ushort(h1) << 16) | __bfloat16_as_ushort(h0);
    h23 = ((uint32_t)__bfloat16_as_ushort(h3) << 16) | __bfloat16_as_ushort(h2);
    l01 = ((uint32_t)__bfloat16_as_ushort(l1) << 16) | __bfloat16_as_ushort(l0);
    l23 = ((uint32_t)__bfloat16_as_ushort(l3) << 16) | __bfloat16_as_ushort(l2);
}

#define STS64(addr_, r0_, r1_) \
    asm volatile("st.shared.v2.b32 [%0], {%1,%2};" :: "r"(addr_), "r"(r0_), "r"(r1_) : "memory")
#define LDMX4(r0_, r1_, r2_, r3_, addr_) \
    asm volatile("ldmatrix.sync.aligned.m8n8.x4.shared.b16 {%0,%1,%2,%3}, [%4];" \
        : "=r"(r0_), "=r"(r1_), "=r"(r2_), "=r"(r3_) : "r"(addr_))
#define LDMX4T(r0_, r1_, r2_, r3_, addr_) \
    asm volatile("ldmatrix.sync.aligned.m8n8.x4.trans.shared.b16 {%0,%1,%2,%3}, [%4];" \
        : "=r"(r0_), "=r"(r1_), "=r"(r2_), "=r"(r3_) : "r"(addr_))
#define MMA_BF16(c_, a_, b0_, b1_) \
    asm volatile("mma.sync.aligned.m16n8k16.row.col.f32.bf16.bf16.f32 " \
        "{%0,%1,%2,%3}, {%4,%5,%6,%7}, {%8,%9}, {%0,%1,%2,%3};" \
        : "+f"((c_)[0]), "+f"((c_)[1]), "+f"((c_)[2]), "+f"((c_)[3]) \
        : "r"((a_)[0]), "r"((a_)[1]), "r"((a_)[2]), "r"((a_)[3]), "r"(b0_), "r"(b1_))
#define MMA_F16(c_, a_, b0_, b1_) \
    asm volatile("mma.sync.aligned.m16n8k16.row.col.f32.f16.f16.f32 " \
        "{%0,%1,%2,%3}, {%4,%5,%6,%7}, {%8,%9}, {%0,%1,%2,%3};" \
        : "+f"((c_)[0]), "+f"((c_)[1]), "+f"((c_)[2]), "+f"((c_)[3]) \
        : "r"((a_)[0]), "r"((a_)[1]), "r"((a_)[2]), "r"((a_)[3]), "r"(b0_), "r"(b1_))
#define CP_ASYNC8(dst_, src_) \
    asm volatile("cp.async.ca.shared.global [%0], [%1], 8;" :: "r"(dst_), "l"(src_) : "memory")
#define CP_COMMIT() asm volatile("cp.async.commit_group;" ::: "memory")
#define CP_WAIT(n_)  asm volatile("cp.async.wait_group %0;" :: "n"(n_) : "memory")

// =======================================================================
// fp16 2-product GEMM, cp.async 4-stage: C = A(f16) @ (Wh+Wl)(f16)^T + bias
// CTA 128x128, BK=32, 256 thr (8 warps 2Mx4N), warp tile 64x32.
// =======================================================================
#define LDSB 40
#define GT_BYTES (128 * LDSB * 2)        // 10240
#define STAGE_BYTES (3 * GT_BYTES)       // A, Wh, Wl
#define NSTAGE 4
#define GEMM_SMEM (NSTAGE * STAGE_BYTES) // 122880

__device__ __forceinline__ void copy_stage(const __half* __restrict__ A,
                                           const __half* __restrict__ Wh,
                                           const __half* __restrict__ Wl,
                                           int K, int k0, uint32_t base, int tid) {
    const int chunk = tid & 7, row0 = tid >> 3;
    #pragma unroll
    for (int p = 0; p < 4; ++p) {
        const int r = row0 + p * 32;
        const uint32_t d = base + (uint32_t)(r * 80 + chunk * 8);
        const size_t s = (size_t)r * K + k0 + chunk * 4;
        CP_ASYNC8(d,                A + s);
        CP_ASYNC8(d + GT_BYTES,     Wh + s);
        CP_ASYNC8(d + 2 * GT_BYTES, Wl + s);
    }
}

__global__ void __launch_bounds__(256, 1) gemm_mma_kernel(
    const __half* __restrict__ A, const __half* __restrict__ Wh,
    const __half* __restrict__ Wl, const float* __restrict__ bias,
    float* __restrict__ C, int M, int N, int K) {
    extern __shared__ __align__(16) char gsm[];
    const uint32_t u0 = smem_u32(gsm);
    const int tid = threadIdx.x;
    const int lane = tid & 31, wid = tid >> 5;
    const int warp_m = wid & 1, warp_n = wid >> 1;

    const __half* Ag  = A  + (size_t)blockIdx.y * 128 * K;
    const __half* Whg = Wh + (size_t)blockIdx.x * 128 * K;
    const __half* Wlg = Wl + (size_t)blockIdx.x * 128 * K;

    const int a_m = (lane & 7) + ((lane >> 3) & 1) * 8;
    const int a_k = (lane >> 4) * 8;
    const int b_n = (lane & 7) + (lane >> 4) * 8;
    const int b_k = ((lane >> 3) & 1) * 8;

    float acc[4][4][4];
    #pragma unroll
    for (int i = 0; i < 4; i++)
        #pragma unroll
        for (int j = 0; j < 4; j++)
            #pragma unroll
            for (int t = 0; t < 4; t++) acc[i][j][t] = 0.f;

    const int NK = K / 32;
    // prologue: fill 3 stages
    #pragma unroll
    for (int s = 0; s < NSTAGE - 1; ++s) {
        if (s < NK) copy_stage(Ag, Whg, Wlg, K, s * 32, u0 + s * STAGE_BYTES, tid);
        CP_COMMIT();
    }

    for (int c = 0; c < NK; ++c) {
        CP_WAIT(NSTAGE - 2);
        __syncthreads();
        const uint32_t co = (uint32_t)(c % NSTAGE) * STAGE_BYTES;
        const uint32_t uA = u0 + co, uBh = u0 + co + GT_BYTES, uBl = u0 + co + 2 * GT_BYTES;
        #pragma unroll
        for (int ks = 0; ks < 2; ++ks) {
            uint32_t ah[4][4], bh[2][4], bl[2][4];
            #pragma unroll
            for (int mt = 0; mt < 4; ++mt) {
                uint32_t off = (uint32_t)((warp_m * 64 + mt * 16 + a_m) * LDSB + ks * 16 + a_k) * 2;
                LDMX4(ah[mt][0], ah[mt][1], ah[mt][2], ah[mt][3], uA + off);
            }
            #pragma unroll
            for (int np = 0; np < 2; ++np) {
                uint32_t off = (uint32_t)((warp_n * 32 + np * 16 + b_n) * LDSB + ks * 16 + b_k) * 2;
                LDMX4(bh[np][0], bh[np][1], bh[np][2], bh[np][3], uBh + off);
                LDMX4(bl[np][0], bl[np][1], bl[np][2], bl[np][3], uBl + off);
            }
            #pragma unroll
            for (int mt = 0; mt < 4; ++mt) {
                #pragma unroll
                for (int nt = 0; nt < 4; ++nt) {
                    const int np = nt >> 1, sel = (nt & 1) * 2;
                    MMA_F16(acc[mt][nt], ah[mt], bh[np][sel], bh[np][sel + 1]);
                    MMA_F16(acc[mt][nt], ah[mt], bl[np][sel], bl[np][sel + 1]);
                }
            }
        }
        // issue stage c+3 (its buffer was last read at iter c-1; sync above protects it)
        if (c + NSTAGE - 1 < NK)
            copy_stage(Ag, Whg, Wlg, K, (c + NSTAGE - 1) * 32,
                       u0 + (uint32_t)((c + NSTAGE - 1) % NSTAGE) * STAGE_BYTES, tid);
        CP_COMMIT();
    }

    const int g = lane >> 2, c2 = (lane & 3) * 2;
    const int rowb = blockIdx.y * 128 + warp_m * 64;
    const int colb = blockIdx.x * 128 + warp_n * 32;
    #pragma unroll
    for (int mt = 0; mt < 4; ++mt) {
        #pragma unroll
        for (int nt = 0; nt < 4; ++nt) {
            int row = rowb + mt * 16 + g;
            int col = colb + nt * 8 + c2;
            float b0 = 0.f, b1 = 0.f;
            if (bias) { b0 = bias[col]; b1 = bias[col + 1]; }
            *(float2*)(C + (size_t)row * N + col) =
                make_float2(acc[mt][nt][0] + b0, acc[mt][nt][1] + b1);
            *(float2*)(C + (size_t)(row + 8) * N + col) =
                make_float2(acc[mt][nt][2] + b0, acc[mt][nt][3] + b1);
        }
    }
}

// ---------------- weight hi/lo split ----------------
__global__ void wsplit_kernel(const float* __restrict__ W, __half* __restrict__ Wh,
                              __half* __restrict__ Wl, int n) {
    int i = blockIdx.x * blockDim.x + threadIdx.x;
    if (i < n) {
        float v = W[i];
        __half h = __float2half_rn(v);
        Wh[i] = h;
        Wl[i] = __float2half_rn(v - __half2float(h));
    }
}

// ---------------- layernorm -> fp16 ----------------
__global__ void layernorm_kernel(const float* __restrict__ in, __half* __restrict__ out,
                                 const float* __restrict__ g, const float* __restrict__ b,
                                 int C) {
    const int row = blockIdx.x;
    const float* x = in + (size_t)row * C;
    __half* y = out + (size_t)row * C;
    float s = 0.f, ss = 0.f;
    for (int i = threadIdx.x; i < C; i += blockDim.x) {
        float v = x[i]; s += v; ss += v * v;
    }
    __shared__ float red[2][32];
    #pragma unroll
    for (int o = 16; o; o >>= 1) {
        s  += __shfl_xor_sync(0xffffffffu, s,  o);
        ss += __shfl_xor_sync(0xffffffffu, ss, o);
    }
    int warp = threadIdx.x >> 5, lane = threadIdx.x & 31;
    if (lane == 0) { red[0][warp] = s; red[1][warp] = ss; }
    __syncthreads();
    int nw = blockDim.x >> 5;
    if (warp == 0) {
        s  = (lane < nw) ? red[0][lane] : 0.f;
        ss = (lane < nw) ? red[1][lane] : 0.f;
        #pragma unroll
        for (int o = 16; o; o >>= 1) {
            s  += __shfl_xor_sync(0xffffffffu, s,  o);
            ss += __shfl_xor_sync(0xffffffffu, ss, o);
        }
        if (lane == 0) { red[0][0] = s; red[1][0] = ss; }
    }
    __syncthreads();
    float invC = 1.f / (float)C;
    float mu  = red[0][0] * invC;
    float var = red[1][0] * invC - mu * mu;
    float rs  = rsqrtf(var + 1e-5f);
    for (int i = threadIdx.x; i < C; i += blockDim.x)
        y[i] = __float2half_rn((x[i] - mu) * rs * g[i] + b[i]);
}

// ---------------- per-head rmsnorm (fp32 in-place) ----------------
__global__ void rmsnorm_kernel(float* __restrict__ data, const float* __restrict__ g,
                               int nrows, int rowstride, int nchunks, float scale) {
    int wg   = (blockIdx.x * blockDim.x + threadIdx.x) >> 5;
    int lane = threadIdx.x & 31;
    int total = nrows * nchunks;
    if (wg >= total) return;
    int row = wg / nchunks;
    int chunk = wg - row * nchunks;
    float* p = data + (size_t)row * rowstride + chunk * DH;
    float v0 = p[lane], v1 = p[lane + 32];
    float ss = v0 * v0 + v1 * v1;
    #pragma unroll
    for (int o = 16; o; o >>= 1) ss += __shfl_xor_sync(0xffffffffu, ss, o);
    float norm = sqrtf(ss) * 0.125f;
    float r = scale / fmaxf(norm, 1e-8f);
    p[lane]      = v0 * r * g[lane];
    p[lane + 32] = v1 * r * g[lane + 32];
}

// =======================================================================
// flash attention via mma.sync split-bf16 (3-product), fp16 output.
// =======================================================================
#define QTILE 128
#define LDA 72
#define ATT_SMEM 73984

__global__ void __launch_bounds__(256, 1) attn_mma_kernel(
    const float* __restrict__ q, const float* __restrict__ kvx,
    const float* __restrict__ kvl, const int* __restrict__ mask,
    __half* __restrict__ out) {
    extern __shared__ __align__(16) char asmem[];
    const uint32_t u0 = smem_u32(asmem);
    const uint32_t uQh = u0, uQl = u0 + 18432;
    const uint32_t uKh = u0 + 36864, uKl = u0 + 46080;
    const uint32_t uVh = u0 + 55296, uVl = u0 + 64512;
    float* mkf = (float*)(asmem + 73728);

    const int qt = blockIdx.x, h = blockIdx.y, b = blockIdx.z;
    const int tid = threadIdx.x, lane = tid & 31, wid = tid >> 5;

    const float* qg = q + ((size_t)(b * M_LAT + qt * QTILE)) * D_INR + h * DH;
    #pragma unroll
    for (int i = 0; i < 8; ++i) {
        int id = tid + i * 256;
        int row = id >> 4, c4 = id & 15;
        float4 v = *(const float4*)(qg + (size_t)row * D_INR + c4 * 4);
        uint32_t h01, h23, l01, l23; cvt_hilo_bf(v, h01, h23, l01, l23);
        uint32_t off = (uint32_t)(row * LDA + c4 * 4) * 2;
        STS64(uQh + off, h01, h23);
        STS64(uQl + off, l01, l23);
    }
    __syncthreads();

    const int a_m = (lane & 7) + ((lane >> 3) & 1) * 8;
    const int a_k = (lane >> 4) * 8;
    uint32_t qh[4][4], ql[4][4];
    #pragma unroll
    for (int kc = 0; kc < 4; ++kc) {
        uint32_t off = (uint32_t)((wid * 16 + a_m) * LDA + kc * 16 + a_k) * 2;
        LDMX4(qh[kc][0], qh[kc][1], qh[kc][2], qh[kc][3], uQh + off);
        LDMX4(ql[kc][0], ql[kc][1], ql[kc][2], ql[kc][3], uQl + off);
    }

    float m0 = -3.0e38f, m8 = -3.0e38f, l0 = 0.f, l8 = 0.f;
    float O[8][4];
    #pragma unroll
    for (int i = 0; i < 8; ++i)
        #pragma unroll
        for (int j = 0; j < 4; ++j) O[i][j] = 0.f;

    const int b_n = (lane & 7) + (lane >> 4) * 8;
    const int b_k = ((lane >> 3) & 1) * 8;
    const int v_r = a_m;
    const int v_c = (lane >> 4) * 8;
    const int cq = (lane & 3) * 2;

    for (int j0 = 0; j0 < L_TOT; j0 += 64) {
        const bool in_x = (j0 < N_X);
        const float* kvb = in_x
            ? kvx + ((size_t)(b * N_X + j0)) * (2 * D_INR) + h * DH
            : kvl + ((size_t)(b * M_LAT + (j0 - N_X))) * (2 * D_INR) + h * DH;
        __syncthreads();
        #pragma unroll
        for (int i = 0; i < 4; ++i) {
            int id = tid + i * 256;
            int row = id >> 4, c4 = id & 15;
            float4 kv4 = *(const float4*)(kvb + (size_t)row * (2 * D_INR) + c4 * 4);
            float4 vv4 = *(const float4*)(kvb + (size_t)row * (2 * D_INR) + D_INR + c4 * 4);
            uint32_t off = (uint32_t)(row * LDA + c4 * 4) * 2;
            uint32_t h01, h23, l01, l23;
            cvt_hilo_bf(kv4, h01, h23, l01, l23);
            STS64(uKh + off, h01, h23); STS64(uKl + off, l01, l23);
            cvt_hilo_bf(vv4, h01, h23, l01, l23);
            STS64(uVh + off, h01, h23); STS64(uVl + off, l01, l23);
        }
        if (tid < 64) mkf[tid] = (!in_x || mask[b * N_X + j0 + tid]) ? 0.f : -3.0e38f;
        __syncthreads();

        float S[8][4];
        #pragma unroll
        for (int i = 0; i < 8; ++i) { S[i][0] = S[i][1] = S[i][2] = S[i][3] = 0.f; }
        #pragma unroll
        for (int kc = 0; kc < 4; ++kc) {
            #pragma unroll
            for (int ng = 0; ng < 4; ++ng) {
                uint32_t kh4[4], kl4[4];
                uint32_t off = (uint32_t)((ng * 16 + b_n) * LDA + kc * 16 + b_k) * 2;
                LDMX4(kh4[0], kh4[1], kh4[2], kh4[3], uKh + off);
                LDMX4(kl4[0], kl4[1], kl4[2], kl4[3], uKl + off);
                MMA_BF16(S[2 * ng],     qh[kc], kh4[0], kh4[1]);
                MMA_BF16(S[2 * ng],     qh[kc], kl4[0], kl4[1]);
                MMA_BF16(S[2 * ng],     ql[kc], kh4[0], kh4[1]);
                MMA_BF16(S[2 * ng + 1], qh[kc], kh4[2], kh4[3]);
                MMA_BF16(S[2 * ng + 1], qh[kc], kl4[2], kl4[3]);
                MMA_BF16(S[2 * ng + 1], ql[kc], kh4[2], kh4[3]);
            }
        }
        #pragma unroll
        for (int nt = 0; nt < 8; ++nt) {
            float a0 = mkf[nt * 8 + cq], a1 = mkf[nt * 8 + cq + 1];
            S[nt][0] += a0; S[nt][1] += a1; S[nt][2] += a0; S[nt][3] += a1;
        }
        float mx0 = -3.0e38f, mx8 = -3.0e38f;
        #pragma unroll
        for (int nt = 0; nt < 8; ++nt) {
            mx0 = fmaxf(mx0, fmaxf(S[nt][0], S[nt][1]));
            mx8 = fmaxf(mx8, fmaxf(S[nt][2], S[nt][3]));
        }
        mx0 = fmaxf(mx0, __shfl_xor_sync(0xffffffffu, mx0, 1));
        mx0 = fmaxf(mx0, __shfl_xor_sync(0xffffffffu, mx0, 2));
        mx8 = fmaxf(mx8, __shfl_xor_sync(0xffffffffu, mx8, 1));
        mx8 = fmaxf(mx8, __shfl_xor_sync(0xffffffffu, mx8, 2));
        float mn0 = fmaxf(m0, mx0), mn8 = fmaxf(m8, mx8);
        float c0r = __expf(m0 - mn0), c8r = __expf(m8 - mn8);
        m0 = mn0; m8 = mn8;
        float rs0 = 0.f, rs8 = 0.f;
        uint32_t ph[4][4], pl[4][4];
        #pragma unroll
        for (int nt = 0; nt < 8; ++nt) {
            float p0 = __expf(S[nt][0] - m0), p1 = __expf(S[nt][1] - m0);
            float p2 = __expf(S[nt][2] - m8), p3 = __expf(S[nt][3] - m8);
            rs0 += p0 + p1; rs8 += p2 + p3;
            uint32_t hA = pack_bf16(p0, p1), hB = pack_bf16(p2, p3);
            float r0 = p0 - __bfloat162float(__float2bfloat16_rn(p0));
            float r1 = p1 - __bfloat162float(__float2bfloat16_rn(p1));
            float r2 = p2 - __bfloat162float(__float2bfloat16_rn(p2));
            float r3 = p3 - __bfloat162float(__float2bfloat16_rn(p3));
            uint32_t lA = pack_bf16(r0, r1), lB = pack_bf16(r2, r3);
            const int kcI = nt >> 1, ap = (nt & 1) * 2;
            ph[kcI][ap] = hA; ph[kcI][ap + 1] = hB;
            pl[kcI][ap] = lA; pl[kcI][ap + 1] = lB;
        }
        rs0 += __shfl_xor_sync(0xffffffffu, rs0, 1);
        rs0 += __shfl_xor_sync(0xffffffffu, rs0, 2);
        rs8 += __shfl_xor_sync(0xffffffffu, rs8, 1);
        rs8 += __shfl_xor_sync(0xffffffffu, rs8, 2);
        l0 = l0 * c0r + rs0;
        l8 = l8 * c8r + rs8;
        #pragma unroll
        for (int dt = 0; dt < 8; ++dt) {
            O[dt][0] *= c0r; O[dt][1] *= c0r;
            O[dt][2] *= c8r; O[dt][3] *= c8r;
        }
        #pragma unroll
        for (int kc = 0; kc < 4; ++kc) {
            #pragma unroll
            for (int dg = 0; dg < 4; ++dg) {
                uint32_t vh4[4], vl4[4];
                uint32_t off = (uint32_t)((kc * 16 + v_r) * LDA + dg * 16 + v_c) * 2;
                LDMX4T(vh4[0], vh4[1], vh4[2], vh4[3], uVh + off);
                LDMX4T(vl4[0], vl4[1], vl4[2], vl4[3], uVl + off);
                MMA_BF16(O[2 * dg],     ph[kc], vh4[0], vh4[1]);
                MMA_BF16(O[2 * dg],     ph[kc], vl4[0], vl4[1]);
                MMA_BF16(O[2 * dg],     pl[kc], vh4[0], vh4[1]);
                MMA_BF16(O[2 * dg + 1], ph[kc], vh4[2], vh4[3]);
                MMA_BF16(O[2 * dg + 1], ph[kc], vl4[2], vl4[3]);
                MMA_BF16(O[2 * dg + 1], pl[kc], vh4[2], vh4[3]);
            }
        }
    }

    const float inv0 = 1.f / l0, inv8 = 1.f / l8;
    const int g = lane >> 2;
    __half* ob = out + ((size_t)(b * M_LAT + qt * QTILE + wid * 16 + g)) * D_INR + h * DH;
    #pragma unroll
    for (int dt = 0; dt < 8; ++dt) {
        int col = dt * 8 + cq;
        *(__half2*)(ob + col) = __floats2half2_rn(O[dt][0] * inv0, O[dt][1] * inv0);
        *(__half2*)(ob + (size_t)8 * D_INR + col) = __floats2half2_rn(O[dt][2] * inv8, O[dt][3] * inv8);
    }
}

// ---------------- launch ----------------
extern "C" void kernel_launch(void* const* d_in, const int* in_sizes, int n_in,
                              void* d_out, int out_size) {
    const float* x      = (const float*)d_in[0];
    const float* lat    = (const float*)d_in[1];
    const int*   mask   = (const int*)  d_in[2];
    const float* ln_x_g = (const float*)d_in[3];
    const float* ln_x_b = (const float*)d_in[4];
    const float* ln_l_g = (const float*)d_in[5];
    const float* ln_l_b = (const float*)d_in[6];
    const float* qn_g   = (const float*)d_in[7];
    const float* kn_g   = (const float*)d_in[8];
    const float* Wq     = (const float*)d_in[9];
    const float* Wkv    = (const float*)d_in[10];
    const float* Wlkv   = (const float*)d_in[11];
    const float* Wo     = (const float*)d_in[12];
    const float* bo     = (const float*)d_in[13];
    float* outp = (float*)d_out;

    __half *xnh, *lnh, *atth, *wqh, *wql, *wkvh, *wkvl, *wlkvh, *wlkvl, *woh, *wol;
    float *qb, *kvx, *kvl;
    cudaGetSymbolAddress((void**)&xnh,  g_xn_h);
    cudaGetSymbolAddress((void**)&lnh,  g_ln_h);
    cudaGetSymbolAddress((void**)&atth, g_att_h);
    cudaGetSymbolAddress((void**)&qb,   g_q);
    cudaGetSymbolAddress((void**)&kvx,  g_kvx);
    cudaGetSymbolAddress((void**)&kvl,  g_kvl);
    cudaGetSymbolAddress((void**)&wqh,  g_wq_h);   cudaGetSymbolAddress((void**)&wql,  g_wq_l);
    cudaGetSymbolAddress((void**)&wkvh, g_wkv_h);  cudaGetSymbolAddress((void**)&wkvl, g_wkv_l);
    cudaGetSymbolAddress((void**)&wlkvh,g_wlkv_h); cudaGetSymbolAddress((void**)&wlkvl,g_wlkv_l);
    cudaGetSymbolAddress((void**)&woh,  g_wo_h);   cudaGetSymbolAddress((void**)&wol,  g_wo_l);

    cudaFuncSetAttribute(gemm_mma_kernel, cudaFuncAttributeMaxDynamicSharedMemorySize, GEMM_SMEM);
    cudaFuncSetAttribute(attn_mma_kernel, cudaFuncAttributeMaxDynamicSharedMemorySize, ATT_SMEM);

    // 1) layernorms -> fp16 activations; weight splits
    layernorm_kernel<<<B_ * N_X,   256>>>(x,   xnh, ln_x_g, ln_x_b, D_IN);
    layernorm_kernel<<<B_ * M_LAT, 256>>>(lat, lnh, ln_l_g, ln_l_b, D_LAT);
    wsplit_kernel<<<(D_INR * D_LAT + 255) / 256, 256>>>(Wq, wqh, wql, D_INR * D_LAT);
    wsplit_kernel<<<(2 * D_INR * D_IN + 255) / 256, 256>>>(Wkv, wkvh, wkvl, 2 * D_INR * D_IN);
    wsplit_kernel<<<(2 * D_INR * D_LAT + 255) / 256, 256>>>(Wlkv, wlkvh, wlkvl, 2 * D_INR * D_LAT);
    wsplit_kernel<<<(D_LAT * D_INR + 255) / 256, 256>>>(Wo, woh, wol, D_LAT * D_INR);

    // 2) projections
    {
        dim3 g(D_INR / 128, (B_ * M_LAT) / 128);
        gemm_mma_kernel<<<g, 256, GEMM_SMEM>>>(lnh, wqh, wql, nullptr, qb, B_ * M_LAT, D_INR, D_LAT);
    }
    {
        dim3 g((2 * D_INR) / 128, (B_ * N_X) / 128);
        gemm_mma_kernel<<<g, 256, GEMM_SMEM>>>(xnh, wkvh, wkvl, nullptr, kvx, B_ * N_X, 2 * D_INR, D_IN);
    }
    {
        dim3 g((2 * D_INR) / 128, (B_ * M_LAT) / 128);
        gemm_mma_kernel<<<g, 256, GEMM_SMEM>>>(lnh, wlkvh, wlkvl, nullptr, kvl, B_ * M_LAT, 2 * D_INR, D_LAT);
    }

    // 3) head rmsnorms (q carries gamma * SCALE)
    rmsnorm_kernel<<<(B_ * M_LAT * HEADS) / 8, 256>>>(qb,  qn_g, B_ * M_LAT, D_INR,     HEADS, 0.125f);
    rmsnorm_kernel<<<(B_ * N_X  * HEADS) / 8, 256>>>(kvx, kn_g, B_ * N_X,  2 * D_INR, HEADS, 1.0f);
    rmsnorm_kernel<<<(B_ * M_LAT * HEADS) / 8, 256>>>(kvl, kn_g, B_ * M_LAT, 2 * D_INR, HEADS, 1.0f);

    // 4) attention -> fp16 output
    {
        dim3 g(M_LAT / QTILE, HEADS, B_);
        attn_mma_kernel<<<g, 256, ATT_SMEM>>>(qb, kvx, kvl, mask, atth);
    }

    // 5) output projection + bias (fp32 out)
    {
        dim3 g(D_LAT / 128, (B_ * M_LAT) / 128);
        gemm_mma_kernel<<<g, 256, GEMM_SMEM>>>(atth, woh, wol, bo, outp, B_ * M_LAT, D_LAT, D_INR);
    }
}

// round 7
// speedup vs baseline: 4.1788x; 1.1327x over previous
#include <cuda_runtime.h>
#include <cuda_bf16.h>
#include <cuda_fp16.h>
#include <cstdint>
#include <cstddef>

// ---------------- problem constants ----------------
#define B_    4
#define N_X   4096
#define M_LAT 512
#define D_IN  768
#define D_LAT 1024
#define D_INR 1024
#define HEADS 16
#define DH    64
#define L_TOT (N_X + M_LAT)   // 4608

// ---------------- scratch (no allocs allowed) ----------------
__device__ __half g_xn_h [(size_t)B_ * N_X  * D_IN ];
__device__ __half g_ln_h [(size_t)B_ * M_LAT * D_LAT];
__device__ __half g_att_h[(size_t)B_ * M_LAT * D_INR];
__device__ float  g_q  [(size_t)B_ * M_LAT * D_INR];
__device__ float  g_kvx[(size_t)B_ * N_X  * 2 * D_INR];
__device__ float  g_kvl[(size_t)B_ * M_LAT * 2 * D_INR];
__device__ __half g_wq_h [(size_t)D_INR * D_LAT],      g_wq_l [(size_t)D_INR * D_LAT];
__device__ __half g_wkv_h[(size_t)2 * D_INR * D_IN],   g_wkv_l[(size_t)2 * D_INR * D_IN];
__device__ __half g_wlkv_h[(size_t)2 * D_INR * D_LAT], g_wlkv_l[(size_t)2 * D_INR * D_LAT];
__device__ __half g_wo_h [(size_t)D_LAT * D_INR],      g_wo_l [(size_t)D_LAT * D_INR];
// fp16 hi/lo planes for attention
__device__ __half g_Kh[(size_t)B_ * L_TOT * D_INR], g_Kl[(size_t)B_ * L_TOT * D_INR];
__device__ __half g_Vh[(size_t)B_ * L_TOT * D_INR], g_Vl[(size_t)B_ * L_TOT * D_INR];
__device__ __half g_Qh[(size_t)B_ * M_LAT * D_INR], g_Ql[(size_t)B_ * M_LAT * D_INR];

__device__ __forceinline__ uint32_t smem_u32(const void* p) {
    uint32_t a;
    asm("{ .reg .u64 t; cvta.to.shared.u64 t, %1; cvt.u32.u64 %0, t; }" : "=r"(a) : "l"(p));
    return a;
}
__device__ __forceinline__ uint32_t pack_h(__half a, __half b) {
    return ((uint32_t)__half_as_ushort(b) << 16) | __half_as_ushort(a);
}

#define LDMX4(r0_, r1_, r2_, r3_, addr_) \
    asm volatile("ldmatrix.sync.aligned.m8n8.x4.shared.b16 {%0,%1,%2,%3}, [%4];" \
        : "=r"(r0_), "=r"(r1_), "=r"(r2_), "=r"(r3_) : "r"(addr_))
#define LDMX4T(r0_, r1_, r2_, r3_, addr_) \
    asm volatile("ldmatrix.sync.aligned.m8n8.x4.trans.shared.b16 {%0,%1,%2,%3}, [%4];" \
        : "=r"(r0_), "=r"(r1_), "=r"(r2_), "=r"(r3_) : "r"(addr_))
#define MMA_F16(c_, a_, b0_, b1_) \
    asm volatile("mma.sync.aligned.m16n8k16.row.col.f32.f16.f16.f32 " \
        "{%0,%1,%2,%3}, {%4,%5,%6,%7}, {%8,%9}, {%0,%1,%2,%3};" \
        : "+f"((c_)[0]), "+f"((c_)[1]), "+f"((c_)[2]), "+f"((c_)[3]) \
        : "r"((a_)[0]), "r"((a_)[1]), "r"((a_)[2]), "r"((a_)[3]), "r"(b0_), "r"(b1_))
#define CP_ASYNC8(dst_, src_) \
    asm volatile("cp.async.ca.shared.global [%0], [%1], 8;" :: "r"(dst_), "l"(src_) : "memory")
#define CP_ASYNC16(dst_, src_) \
    asm volatile("cp.async.cg.shared.global [%0], [%1], 16;" :: "r"(dst_), "l"(src_) : "memory")
#define CP_COMMIT() asm volatile("cp.async.commit_group;" ::: "memory")
#define CP_WAIT(n_)  asm volatile("cp.async.wait_group %0;" :: "n"(n_) : "memory")

// =======================================================================
// fp16 2-product GEMM, cp.async 4-stage (unchanged from R6 — proven)
// =======================================================================
#define LDSB 40
#define GT_BYTES (128 * LDSB * 2)
#define STAGE_BYTES (3 * GT_BYTES)
#define NSTAGE 4
#define GEMM_SMEM (NSTAGE * STAGE_BYTES)

__device__ __forceinline__ void copy_stage(const __half* __restrict__ A,
                                           const __half* __restrict__ Wh,
                                           const __half* __restrict__ Wl,
                                           int K, int k0, uint32_t base, int tid) {
    const int chunk = tid & 7, row0 = tid >> 3;
    #pragma unroll
    for (int p = 0; p < 4; ++p) {
        const int r = row0 + p * 32;
        const uint32_t d = base + (uint32_t)(r * 80 + chunk * 8);
        const size_t s = (size_t)r * K + k0 + chunk * 4;
        CP_ASYNC8(d,                A + s);
        CP_ASYNC8(d + GT_BYTES,     Wh + s);
        CP_ASYNC8(d + 2 * GT_BYTES, Wl + s);
    }
}

__global__ void __launch_bounds__(256, 1) gemm_mma_kernel(
    const __half* __restrict__ A, const __half* __restrict__ Wh,
    const __half* __restrict__ Wl, const float* __restrict__ bias,
    float* __restrict__ C, int M, int N, int K) {
    extern __shared__ __align__(16) char gsm[];
    const uint32_t u0 = smem_u32(gsm);
    const int tid = threadIdx.x;
    const int lane = tid & 31, wid = tid >> 5;
    const int warp_m = wid & 1, warp_n = wid >> 1;

    const __half* Ag  = A  + (size_t)blockIdx.y * 128 * K;
    const __half* Whg = Wh + (size_t)blockIdx.x * 128 * K;
    const __half* Wlg = Wl + (size_t)blockIdx.x * 128 * K;

    const int a_m = (lane & 7) + ((lane >> 3) & 1) * 8;
    const int a_k = (lane >> 4) * 8;
    const int b_n = (lane & 7) + (lane >> 4) * 8;
    const int b_k = ((lane >> 3) & 1) * 8;

    float acc[4][4][4];
    #pragma unroll
    for (int i = 0; i < 4; i++)
        #pragma unroll
        for (int j = 0; j < 4; j++)
            #pragma unroll
            for (int t = 0; t < 4; t++) acc[i][j][t] = 0.f;

    const int NK = K / 32;
    #pragma unroll
    for (int s = 0; s < NSTAGE - 1; ++s) {
        if (s < NK) copy_stage(Ag, Whg, Wlg, K, s * 32, u0 + s * STAGE_BYTES, tid);
        CP_COMMIT();
    }

    for (int c = 0; c < NK; ++c) {
        CP_WAIT(NSTAGE - 2);
        __syncthreads();
        const uint32_t co = (uint32_t)(c % NSTAGE) * STAGE_BYTES;
        const uint32_t uA = u0 + co, uBh = u0 + co + GT_BYTES, uBl = u0 + co + 2 * GT_BYTES;
        #pragma unroll
        for (int ks = 0; ks < 2; ++ks) {
            uint32_t ah[4][4], bh[2][4], bl[2][4];
            #pragma unroll
            for (int mt = 0; mt < 4; ++mt) {
                uint32_t off = (uint32_t)((warp_m * 64 + mt * 16 + a_m) * LDSB + ks * 16 + a_k) * 2;
                LDMX4(ah[mt][0], ah[mt][1], ah[mt][2], ah[mt][3], uA + off);
            }
            #pragma unroll
            for (int np = 0; np < 2; ++np) {
                uint32_t off = (uint32_t)((warp_n * 32 + np * 16 + b_n) * LDSB + ks * 16 + b_k) * 2;
                LDMX4(bh[np][0], bh[np][1], bh[np][2], bh[np][3], uBh + off);
                LDMX4(bl[np][0], bl[np][1], bl[np][2], bl[np][3], uBl + off);
            }
            #pragma unroll
            for (int mt = 0; mt < 4; ++mt) {
                #pragma unroll
                for (int nt = 0; nt < 4; ++nt) {
                    const int np = nt >> 1, sel = (nt & 1) * 2;
                    MMA_F16(acc[mt][nt], ah[mt], bh[np][sel], bh[np][sel + 1]);
                    MMA_F16(acc[mt][nt], ah[mt], bl[np][sel], bl[np][sel + 1]);
                }
            }
        }
        if (c + NSTAGE - 1 < NK)
            copy_stage(Ag, Whg, Wlg, K, (c + NSTAGE - 1) * 32,
                       u0 + (uint32_t)((c + NSTAGE - 1) % NSTAGE) * STAGE_BYTES, tid);
        CP_COMMIT();
    }

    const int g = lane >> 2, c2 = (lane & 3) * 2;
    const int rowb = blockIdx.y * 128 + warp_m * 64;
    const int colb = blockIdx.x * 128 + warp_n * 32;
    #pragma unroll
    for (int mt = 0; mt < 4; ++mt) {
        #pragma unroll
        for (int nt = 0; nt < 4; ++nt) {
            int row = rowb + mt * 16 + g;
            int col = colb + nt * 8 + c2;
            float b0 = 0.f, b1 = 0.f;
            if (bias) { b0 = bias[col]; b1 = bias[col + 1]; }
            *(float2*)(C + (size_t)row * N + col) =
                make_float2(acc[mt][nt][0] + b0, acc[mt][nt][1] + b1);
            *(float2*)(C + (size_t)(row + 8) * N + col) =
                make_float2(acc[mt][nt][2] + b0, acc[mt][nt][3] + b1);
        }
    }
}

// ---------------- weight hi/lo split (vectorized) ----------------
__global__ void wsplit_kernel(const float4* __restrict__ W, uint32_t* __restrict__ Wh,
                              uint32_t* __restrict__ Wl, int n4) {
    int i = blockIdx.x * blockDim.x + threadIdx.x;
    if (i >= n4) return;
    float4 v = W[i];
    __half h0 = __float2half_rn(v.x), h1 = __float2half_rn(v.y);
    __half h2 = __float2half_rn(v.z), h3 = __float2half_rn(v.w);
    __half l0 = __float2half_rn(v.x - __half2float(h0));
    __half l1 = __float2half_rn(v.y - __half2float(h1));
    __half l2 = __float2half_rn(v.z - __half2float(h2));
    __half l3 = __float2half_rn(v.w - __half2float(h3));
    Wh[i * 2]     = pack_h(h0, h1); Wh[i * 2 + 1] = pack_h(h2, h3);
    Wl[i * 2]     = pack_h(l0, l1); Wl[i * 2 + 1] = pack_h(l2, l3);
}

// ---------------- layernorm -> fp16 ----------------
__global__ void layernorm_kernel(const float* __restrict__ in, __half* __restrict__ out,
                                 const float* __restrict__ g, const float* __restrict__ b,
                                 int C) {
    const int row = blockIdx.x;
    const float* x = in + (size_t)row * C;
    __half* y = out + (size_t)row * C;
    float s = 0.f, ss = 0.f;
    for (int i = threadIdx.x; i < C; i += blockDim.x) {
        float v = x[i]; s += v; ss += v * v;
    }
    __shared__ float red[2][32];
    #pragma unroll
    for (int o = 16; o; o >>= 1) {
        s  += __shfl_xor_sync(0xffffffffu, s,  o);
        ss += __shfl_xor_sync(0xffffffffu, ss, o);
    }
    int warp = threadIdx.x >> 5, lane = threadIdx.x & 31;
    if (lane == 0) { red[0][warp] = s; red[1][warp] = ss; }
    __syncthreads();
    int nw = blockDim.x >> 5;
    if (warp == 0) {
        s  = (lane < nw) ? red[0][lane] : 0.f;
        ss = (lane < nw) ? red[1][lane] : 0.f;
        #pragma unroll
        for (int o = 16; o; o >>= 1) {
            s  += __shfl_xor_sync(0xffffffffu, s,  o);
            ss += __shfl_xor_sync(0xffffffffu, ss, o);
        }
        if (lane == 0) { red[0][0] = s; red[1][0] = ss; }
    }
    __syncthreads();
    float invC = 1.f / (float)C;
    float mu  = red[0][0] * invC;
    float var = red[1][0] * invC - mu * mu;
    float rs  = rsqrtf(var + 1e-5f);
    for (int i = threadIdx.x; i < C; i += blockDim.x)
        y[i] = __float2half_rn((x[i] - mu) * rs * g[i] + b[i]);
}

// ---------------- kv rmsnorm + hi/lo split into planes ----------------
// One warp per 64-chunk. 32 chunks per kv row: 0-15 = K (rmsnorm), 16-31 = V (plain).
__global__ void kv_split_kernel(const float* __restrict__ kv, const float* __restrict__ kg,
                                __half* __restrict__ Kh, __half* __restrict__ Kl,
                                __half* __restrict__ Vh, __half* __restrict__ Vl,
                                int R, int off) {
    int wg   = (blockIdx.x * blockDim.x + threadIdx.x) >> 5;
    int lane = threadIdx.x & 31;
    int row = wg >> 5, chunk = wg & 31;
    if (row >= B_ * R) return;
    int b = row / R, n = row - b * R;
    const float* src = kv + (size_t)row * (2 * D_INR) + chunk * DH;
    float v0 = src[lane], v1 = src[lane + 32];
    size_t drow = ((size_t)b * L_TOT + off + n) * D_INR;
    __half *Ph, *Pl;
    size_t d;
    if (chunk < 16) {
        float ss = v0 * v0 + v1 * v1;
        #pragma unroll
        for (int o = 16; o; o >>= 1) ss += __shfl_xor_sync(0xffffffffu, ss, o);
        float norm = sqrtf(ss) * 0.125f;
        float r = 1.f / fmaxf(norm, 1e-8f);
        v0 *= r * kg[lane]; v1 *= r * kg[lane + 32];
        Ph = Kh; Pl = Kl; d = drow + chunk * DH;
    } else {
        Ph = Vh; Pl = Vl; d = drow + (chunk - 16) * DH;
    }
    __half h0 = __float2half_rn(v0), h1 = __float2half_rn(v1);
    Ph[d + lane]      = h0; Pl[d + lane]      = __float2half_rn(v0 - __half2float(h0));
    Ph[d + lane + 32] = h1; Pl[d + lane + 32] = __float2half_rn(v1 - __half2float(h1));
}

// q rmsnorm (gamma * SCALE) + split. 16 chunks per row.
__global__ void q_split_kernel(const float* __restrict__ q, const float* __restrict__ qg,
                               __half* __restrict__ Qh, __half* __restrict__ Ql) {
    int wg   = (blockIdx.x * blockDim.x + threadIdx.x) >> 5;
    int lane = threadIdx.x & 31;
    int row = wg >> 4, chunk = wg & 15;
    if (row >= B_ * M_LAT) return;
    const float* src = q + (size_t)row * D_INR + chunk * DH;
    float v0 = src[lane], v1 = src[lane + 32];
    float ss = v0 * v0 + v1 * v1;
    #pragma unroll
    for (int o = 16; o; o >>= 1) ss += __shfl_xor_sync(0xffffffffu, ss, o);
    float norm = sqrtf(ss) * 0.125f;
    float r = 0.125f / fmaxf(norm, 1e-8f);
    v0 *= r * qg[lane]; v1 *= r * qg[lane + 32];
    size_t d = (size_t)row * D_INR + chunk * DH;
    __half h0 = __float2half_rn(v0), h1 = __float2half_rn(v1);
    Qh[d + lane]      = h0; Ql[d + lane]      = __float2half_rn(v0 - __half2float(h0));
    Qh[d + lane + 32] = h1; Ql[d + lane + 32] = __float2half_rn(v1 - __half2float(h1));
}

// =======================================================================
// flash attention: fp16 hi/lo 3-product, cp.async double-buffered K/V.
// Block 128 q-rows, 8 warps x 16 rows. 72 kv tiles of 64.
// =======================================================================
#define QTILE 128
#define LDA 72
// smem: Qh 18432, Ql 18432, 2 stages x (4 planes x 9216 + 512 mask) = 2 x 37376
#define AST_BYTES 37376
#define ATT_SMEM (36864 + 2 * AST_BYTES)   // 111616

__device__ __forceinline__ void att_stage_copy(
    uint32_t sb, const __half* __restrict__ Kh, const __half* __restrict__ Kl,
    const __half* __restrict__ Vh, const __half* __restrict__ Vl,
    const int* __restrict__ mask, size_t grow0, int hoff,
    int in_x, int mrow0, int tid) {
    #pragma unroll
    for (int i = 0; i < 8; ++i) {
        const int plane = i >> 1;
        const int sub = ((i & 1) << 8) + tid;
        const int row = sub >> 3, ch = sub & 7;
        const __half* base = (plane == 0) ? Kh : (plane == 1) ? Kl : (plane == 2) ? Vh : Vl;
        const __half* src = base + (grow0 + row) * (size_t)D_INR + hoff + ch * 8;
        const uint32_t dst = sb + (uint32_t)(plane * 9216 + row * 144 + ch * 16);
        CP_ASYNC16(dst, src);
    }
    if (in_x && tid < 16)
        CP_ASYNC16(sb + 36864 + tid * 16, mask + mrow0 + tid * 4);
}

__global__ void __launch_bounds__(256, 1) attn_mma_kernel(
    const __half* __restrict__ Qhp, const __half* __restrict__ Qlp,
    const __half* __restrict__ Khp, const __half* __restrict__ Klp,
    const __half* __restrict__ Vhp, const __half* __restrict__ Vlp,
    const int* __restrict__ mask, __half* __restrict__ out) {
    extern __shared__ __align__(16) char asmem[];
    const uint32_t u0 = smem_u32(asmem);
    const uint32_t uQh = u0, uQl = u0 + 18432;
    const uint32_t uST = u0 + 36864;

    const int qt = blockIdx.x, h = blockIdx.y, b = blockIdx.z;
    const int tid = threadIdx.x, lane = tid & 31, wid = tid >> 5;
    const int hoff = h * DH;
    const size_t qrow0 = (size_t)(b * M_LAT + qt * QTILE);
    const size_t brow0 = (size_t)b * L_TOT;

    // Q stage (group A)
    #pragma unroll
    for (int i = 0; i < 8; ++i) {
        const int plane = i >> 2;
        const int sub = ((i & 3) << 8) + tid;
        const int row = sub >> 3, ch = sub & 7;
        const __half* src = (plane ? Qlp : Qhp) + (qrow0 + row) * (size_t)D_INR + hoff + ch * 8;
        const uint32_t dst = (plane ? uQl : uQh) + (uint32_t)(row * 144 + ch * 16);
        CP_ASYNC16(dst, src);
    }
    CP_COMMIT();
    // stage 0 (group B)
    att_stage_copy(uST, Khp, Klp, Vhp, Vlp, mask, brow0, hoff, 1, b * N_X, tid);
    CP_COMMIT();
    CP_WAIT(1);        // Q ready
    __syncthreads();

    const int a_m = (lane & 7) + ((lane >> 3) & 1) * 8;
    const int a_k = (lane >> 4) * 8;
    uint32_t qh[4][4], ql[4][4];
    #pragma unroll
    for (int kc = 0; kc < 4; ++kc) {
        uint32_t off = (uint32_t)((wid * 16 + a_m) * LDA + kc * 16 + a_k) * 2;
        LDMX4(qh[kc][0], qh[kc][1], qh[kc][2], qh[kc][3], uQh + off);
        LDMX4(ql[kc][0], ql[kc][1], ql[kc][2], ql[kc][3], uQl + off);
    }

    float m0 = -3.0e38f, m8 = -3.0e38f, l0 = 0.f, l8 = 0.f;
    float O[8][4];
    #pragma unroll
    for (int i = 0; i < 8; ++i)
        #pragma unroll
        for (int j = 0; j < 4; ++j) O[i][j] = 0.f;

    const int b_n = (lane & 7) + (lane >> 4) * 8;
    const int b_k = ((lane >> 3) & 1) * 8;
    const int v_r = a_m;
    const int v_c = (lane >> 4) * 8;
    const int cq = (lane & 3) * 2;

    const int NT = L_TOT / 64;   // 72
    for (int t = 0; t < NT; ++t) {
        const int j0 = t * 64;
        const bool in_x = (j0 < N_X);
        __syncthreads();   // buffer (t+1)&1 fully consumed (at iter t-1)
        if (t + 1 < NT) {
            const int j1 = j0 + 64;
            att_stage_copy(uST + (uint32_t)((t + 1) & 1) * AST_BYTES,
                           Khp, Klp, Vhp, Vlp, mask, brow0 + j1, hoff,
                           (j1 < N_X) ? 1 : 0, b * N_X + j1, tid);
        }
        CP_COMMIT();
        CP_WAIT(1);
        __syncthreads();   // stage t ready for all threads

        const uint32_t sb = uST + (uint32_t)(t & 1) * AST_BYTES;
        const uint32_t uKh = sb, uKl = sb + 9216, uVh = sb + 18432, uVl = sb + 27648;
        const int* mi = (const int*)(asmem + (36864 + (size_t)(t & 1) * AST_BYTES + 36864));

        // S = Q K^T  (fp16 3-product: hh + hl + lh)
        float S[8][4];
        #pragma unroll
        for (int i = 0; i < 8; ++i) { S[i][0] = S[i][1] = S[i][2] = S[i][3] = 0.f; }
        #pragma unroll
        for (int kc = 0; kc < 4; ++kc) {
            #pragma unroll
            for (int ng = 0; ng < 4; ++ng) {
                uint32_t kh4[4], kl4[4];
                uint32_t off = (uint32_t)((ng * 16 + b_n) * LDA + kc * 16 + b_k) * 2;
                LDMX4(kh4[0], kh4[1], kh4[2], kh4[3], uKh + off);
                LDMX4(kl4[0], kl4[1], kl4[2], kl4[3], uKl + off);
                MMA_F16(S[2 * ng],     qh[kc], kh4[0], kh4[1]);
                MMA_F16(S[2 * ng],     qh[kc], kl4[0], kl4[1]);
                MMA_F16(S[2 * ng],     ql[kc], kh4[0], kh4[1]);
                MMA_F16(S[2 * ng + 1], qh[kc], kh4[2], kh4[3]);
                MMA_F16(S[2 * ng + 1], qh[kc], kl4[2], kl4[3]);
                MMA_F16(S[2 * ng + 1], ql[kc], kh4[2], kh4[3]);
            }
        }
        if (in_x) {
            #pragma unroll
            for (int nt = 0; nt < 8; ++nt) {
                float a0 = mi[nt * 8 + cq]     ? 0.f : -3.0e38f;
                float a1 = mi[nt * 8 + cq + 1] ? 0.f : -3.0e38f;
                S[nt][0] += a0; S[nt][1] += a1; S[nt][2] += a0; S[nt][3] += a1;
            }
        }
        float mx0 = -3.0e38f, mx8 = -3.0e38f;
        #pragma unroll
        for (int nt = 0; nt < 8; ++nt) {
            mx0 = fmaxf(mx0, fmaxf(S[nt][0], S[nt][1]));
            mx8 = fmaxf(mx8, fmaxf(S[nt][2], S[nt][3]));
        }
        mx0 = fmaxf(mx0, __shfl_xor_sync(0xffffffffu, mx0, 1));
        mx0 = fmaxf(mx0, __shfl_xor_sync(0xffffffffu, mx0, 2));
        mx8 = fmaxf(mx8, __shfl_xor_sync(0xffffffffu, mx8, 1));
        mx8 = fmaxf(mx8, __shfl_xor_sync(0xffffffffu, mx8, 2));
        float mn0 = fmaxf(m0, mx0), mn8 = fmaxf(m8, mx8);
        float c0r = __expf(m0 - mn0), c8r = __expf(m8 - mn8);
        m0 = mn0; m8 = mn8;
        float rs0 = 0.f, rs8 = 0.f;
        uint32_t ph[4][4], pl[4][4];
        #pragma unroll
        for (int nt = 0; nt < 8; ++nt) {
            float p0 = __expf(S[nt][0] - m0), p1 = __expf(S[nt][1] - m0);
            float p2 = __expf(S[nt][2] - m8), p3 = __expf(S[nt][3] - m8);
            rs0 += p0 + p1; rs8 += p2 + p3;
            __half h0 = __float2half_rn(p0), h1 = __float2half_rn(p1);
            __half h2 = __float2half_rn(p2), h3 = __float2half_rn(p3);
            uint32_t hA = pack_h(h0, h1), hB = pack_h(h2, h3);
            uint32_t lA = pack_h(__float2half_rn(p0 - __half2float(h0)),
                                 __float2half_rn(p1 - __half2float(h1)));
            uint32_t lB = pack_h(__float2half_rn(p2 - __half2float(h2)),
                                 __float2half_rn(p3 - __half2float(h3)));
            const int kcI = nt >> 1, ap = (nt & 1) * 2;
            ph[kcI][ap] = hA; ph[kcI][ap + 1] = hB;
            pl[kcI][ap] = lA; pl[kcI][ap + 1] = lB;
        }
        rs0 += __shfl_xor_sync(0xffffffffu, rs0, 1);
        rs0 += __shfl_xor_sync(0xffffffffu, rs0, 2);
        rs8 += __shfl_xor_sync(0xffffffffu, rs8, 1);
        rs8 += __shfl_xor_sync(0xffffffffu, rs8, 2);
        l0 = l0 * c0r + rs0;
        l8 = l8 * c8r + rs8;
        #pragma unroll
        for (int dt = 0; dt < 8; ++dt) {
            O[dt][0] *= c0r; O[dt][1] *= c0r;
            O[dt][2] *= c8r; O[dt][3] *= c8r;
        }
        // O += P V (fp16 3-product)
        #pragma unroll
        for (int kc = 0; kc < 4; ++kc) {
            #pragma unroll
            for (int dg = 0; dg < 4; ++dg) {
                uint32_t vh4[4], vl4[4];
                uint32_t off = (uint32_t)((kc * 16 + v_r) * LDA + dg * 16 + v_c) * 2;
                LDMX4T(vh4[0], vh4[1], vh4[2], vh4[3], uVh + off);
                LDMX4T(vl4[0], vl4[1], vl4[2], vl4[3], uVl + off);
                MMA_F16(O[2 * dg],     ph[kc], vh4[0], vh4[1]);
                MMA_F16(O[2 * dg],     ph[kc], vl4[0], vl4[1]);
                MMA_F16(O[2 * dg],     pl[kc], vh4[0], vh4[1]);
                MMA_F16(O[2 * dg + 1], ph[kc], vh4[2], vh4[3]);
                MMA_F16(O[2 * dg + 1], ph[kc], vl4[2], vl4[3]);
                MMA_F16(O[2 * dg + 1], pl[kc], vh4[2], vh4[3]);
            }
        }
    }

    const float inv0 = 1.f / l0, inv8 = 1.f / l8;
    const int g = lane >> 2;
    __half* ob = out + ((size_t)(b * M_LAT + qt * QTILE + wid * 16 + g)) * D_INR + hoff;
    #pragma unroll
    for (int dt = 0; dt < 8; ++dt) {
        int col = dt * 8 + cq;
        *(__half2*)(ob + col) = __floats2half2_rn(O[dt][0] * inv0, O[dt][1] * inv0);
        *(__half2*)(ob + (size_t)8 * D_INR + col) = __floats2half2_rn(O[dt][2] * inv8, O[dt][3] * inv8);
    }
}

// ---------------- launch ----------------
extern "C" void kernel_launch(void* const* d_in, const int* in_sizes, int n_in,
                              void* d_out, int out_size) {
    const float* x      = (const float*)d_in[0];
    const float* lat    = (const float*)d_in[1];
    const int*   mask   = (const int*)  d_in[2];
    const float* ln_x_g = (const float*)d_in[3];
    const float* ln_x_b = (const float*)d_in[4];
    const float* ln_l_g = (const float*)d_in[5];
    const float* ln_l_b = (const float*)d_in[6];
    const float* qn_g   = (const float*)d_in[7];
    const float* kn_g   = (const float*)d_in[8];
    const float* Wq     = (const float*)d_in[9];
    const float* Wkv    = (const float*)d_in[10];
    const float* Wlkv   = (const float*)d_in[11];
    const float* Wo     = (const float*)d_in[12];
    const float* bo     = (const float*)d_in[13];
    float* outp = (float*)d_out;

    __half *xnh, *lnh, *atth, *wqh, *wql, *wkvh, *wkvl, *wlkvh, *wlkvl, *woh, *wol;
    __half *Khp, *Klp, *Vhp, *Vlp, *Qhp, *Qlp;
    float *qb, *kvx, *kvl;
    cudaGetSymbolAddress((void**)&xnh,  g_xn_h);
    cudaGetSymbolAddress((void**)&lnh,  g_ln_h);
    cudaGetSymbolAddress((void**)&atth, g_att_h);
    cudaGetSymbolAddress((void**)&qb,   g_q);
    cudaGetSymbolAddress((void**)&kvx,  g_kvx);
    cudaGetSymbolAddress((void**)&kvl,  g_kvl);
    cudaGetSymbolAddress((void**)&wqh,  g_wq_h);   cudaGetSymbolAddress((void**)&wql,  g_wq_l);
    cudaGetSymbolAddress((void**)&wkvh, g_wkv_h);  cudaGetSymbolAddress((void**)&wkvl, g_wkv_l);
    cudaGetSymbolAddress((void**)&wlkvh,g_wlkv_h); cudaGetSymbolAddress((void**)&wlkvl,g_wlkv_l);
    cudaGetSymbolAddress((void**)&woh,  g_wo_h);   cudaGetSymbolAddress((void**)&wol,  g_wo_l);
    cudaGetSymbolAddress((void**)&Khp,  g_Kh);     cudaGetSymbolAddress((void**)&Klp,  g_Kl);
    cudaGetSymbolAddress((void**)&Vhp,  g_Vh);     cudaGetSymbolAddress((void**)&Vlp,  g_Vl);
    cudaGetSymbolAddress((void**)&Qhp,  g_Qh);     cudaGetSymbolAddress((void**)&Qlp,  g_Ql);

    cudaFuncSetAttribute(gemm_mma_kernel, cudaFuncAttributeMaxDynamicSharedMemorySize, GEMM_SMEM);
    cudaFuncSetAttribute(attn_mma_kernel, cudaFuncAttributeMaxDynamicSharedMemorySize, ATT_SMEM);

    // 1) layernorms -> fp16; weight splits
    layernorm_kernel<<<B_ * N_X,   256>>>(x,   xnh, ln_x_g, ln_x_b, D_IN);
    layernorm_kernel<<<B_ * M_LAT, 256>>>(lat, lnh, ln_l_g, ln_l_b, D_LAT);
    wsplit_kernel<<<(D_INR * D_LAT / 4 + 255) / 256, 256>>>((const float4*)Wq, (uint32_t*)wqh, (uint32_t*)wql, D_INR * D_LAT / 4);
    wsplit_kernel<<<(2 * D_INR * D_IN / 4 + 255) / 256, 256>>>((const float4*)Wkv, (uint32_t*)wkvh, (uint32_t*)wkvl, 2 * D_INR * D_IN / 4);
    wsplit_kernel<<<(2 * D_INR * D_LAT / 4 + 255) / 256, 256>>>((const float4*)Wlkv, (uint32_t*)wlkvh, (uint32_t*)wlkvl, 2 * D_INR * D_LAT / 4);
    wsplit_kernel<<<(D_LAT * D_INR / 4 + 255) / 256, 256>>>((const float4*)Wo, (uint32_t*)woh, (uint32_t*)wol, D_LAT * D_INR / 4);

    // 2) projections
    {
        dim3 g(D_INR / 128, (B_ * M_LAT) / 128);
        gemm_mma_kernel<<<g, 256, GEMM_SMEM>>>(lnh, wqh, wql, nullptr, qb, B_ * M_LAT, D_INR, D_LAT);
    }
    {
        dim3 g((2 * D_INR) / 128, (B_ * N_X) / 128);
        gemm_mma_kernel<<<g, 256, GEMM_SMEM>>>(xnh, wkvh, wkvl, nullptr, kvx, B_ * N_X, 2 * D_INR, D_IN);
    }
    {
        dim3 g((2 * D_INR) / 128, (B_ * M_LAT) / 128);
        gemm_mma_kernel<<<g, 256, GEMM_SMEM>>>(lnh, wlkvh, wlkvl, nullptr, kvl, B_ * M_LAT, 2 * D_INR, D_LAT);
    }

    // 3) rmsnorm + hi/lo split into planes
    q_split_kernel<<<(B_ * M_LAT * 16) / 8, 256>>>(qb, qn_g, Qhp, Qlp);
    kv_split_kernel<<<(B_ * N_X * 32) / 8,  256>>>(kvx, kn_g, Khp, Klp, Vhp, Vlp, N_X, 0);
    kv_split_kernel<<<(B_ * M_LAT * 32) / 8, 256>>>(kvl, kn_g, Khp, Klp, Vhp, Vlp, M_LAT, N_X);

    // 4) attention -> fp16 output
    {
        dim3 g(M_LAT / QTILE, HEADS, B_);
        attn_mma_kernel<<<g, 256, ATT_SMEM>>>(Qhp, Qlp, Khp, Klp, Vhp, Vlp, mask, atth);
    }

    // 5) output projection + bias (fp32 out)
    {
        dim3 g(D_LAT / 128, (B_ * M_LAT) / 128);
        gemm_mma_kernel<<<g, 256, GEMM_SMEM>>>(atth, woh, wol, bo, outp, B_ * M_LAT, D_LAT, D_INR);
    }
}

// round 8
// speedup vs baseline: 4.1795x; 1.0002x over previous
#include <cuda_runtime.h>
#include <cuda_bf16.h>
#include <cuda_fp16.h>
#include <cstdint>
#include <cstddef>

// ---------------- problem constants ----------------
#define B_    4
#define N_X   4096
#define M_LAT 512
#define D_IN  768
#define D_LAT 1024
#define D_INR 1024
#define HEADS 16
#define DH    64
#define L_TOT (N_X + M_LAT)   // 4608

// ---------------- scratch (no allocs allowed) ----------------
__device__ __half g_xn_h [(size_t)B_ * N_X  * D_IN ];
__device__ __half g_ln_h [(size_t)B_ * M_LAT * D_LAT];
__device__ __half g_att_h[(size_t)B_ * M_LAT * D_INR];
__device__ float  g_q  [(size_t)B_ * M_LAT * D_INR];
__device__ float  g_kvx[(size_t)B_ * N_X  * 2 * D_INR];
__device__ float  g_kvl[(size_t)B_ * M_LAT * 2 * D_INR];
__device__ __half g_wq_h [(size_t)D_INR * D_LAT],      g_wq_l [(size_t)D_INR * D_LAT];
__device__ __half g_wkv_h[(size_t)2 * D_INR * D_IN],   g_wkv_l[(size_t)2 * D_INR * D_IN];
__device__ __half g_wlkv_h[(size_t)2 * D_INR * D_LAT], g_wlkv_l[(size_t)2 * D_INR * D_LAT];
__device__ __half g_wo_h [(size_t)D_LAT * D_INR],      g_wo_l [(size_t)D_LAT * D_INR];
__device__ __half g_Kh[(size_t)B_ * L_TOT * D_INR], g_Kl[(size_t)B_ * L_TOT * D_INR];
__device__ __half g_Vh[(size_t)B_ * L_TOT * D_INR], g_Vl[(size_t)B_ * L_TOT * D_INR];
__device__ __half g_Qh[(size_t)B_ * M_LAT * D_INR], g_Ql[(size_t)B_ * M_LAT * D_INR];

__device__ __forceinline__ uint32_t smem_u32(const void* p) {
    uint32_t a;
    asm("{ .reg .u64 t; cvta.to.shared.u64 t, %1; cvt.u32.u64 %0, t; }" : "=r"(a) : "l"(p));
    return a;
}
__device__ __forceinline__ uint32_t pack_h(__half a, __half b) {
    return ((uint32_t)__half_as_ushort(b) << 16) | __half_as_ushort(a);
}

#define LDMX4(r0_, r1_, r2_, r3_, addr_) \
    asm volatile("ldmatrix.sync.aligned.m8n8.x4.shared.b16 {%0,%1,%2,%3}, [%4];" \
        : "=r"(r0_), "=r"(r1_), "=r"(r2_), "=r"(r3_) : "r"(addr_))
#define LDMX4T(r0_, r1_, r2_, r3_, addr_) \
    asm volatile("ldmatrix.sync.aligned.m8n8.x4.trans.shared.b16 {%0,%1,%2,%3}, [%4];" \
        : "=r"(r0_), "=r"(r1_), "=r"(r2_), "=r"(r3_) : "r"(addr_))
#define MMA_F16(c_, a_, b0_, b1_) \
    asm volatile("mma.sync.aligned.m16n8k16.row.col.f32.f16.f16.f32 " \
        "{%0,%1,%2,%3}, {%4,%5,%6,%7}, {%8,%9}, {%0,%1,%2,%3};" \
        : "+f"((c_)[0]), "+f"((c_)[1]), "+f"((c_)[2]), "+f"((c_)[3]) \
        : "r"((a_)[0]), "r"((a_)[1]), "r"((a_)[2]), "r"((a_)[3]), "r"(b0_), "r"(b1_))
#define CP_ASYNC8(dst_, src_) \
    asm volatile("cp.async.ca.shared.global [%0], [%1], 8;" :: "r"(dst_), "l"(src_) : "memory")
#define CP_ASYNC16(dst_, src_) \
    asm volatile("cp.async.cg.shared.global [%0], [%1], 16;" :: "r"(dst_), "l"(src_) : "memory")
#define CP_COMMIT() asm volatile("cp.async.commit_group;" ::: "memory")
#define CP_WAIT(n_)  asm volatile("cp.async.wait_group %0;" :: "n"(n_) : "memory")

// =======================================================================
// fp16 2-product GEMM, cp.async 4-stage (proven R6/R7)
// =======================================================================
#define LDSB 40
#define GT_BYTES (128 * LDSB * 2)
#define STAGE_BYTES (3 * GT_BYTES)
#define NSTAGE 4
#define GEMM_SMEM (NSTAGE * STAGE_BYTES)

__device__ __forceinline__ void copy_stage(const __half* __restrict__ A,
                                           const __half* __restrict__ Wh,
                                           const __half* __restrict__ Wl,
                                           int K, int k0, uint32_t base, int tid) {
    const int chunk = tid & 7, row0 = tid >> 3;
    #pragma unroll
    for (int p = 0; p < 4; ++p) {
        const int r = row0 + p * 32;
        const uint32_t d = base + (uint32_t)(r * 80 + chunk * 8);
        const size_t s = (size_t)r * K + k0 + chunk * 4;
        CP_ASYNC8(d,                A + s);
        CP_ASYNC8(d + GT_BYTES,     Wh + s);
        CP_ASYNC8(d + 2 * GT_BYTES, Wl + s);
    }
}

__global__ void __launch_bounds__(256, 1) gemm_mma_kernel(
    const __half* __restrict__ A, const __half* __restrict__ Wh,
    const __half* __restrict__ Wl, const float* __restrict__ bias,
    float* __restrict__ C, int M, int N, int K) {
    extern __shared__ __align__(16) char gsm[];
    const uint32_t u0 = smem_u32(gsm);
    const int tid = threadIdx.x;
    const int lane = tid & 31, wid = tid >> 5;
    const int warp_m = wid & 1, warp_n = wid >> 1;

    const __half* Ag  = A  + (size_t)blockIdx.y * 128 * K;
    const __half* Whg = Wh + (size_t)blockIdx.x * 128 * K;
    const __half* Wlg = Wl + (size_t)blockIdx.x * 128 * K;

    const int a_m = (lane & 7) + ((lane >> 3) & 1) * 8;
    const int a_k = (lane >> 4) * 8;
    const int b_n = (lane & 7) + (lane >> 4) * 8;
    const int b_k = ((lane >> 3) & 1) * 8;

    float acc[4][4][4];
    #pragma unroll
    for (int i = 0; i < 4; i++)
        #pragma unroll
        for (int j = 0; j < 4; j++)
            #pragma unroll
            for (int t = 0; t < 4; t++) acc[i][j][t] = 0.f;

    const int NK = K / 32;
    #pragma unroll
    for (int s = 0; s < NSTAGE - 1; ++s) {
        if (s < NK) copy_stage(Ag, Whg, Wlg, K, s * 32, u0 + s * STAGE_BYTES, tid);
        CP_COMMIT();
    }

    for (int c = 0; c < NK; ++c) {
        CP_WAIT(NSTAGE - 2);
        __syncthreads();
        const uint32_t co = (uint32_t)(c % NSTAGE) * STAGE_BYTES;
        const uint32_t uA = u0 + co, uBh = u0 + co + GT_BYTES, uBl = u0 + co + 2 * GT_BYTES;
        #pragma unroll
        for (int ks = 0; ks < 2; ++ks) {
            uint32_t ah[4][4], bh[2][4], bl[2][4];
            #pragma unroll
            for (int mt = 0; mt < 4; ++mt) {
                uint32_t off = (uint32_t)((warp_m * 64 + mt * 16 + a_m) * LDSB + ks * 16 + a_k) * 2;
                LDMX4(ah[mt][0], ah[mt][1], ah[mt][2], ah[mt][3], uA + off);
            }
            #pragma unroll
            for (int np = 0; np < 2; ++np) {
                uint32_t off = (uint32_t)((warp_n * 32 + np * 16 + b_n) * LDSB + ks * 16 + b_k) * 2;
                LDMX4(bh[np][0], bh[np][1], bh[np][2], bh[np][3], uBh + off);
                LDMX4(bl[np][0], bl[np][1], bl[np][2], bl[np][3], uBl + off);
            }
            #pragma unroll
            for (int mt = 0; mt < 4; ++mt) {
                #pragma unroll
                for (int nt = 0; nt < 4; ++nt) {
                    const int np = nt >> 1, sel = (nt & 1) * 2;
                    MMA_F16(acc[mt][nt], ah[mt], bh[np][sel], bh[np][sel + 1]);
                    MMA_F16(acc[mt][nt], ah[mt], bl[np][sel], bl[np][sel + 1]);
                }
            }
        }
        if (c + NSTAGE - 1 < NK)
            copy_stage(Ag, Whg, Wlg, K, (c + NSTAGE - 1) * 32,
                       u0 + (uint32_t)((c + NSTAGE - 1) % NSTAGE) * STAGE_BYTES, tid);
        CP_COMMIT();
    }

    const int g = lane >> 2, c2 = (lane & 3) * 2;
    const int rowb = blockIdx.y * 128 + warp_m * 64;
    const int colb = blockIdx.x * 128 + warp_n * 32;
    #pragma unroll
    for (int mt = 0; mt < 4; ++mt) {
        #pragma unroll
        for (int nt = 0; nt < 4; ++nt) {
            int row = rowb + mt * 16 + g;
            int col = colb + nt * 8 + c2;
            float b0 = 0.f, b1 = 0.f;
            if (bias) { b0 = bias[col]; b1 = bias[col + 1]; }
            *(float2*)(C + (size_t)row * N + col) =
                make_float2(acc[mt][nt][0] + b0, acc[mt][nt][1] + b1);
            *(float2*)(C + (size_t)(row + 8) * N + col) =
                make_float2(acc[mt][nt][2] + b0, acc[mt][nt][3] + b1);
        }
    }
}

// ---------------- weight hi/lo split ----------------
__global__ void wsplit_kernel(const float4* __restrict__ W, uint32_t* __restrict__ Wh,
                              uint32_t* __restrict__ Wl, int n4) {
    int i = blockIdx.x * blockDim.x + threadIdx.x;
    if (i >= n4) return;
    float4 v = W[i];
    __half h0 = __float2half_rn(v.x), h1 = __float2half_rn(v.y);
    __half h2 = __float2half_rn(v.z), h3 = __float2half_rn(v.w);
    __half l0 = __float2half_rn(v.x - __half2float(h0));
    __half l1 = __float2half_rn(v.y - __half2float(h1));
    __half l2 = __float2half_rn(v.z - __half2float(h2));
    __half l3 = __float2half_rn(v.w - __half2float(h3));
    Wh[i * 2]     = pack_h(h0, h1); Wh[i * 2 + 1] = pack_h(h2, h3);
    Wl[i * 2]     = pack_h(l0, l1); Wl[i * 2 + 1] = pack_h(l2, l3);
}

// ---------------- layernorm -> fp16 ----------------
__global__ void layernorm_kernel(const float* __restrict__ in, __half* __restrict__ out,
                                 const float* __restrict__ g, const float* __restrict__ b,
                                 int C) {
    const int row = blockIdx.x;
    const float* x = in + (size_t)row * C;
    __half* y = out + (size_t)row * C;
    float s = 0.f, ss = 0.f;
    for (int i = threadIdx.x; i < C; i += blockDim.x) {
        float v = x[i]; s += v; ss += v * v;
    }
    __shared__ float red[2][32];
    #pragma unroll
    for (int o = 16; o; o >>= 1) {
        s  += __shfl_xor_sync(0xffffffffu, s,  o);
        ss += __shfl_xor_sync(0xffffffffu, ss, o);
    }
    int warp = threadIdx.x >> 5, lane = threadIdx.x & 31;
    if (lane == 0) { red[0][warp] = s; red[1][warp] = ss; }
    __syncthreads();
    int nw = blockDim.x >> 5;
    if (warp == 0) {
        s  = (lane < nw) ? red[0][lane] : 0.f;
        ss = (lane < nw) ? red[1][lane] : 0.f;
        #pragma unroll
        for (int o = 16; o; o >>= 1) {
            s  += __shfl_xor_sync(0xffffffffu, s,  o);
            ss += __shfl_xor_sync(0xffffffffu, ss, o);
        }
        if (lane == 0) { red[0][0] = s; red[1][0] = ss; }
    }
    __syncthreads();
    float invC = 1.f / (float)C;
    float mu  = red[0][0] * invC;
    float var = red[1][0] * invC - mu * mu;
    float rs  = rsqrtf(var + 1e-5f);
    for (int i = threadIdx.x; i < C; i += blockDim.x)
        y[i] = __float2half_rn((x[i] - mu) * rs * g[i] + b[i]);
}

// ---------------- kv rmsnorm + hi/lo split into planes ----------------
__global__ void kv_split_kernel(const float* __restrict__ kv, const float* __restrict__ kg,
                                __half* __restrict__ Kh, __half* __restrict__ Kl,
                                __half* __restrict__ Vh, __half* __restrict__ Vl,
                                int R, int off) {
    int wg   = (blockIdx.x * blockDim.x + threadIdx.x) >> 5;
    int lane = threadIdx.x & 31;
    int row = wg >> 5, chunk = wg & 31;
    if (row >= B_ * R) return;
    int b = row / R, n = row - b * R;
    const float* src = kv + (size_t)row * (2 * D_INR) + chunk * DH;
    float v0 = src[lane], v1 = src[lane + 32];
    size_t drow = ((size_t)b * L_TOT + off + n) * D_INR;
    __half *Ph, *Pl;
    size_t d;
    if (chunk < 16) {
        float ss = v0 * v0 + v1 * v1;
        #pragma unroll
        for (int o = 16; o; o >>= 1) ss += __shfl_xor_sync(0xffffffffu, ss, o);
        float norm = sqrtf(ss) * 0.125f;
        float r = 1.f / fmaxf(norm, 1e-8f);
        v0 *= r * kg[lane]; v1 *= r * kg[lane + 32];
        Ph = Kh; Pl = Kl; d = drow + chunk * DH;
    } else {
        Ph = Vh; Pl = Vl; d = drow + (chunk - 16) * DH;
    }
    __half h0 = __float2half_rn(v0), h1 = __float2half_rn(v1);
    Ph[d + lane]      = h0; Pl[d + lane]      = __float2half_rn(v0 - __half2float(h0));
    Ph[d + lane + 32] = h1; Pl[d + lane + 32] = __float2half_rn(v1 - __half2float(h1));
}

__global__ void q_split_kernel(const float* __restrict__ q, const float* __restrict__ qg,
                               __half* __restrict__ Qh, __half* __restrict__ Ql) {
    int wg   = (blockIdx.x * blockDim.x + threadIdx.x) >> 5;
    int lane = threadIdx.x & 31;
    int row = wg >> 4, chunk = wg & 15;
    if (row >= B_ * M_LAT) return;
    const float* src = q + (size_t)row * D_INR + chunk * DH;
    float v0 = src[lane], v1 = src[lane + 32];
    float ss = v0 * v0 + v1 * v1;
    #pragma unroll
    for (int o = 16; o; o >>= 1) ss += __shfl_xor_sync(0xffffffffu, ss, o);
    float norm = sqrtf(ss) * 0.125f;
    float r = 0.125f / fmaxf(norm, 1e-8f);
    v0 *= r * qg[lane]; v1 *= r * qg[lane + 32];
    size_t d = (size_t)row * D_INR + chunk * DH;
    __half h0 = __float2half_rn(v0), h1 = __float2half_rn(v1);
    Qh[d + lane]      = h0; Ql[d + lane]      = __float2half_rn(v0 - __half2float(h0));
    Qh[d + lane + 32] = h1; Ql[d + lane + 32] = __float2half_rn(v1 - __half2float(h1));
}

// =======================================================================
// flash attention: QTILE=64, 128 threads (4 warps x 16 rows), 2 CTAs/SM.
// fp16 hi/lo 3-product, cp.async double-buffered K/V.
// =======================================================================
#define QTILE 64
#define LDA 72
#define AST_BYTES 37376     // 4 planes x 9216 + 512 mask
#define ATT_SMEM (18432 + 2 * AST_BYTES)   // 93184

__device__ __forceinline__ void att_stage_copy(
    uint32_t sb, const __half* __restrict__ Kh, const __half* __restrict__ Kl,
    const __half* __restrict__ Vh, const __half* __restrict__ Vl,
    const int* __restrict__ mask, size_t grow0, int hoff,
    int in_x, int mrow0, int tid) {
    #pragma unroll
    for (int i = 0; i < 16; ++i) {
        const int plane = i >> 2;
        const int sub = ((i & 3) << 7) + tid;
        const int row = sub >> 3, ch = sub & 7;
        const __half* base = (plane == 0) ? Kh : (plane == 1) ? Kl : (plane == 2) ? Vh : Vl;
        const __half* src = base + (grow0 + row) * (size_t)D_INR + hoff + ch * 8;
        const uint32_t dst = sb + (uint32_t)(plane * 9216 + row * 144 + ch * 16);
        CP_ASYNC16(dst, src);
    }
    if (in_x && tid < 16)
        CP_ASYNC16(sb + 36864 + tid * 16, mask + mrow0 + tid * 4);
}

__global__ void __launch_bounds__(128, 2) attn_mma_kernel(
    const __half* __restrict__ Qhp, const __half* __restrict__ Qlp,
    const __half* __restrict__ Khp, const __half* __restrict__ Klp,
    const __half* __restrict__ Vhp, const __half* __restrict__ Vlp,
    const int* __restrict__ mask, __half* __restrict__ out) {
    extern __shared__ __align__(16) char asmem[];
    const uint32_t u0 = smem_u32(asmem);
    const uint32_t uQh = u0, uQl = u0 + 9216;
    const uint32_t uST = u0 + 18432;

    const int qt = blockIdx.x, h = blockIdx.y, b = blockIdx.z;
    const int tid = threadIdx.x, lane = tid & 31, wid = tid >> 5;
    const int hoff = h * DH;
    const size_t qrow0 = (size_t)(b * M_LAT + qt * QTILE);
    const size_t brow0 = (size_t)b * L_TOT;

    // Q stage (64 rows x 2 planes)
    #pragma unroll
    for (int i = 0; i < 8; ++i) {
        const int plane = i >> 2;
        const int sub = ((i & 3) << 7) + tid;
        const int row = sub >> 3, ch = sub & 7;
        const __half* src = (plane ? Qlp : Qhp) + (qrow0 + row) * (size_t)D_INR + hoff + ch * 8;
        const uint32_t dst = (plane ? uQl : uQh) + (uint32_t)(row * 144 + ch * 16);
        CP_ASYNC16(dst, src);
    }
    CP_COMMIT();
    att_stage_copy(uST, Khp, Klp, Vhp, Vlp, mask, brow0, hoff, 1, b * N_X, tid);
    CP_COMMIT();
    CP_WAIT(1);
    __syncthreads();

    const int a_m = (lane & 7) + ((lane >> 3) & 1) * 8;
    const int a_k = (lane >> 4) * 8;
    uint32_t qh[4][4], ql[4][4];
    #pragma unroll
    for (int kc = 0; kc < 4; ++kc) {
        uint32_t off = (uint32_t)((wid * 16 + a_m) * LDA + kc * 16 + a_k) * 2;
        LDMX4(qh[kc][0], qh[kc][1], qh[kc][2], qh[kc][3], uQh + off);
        LDMX4(ql[kc][0], ql[kc][1], ql[kc][2], ql[kc][3], uQl + off);
    }

    float m0 = -3.0e38f, m8 = -3.0e38f, l0 = 0.f, l8 = 0.f;
    float O[8][4];
    #pragma unroll
    for (int i = 0; i < 8; ++i)
        #pragma unroll
        for (int j = 0; j < 4; ++j) O[i][j] = 0.f;

    const int b_n = (lane & 7) + (lane >> 4) * 8;
    const int b_k = ((lane >> 3) & 1) * 8;
    const int v_r = a_m;
    const int v_c = (lane >> 4) * 8;
    const int cq = (lane & 3) * 2;

    const int NT = L_TOT / 64;   // 72
    for (int t = 0; t < NT; ++t) {
        const int j0 = t * 64;
        const bool in_x = (j0 < N_X);
        __syncthreads();
        if (t + 1 < NT) {
            const int j1 = j0 + 64;
            att_stage_copy(uST + (uint32_t)((t + 1) & 1) * AST_BYTES,
                           Khp, Klp, Vhp, Vlp, mask, brow0 + j1, hoff,
                           (j1 < N_X) ? 1 : 0, b * N_X + j1, tid);
        }
        CP_COMMIT();
        CP_WAIT(1);
        __syncthreads();

        const uint32_t sb = uST + (uint32_t)(t & 1) * AST_BYTES;
        const uint32_t uKh = sb, uKl = sb + 9216, uVh = sb + 18432, uVl = sb + 27648;
        const int* mi = (const int*)(asmem + (18432 + (size_t)(t & 1) * AST_BYTES + 36864));

        float S[8][4];
        #pragma unroll
        for (int i = 0; i < 8; ++i) { S[i][0] = S[i][1] = S[i][2] = S[i][3] = 0.f; }
        #pragma unroll
        for (int kc = 0; kc < 4; ++kc) {
            #pragma unroll
            for (int ng = 0; ng < 4; ++ng) {
                uint32_t kh4[4], kl4[4];
                uint32_t off = (uint32_t)((ng * 16 + b_n) * LDA + kc * 16 + b_k) * 2;
                LDMX4(kh4[0], kh4[1], kh4[2], kh4[3], uKh + off);
                LDMX4(kl4[0], kl4[1], kl4[2], kl4[3], uKl + off);
                MMA_F16(S[2 * ng],     qh[kc], kh4[0], kh4[1]);
                MMA_F16(S[2 * ng],     qh[kc], kl4[0], kl4[1]);
                MMA_F16(S[2 * ng],     ql[kc], kh4[0], kh4[1]);
                MMA_F16(S[2 * ng + 1], qh[kc], kh4[2], kh4[3]);
                MMA_F16(S[2 * ng + 1], qh[kc], kl4[2], kl4[3]);
                MMA_F16(S[2 * ng + 1], ql[kc], kh4[2], kh4[3]);
            }
        }
        if (in_x) {
            #pragma unroll
            for (int nt = 0; nt < 8; ++nt) {
                float a0 = mi[nt * 8 + cq]     ? 0.f : -3.0e38f;
                float a1 = mi[nt * 8 + cq + 1] ? 0.f : -3.0e38f;
                S[nt][0] += a0; S[nt][1] += a1; S[nt][2] += a0; S[nt][3] += a1;
            }
        }
        float mx0 = -3.0e38f, mx8 = -3.0e38f;
        #pragma unroll
        for (int nt = 0; nt < 8; ++nt) {
            mx0 = fmaxf(mx0, fmaxf(S[nt][0], S[nt][1]));
            mx8 = fmaxf(mx8, fmaxf(S[nt][2], S[nt][3]));
        }
        mx0 = fmaxf(mx0, __shfl_xor_sync(0xffffffffu, mx0, 1));
        mx0 = fmaxf(mx0, __shfl_xor_sync(0xffffffffu, mx0, 2));
        mx8 = fmaxf(mx8, __shfl_xor_sync(0xffffffffu, mx8, 1));
        mx8 = fmaxf(mx8, __shfl_xor_sync(0xffffffffu, mx8, 2));
        float mn0 = fmaxf(m0, mx0), mn8 = fmaxf(m8, mx8);
        float c0r = __expf(m0 - mn0), c8r = __expf(m8 - mn8);
        m0 = mn0; m8 = mn8;
        float rs0 = 0.f, rs8 = 0.f;
        uint32_t ph[4][4], pl[4][4];
        #pragma unroll
        for (int nt = 0; nt < 8; ++nt) {
            float p0 = __expf(S[nt][0] - m0), p1 = __expf(S[nt][1] - m0);
            float p2 = __expf(S[nt][2] - m8), p3 = __expf(S[nt][3] - m8);
            rs0 += p0 + p1; rs8 += p2 + p3;
            __half h0 = __float2half_rn(p0), h1 = __float2half_rn(p1);
            __half h2 = __float2half_rn(p2), h3 = __float2half_rn(p3);
            uint32_t hA = pack_h(h0, h1), hB = pack_h(h2, h3);
            uint32_t lA = pack_h(__float2half_rn(p0 - __half2float(h0)),
                                 __float2half_rn(p1 - __half2float(h1)));
            uint32_t lB = pack_h(__float2half_rn(p2 - __half2float(h2)),
                                 __float2half_rn(p3 - __half2float(h3)));
            const int kcI = nt >> 1, ap = (nt & 1) * 2;
            ph[kcI][ap] = hA; ph[kcI][ap + 1] = hB;
            pl[kcI][ap] = lA; pl[kcI][ap + 1] = lB;
        }
        rs0 += __shfl_xor_sync(0xffffffffu, rs0, 1);
        rs0 += __shfl_xor_sync(0xffffffffu, rs0, 2);
        rs8 += __shfl_xor_sync(0xffffffffu, rs8, 1);
        rs8 += __shfl_xor_sync(0xffffffffu, rs8, 2);
        l0 = l0 * c0r + rs0;
        l8 = l8 * c8r + rs8;
        #pragma unroll
        for (int dt = 0; dt < 8; ++dt) {
            O[dt][0] *= c0r; O[dt][1] *= c0r;
            O[dt][2] *= c8r; O[dt][3] *= c8r;
        }
        #pragma unroll
        for (int kc = 0; kc < 4; ++kc) {
            #pragma unroll
            for (int dg = 0; dg < 4; ++dg) {
                uint32_t vh4[4], vl4[4];
                uint32_t off = (uint32_t)((kc * 16 + v_r) * LDA + dg * 16 + v_c) * 2;
                LDMX4T(vh4[0], vh4[1], vh4[2], vh4[3], uVh + off);
                LDMX4T(vl4[0], vl4[1], vl4[2], vl4[3], uVl + off);
                MMA_F16(O[2 * dg],     ph[kc], vh4[0], vh4[1]);
                MMA_F16(O[2 * dg],     ph[kc], vl4[0], vl4[1]);
                MMA_F16(O[2 * dg],     pl[kc], vh4[0], vh4[1]);
                MMA_F16(O[2 * dg + 1], ph[kc], vh4[2], vh4[3]);
                MMA_F16(O[2 * dg + 1], ph[kc], vl4[2], vl4[3]);
                MMA_F16(O[2 * dg + 1], pl[kc], vh4[2], vh4[3]);
            }
        }
    }

    const float inv0 = 1.f / l0, inv8 = 1.f / l8;
    const int g = lane >> 2;
    __half* ob = out + ((size_t)(b * M_LAT + qt * QTILE + wid * 16 + g)) * D_INR + hoff;
    #pragma unroll
    for (int dt = 0; dt < 8; ++dt) {
        int col = dt * 8 + cq;
        *(__half2*)(ob + col) = __floats2half2_rn(O[dt][0] * inv0, O[dt][1] * inv0);
        *(__half2*)(ob + (size_t)8 * D_INR + col) = __floats2half2_rn(O[dt][2] * inv8, O[dt][3] * inv8);
    }
}

// ---------------- launch ----------------
extern "C" void kernel_launch(void* const* d_in, const int* in_sizes, int n_in,
                              void* d_out, int out_size) {
    const float* x      = (const float*)d_in[0];
    const float* lat    = (const float*)d_in[1];
    const int*   mask   = (const int*)  d_in[2];
    const float* ln_x_g = (const float*)d_in[3];
    const float* ln_x_b = (const float*)d_in[4];
    const float* ln_l_g = (const float*)d_in[5];
    const float* ln_l_b = (const float*)d_in[6];
    const float* qn_g   = (const float*)d_in[7];
    const float* kn_g   = (const float*)d_in[8];
    const float* Wq     = (const float*)d_in[9];
    const float* Wkv    = (const float*)d_in[10];
    const float* Wlkv   = (const float*)d_in[11];
    const float* Wo     = (const float*)d_in[12];
    const float* bo     = (const float*)d_in[13];
    float* outp = (float*)d_out;

    __half *xnh, *lnh, *atth, *wqh, *wql, *wkvh, *wkvl, *wlkvh, *wlkvl, *woh, *wol;
    __half *Khp, *Klp, *Vhp, *Vlp, *Qhp, *Qlp;
    float *qb, *kvx, *kvl;
    cudaGetSymbolAddress((void**)&xnh,  g_xn_h);
    cudaGetSymbolAddress((void**)&lnh,  g_ln_h);
    cudaGetSymbolAddress((void**)&atth, g_att_h);
    cudaGetSymbolAddress((void**)&qb,   g_q);
    cudaGetSymbolAddress((void**)&kvx,  g_kvx);
    cudaGetSymbolAddress((void**)&kvl,  g_kvl);
    cudaGetSymbolAddress((void**)&wqh,  g_wq_h);   cudaGetSymbolAddress((void**)&wql,  g_wq_l);
    cudaGetSymbolAddress((void**)&wkvh, g_wkv_h);  cudaGetSymbolAddress((void**)&wkvl, g_wkv_l);
    cudaGetSymbolAddress((void**)&wlkvh,g_wlkv_h); cudaGetSymbolAddress((void**)&wlkvl,g_wlkv_l);
    cudaGetSymbolAddress((void**)&woh,  g_wo_h);   cudaGetSymbolAddress((void**)&wol,  g_wo_l);
    cudaGetSymbolAddress((void**)&Khp,  g_Kh);     cudaGetSymbolAddress((void**)&Klp,  g_Kl);
    cudaGetSymbolAddress((void**)&Vhp,  g_Vh);     cudaGetSymbolAddress((void**)&Vlp,  g_Vl);
    cudaGetSymbolAddress((void**)&Qhp,  g_Qh);     cudaGetSymbolAddress((void**)&Qlp,  g_Ql);

    cudaFuncSetAttribute(gemm_mma_kernel, cudaFuncAttributeMaxDynamicSharedMemorySize, GEMM_SMEM);
    cudaFuncSetAttribute(attn_mma_kernel, cudaFuncAttributeMaxDynamicSharedMemorySize, ATT_SMEM);

    // fork a second stream inside the capture (event fork/join)
    cudaStream_t s2;
    cudaStreamCreateWithFlags(&s2, cudaStreamNonBlocking);
    cudaEvent_t evF, evJ;
    cudaEventCreateWithFlags(&evF, cudaEventDisableTiming);
    cudaEventCreateWithFlags(&evJ, cudaEventDisableTiming);
    cudaEventRecord(evF, 0);
    cudaStreamWaitEvent(s2, evF, 0);

    // ---- stream 0 (x branch): layernorm x -> wsplit Wkv -> kv GEMM ----
    layernorm_kernel<<<B_ * N_X, 256>>>(x, xnh, ln_x_g, ln_x_b, D_IN);
    wsplit_kernel<<<(2 * D_INR * D_IN / 4 + 255) / 256, 256>>>(
        (const float4*)Wkv, (uint32_t*)wkvh, (uint32_t*)wkvl, 2 * D_INR * D_IN / 4);
    {
        dim3 g((2 * D_INR) / 128, (B_ * N_X) / 128);
        gemm_mma_kernel<<<g, 256, GEMM_SMEM>>>(xnh, wkvh, wkvl, nullptr, kvx, B_ * N_X, 2 * D_INR, D_IN);
    }

    // ---- stream s2 (lat branch): layernorm lat, wsplits, q/lkv GEMMs, q_split ----
    layernorm_kernel<<<B_ * M_LAT, 256, 0, s2>>>(lat, lnh, ln_l_g, ln_l_b, D_LAT);
    wsplit_kernel<<<(D_INR * D_LAT / 4 + 255) / 256, 256, 0, s2>>>(
        (const float4*)Wq, (uint32_t*)wqh, (uint32_t*)wql, D_INR * D_LAT / 4);
    wsplit_kernel<<<(2 * D_INR * D_LAT / 4 + 255) / 256, 256, 0, s2>>>(
        (const float4*)Wlkv, (uint32_t*)wlkvh, (uint32_t*)wlkvl, 2 * D_INR * D_LAT / 4);
    wsplit_kernel<<<(D_LAT * D_INR / 4 + 255) / 256, 256, 0, s2>>>(
        (const float4*)Wo, (uint32_t*)woh, (uint32_t*)wol, D_LAT * D_INR / 4);
    {
        dim3 g(D_INR / 128, (B_ * M_LAT) / 128);
        gemm_mma_kernel<<<g, 256, GEMM_SMEM, s2>>>(lnh, wqh, wql, nullptr, qb, B_ * M_LAT, D_INR, D_LAT);
    }
    {
        dim3 g((2 * D_INR) / 128, (B_ * M_LAT) / 128);
        gemm_mma_kernel<<<g, 256, GEMM_SMEM, s2>>>(lnh, wlkvh, wlkvl, nullptr, kvl, B_ * M_LAT, 2 * D_INR, D_LAT);
    }
    q_split_kernel<<<(B_ * M_LAT * 16) / 8, 256, 0, s2>>>(qb, qn_g, Qhp, Qlp);

    // ---- join ----
    cudaEventRecord(evJ, s2);
    cudaStreamWaitEvent(0, evJ, 0);

    // ---- stream 0: splits -> attention -> output projection ----
    kv_split_kernel<<<(B_ * N_X * 32) / 8,  256>>>(kvx, kn_g, Khp, Klp, Vhp, Vlp, N_X, 0);
    kv_split_kernel<<<(B_ * M_LAT * 32) / 8, 256>>>(kvl, kn_g, Khp, Klp, Vhp, Vlp, M_LAT, N_X);
    {
        dim3 g(M_LAT / QTILE, HEADS, B_);
        attn_mma_kernel<<<g, 128, ATT_SMEM>>>(Qhp, Qlp, Khp, Klp, Vhp, Vlp, mask, atth);
    }
    {
        dim3 g(D_LAT / 128, (B_ * M_LAT) / 128);
        gemm_mma_kernel<<<g, 256, GEMM_SMEM>>>(atth, woh, wol, bo, outp, B_ * M_LAT, D_LAT, D_INR);
    }
}

// round 10
// speedup vs baseline: 4.3542x; 1.0418x over previous
#include <cuda_runtime.h>
#include <cuda_bf16.h>
#include <cuda_fp16.h>
#include <cstdint>
#include <cstddef>

// ---------------- problem constants ----------------
#define B_    4
#define N_X   4096
#define M_LAT 512
#define D_IN  768
#define D_LAT 1024
#define D_INR 1024
#define HEADS 16
#define DH    64
#define L_TOT (N_X + M_LAT)   // 4608

// ---------------- scratch (no allocs allowed) ----------------
__device__ __half g_xn_h [(size_t)B_ * N_X  * D_IN ];
__device__ __half g_ln_h [(size_t)B_ * M_LAT * D_LAT];
__device__ __half g_att_h[(size_t)B_ * M_LAT * D_INR];
__device__ __half g_wq_h [(size_t)D_INR * D_LAT],      g_wq_l [(size_t)D_INR * D_LAT];
__device__ __half g_wkv_h[(size_t)2 * D_INR * D_IN],   g_wkv_l[(size_t)2 * D_INR * D_IN];
__device__ __half g_wlkv_h[(size_t)2 * D_INR * D_LAT], g_wlkv_l[(size_t)2 * D_INR * D_LAT];
__device__ __half g_wo_h [(size_t)D_LAT * D_INR],      g_wo_l [(size_t)D_LAT * D_INR];
__device__ __half g_Kh[(size_t)B_ * L_TOT * D_INR], g_Kl[(size_t)B_ * L_TOT * D_INR];
__device__ __half g_Vh[(size_t)B_ * L_TOT * D_INR], g_Vl[(size_t)B_ * L_TOT * D_INR];
__device__ __half g_Qh[(size_t)B_ * M_LAT * D_INR], g_Ql[(size_t)B_ * M_LAT * D_INR];

__device__ __forceinline__ uint32_t smem_u32(const void* p) {
    uint32_t a;
    asm("{ .reg .u64 t; cvta.to.shared.u64 t, %1; cvt.u32.u64 %0, t; }" : "=r"(a) : "l"(p));
    return a;
}
__device__ __forceinline__ uint32_t pack_h(__half a, __half b) {
    return ((uint32_t)__half_as_ushort(b) << 16) | __half_as_ushort(a);
}

#define LDMX4(r0_, r1_, r2_, r3_, addr_) \
    asm volatile("ldmatrix.sync.aligned.m8n8.x4.shared.b16 {%0,%1,%2,%3}, [%4];" \
        : "=r"(r0_), "=r"(r1_), "=r"(r2_), "=r"(r3_) : "r"(addr_))
#define LDMX4T(r0_, r1_, r2_, r3_, addr_) \
    asm volatile("ldmatrix.sync.aligned.m8n8.x4.trans.shared.b16 {%0,%1,%2,%3}, [%4];" \
        : "=r"(r0_), "=r"(r1_), "=r"(r2_), "=r"(r3_) : "r"(addr_))
#define MMA_F16(c_, a_, b0_, b1_) \
    asm volatile("mma.sync.aligned.m16n8k16.row.col.f32.f16.f16.f32 " \
        "{%0,%1,%2,%3}, {%4,%5,%6,%7}, {%8,%9}, {%0,%1,%2,%3};" \
        : "+f"((c_)[0]), "+f"((c_)[1]), "+f"((c_)[2]), "+f"((c_)[3]) \
        : "r"((a_)[0]), "r"((a_)[1]), "r"((a_)[2]), "r"((a_)[3]), "r"(b0_), "r"(b1_))
#define CP_ASYNC8(dst_, src_) \
    asm volatile("cp.async.ca.shared.global [%0], [%1], 8;" :: "r"(dst_), "l"(src_) : "memory")
#define CP_ASYNC16(dst_, src_) \
    asm volatile("cp.async.cg.shared.global [%0], [%1], 16;" :: "r"(dst_), "l"(src_) : "memory")
#define CP_COMMIT() asm volatile("cp.async.commit_group;" ::: "memory")
#define CP_WAIT(n_)  asm volatile("cp.async.wait_group %0;" :: "n"(n_) : "memory")

// =======================================================================
// fp16 2-product GEMM, cp.async 4-stage, fused epilogues:
//   mode 0: C(fp32) = A @ (Wh+Wl)^T + bias
//   mode 1: kv epilogue — K cols rmsnorm(gamma)+split -> Kh/Kl; V cols split -> Vh/Vl
//   mode 2: q  epilogue — rmsnorm(gamma)*SCALE+split -> P0h/P0l
// =======================================================================
#define LDSB 40
#define GT_BYTES (128 * LDSB * 2)
#define STAGE_BYTES (3 * GT_BYTES)
#define NSTAGE 4
#define GEMM_SMEM (NSTAGE * STAGE_BYTES)

__device__ __forceinline__ void copy_stage(const __half* __restrict__ A,
                                           const __half* __restrict__ Wh,
                                           const __half* __restrict__ Wl,
                                           int K, int k0, uint32_t base, int tid) {
    const int chunk = tid & 7, row0 = tid >> 3;
    #pragma unroll
    for (int p = 0; p < 4; ++p) {
        const int r = row0 + p * 32;
        const uint32_t d = base + (uint32_t)(r * 80 + chunk * 8);
        const size_t s = (size_t)r * K + k0 + chunk * 4;
        CP_ASYNC8(d,                A + s);
        CP_ASYNC8(d + GT_BYTES,     Wh + s);
        CP_ASYNC8(d + 2 * GT_BYTES, Wl + s);
    }
}

__global__ void __launch_bounds__(256, 1) gemm_mma_kernel(
    const __half* __restrict__ A, const __half* __restrict__ Wh,
    const __half* __restrict__ Wl, const float* __restrict__ bias,
    float* __restrict__ C, const float* __restrict__ gamma,
    __half* __restrict__ P0h, __half* __restrict__ P0l,
    __half* __restrict__ P1h, __half* __restrict__ P1l,
    int M, int N, int K, int R, int roff, int mode) {
    extern __shared__ __align__(16) char gsm[];
    __shared__ float sred[8][4][2][8];
    const uint32_t u0 = smem_u32(gsm);
    const int tid = threadIdx.x;
    const int lane = tid & 31, wid = tid >> 5;
    const int warp_m = wid & 1, warp_n = wid >> 1;

    const __half* Ag  = A  + (size_t)blockIdx.y * 128 * K;
    const __half* Whg = Wh + (size_t)blockIdx.x * 128 * K;
    const __half* Wlg = Wl + (size_t)blockIdx.x * 128 * K;

    const int a_m = (lane & 7) + ((lane >> 3) & 1) * 8;
    const int a_k = (lane >> 4) * 8;
    const int b_n = (lane & 7) + (lane >> 4) * 8;
    const int b_k = ((lane >> 3) & 1) * 8;

    float acc[4][4][4];
    #pragma unroll
    for (int i = 0; i < 4; i++)
        #pragma unroll
        for (int j = 0; j < 4; j++)
            #pragma unroll
            for (int t = 0; t < 4; t++) acc[i][j][t] = 0.f;

    const int NK = K / 32;
    #pragma unroll
    for (int s = 0; s < NSTAGE - 1; ++s) {
        if (s < NK) copy_stage(Ag, Whg, Wlg, K, s * 32, u0 + s * STAGE_BYTES, tid);
        CP_COMMIT();
    }

    for (int c = 0; c < NK; ++c) {
        CP_WAIT(NSTAGE - 2);
        __syncthreads();
        const uint32_t co = (uint32_t)(c % NSTAGE) * STAGE_BYTES;
        const uint32_t uA = u0 + co, uBh = u0 + co + GT_BYTES, uBl = u0 + co + 2 * GT_BYTES;
        #pragma unroll
        for (int ks = 0; ks < 2; ++ks) {
            uint32_t ah[4][4], bh[2][4], bl[2][4];
            #pragma unroll
            for (int mt = 0; mt < 4; ++mt) {
                uint32_t off = (uint32_t)((warp_m * 64 + mt * 16 + a_m) * LDSB + ks * 16 + a_k) * 2;
                LDMX4(ah[mt][0], ah[mt][1], ah[mt][2], ah[mt][3], uA + off);
            }
            #pragma unroll
            for (int np = 0; np < 2; ++np) {
                uint32_t off = (uint32_t)((warp_n * 32 + np * 16 + b_n) * LDSB + ks * 16 + b_k) * 2;
                LDMX4(bh[np][0], bh[np][1], bh[np][2], bh[np][3], uBh + off);
                LDMX4(bl[np][0], bl[np][1], bl[np][2], bl[np][3], uBl + off);
            }
            #pragma unroll
            for (int mt = 0; mt < 4; ++mt) {
                #pragma unroll
                for (int nt = 0; nt < 4; ++nt) {
                    const int np = nt >> 1, sel = (nt & 1) * 2;
                    MMA_F16(acc[mt][nt], ah[mt], bh[np][sel], bh[np][sel + 1]);
                    MMA_F16(acc[mt][nt], ah[mt], bl[np][sel], bl[np][sel + 1]);
                }
            }
        }
        if (c + NSTAGE - 1 < NK)
            copy_stage(Ag, Whg, Wlg, K, (c + NSTAGE - 1) * 32,
                       u0 + (uint32_t)((c + NSTAGE - 1) % NSTAGE) * STAGE_BYTES, tid);
        CP_COMMIT();
    }

    const int g = lane >> 2, c2 = (lane & 3) * 2;
    const int rowb = blockIdx.y * 128 + warp_m * 64;
    const int colb = blockIdx.x * 128 + warp_n * 32;

    if (mode == 0) {
        #pragma unroll
        for (int mt = 0; mt < 4; ++mt) {
            #pragma unroll
            for (int nt = 0; nt < 4; ++nt) {
                int row = rowb + mt * 16 + g;
                int col = colb + nt * 8 + c2;
                float b0 = 0.f, b1 = 0.f;
                if (bias) { b0 = bias[col]; b1 = bias[col + 1]; }
                *(float2*)(C + (size_t)row * N + col) =
                    make_float2(acc[mt][nt][0] + b0, acc[mt][nt][1] + b1);
                *(float2*)(C + (size_t)(row + 8) * N + col) =
                    make_float2(acc[mt][nt][2] + b0, acc[mt][nt][3] + b1);
            }
        }
        return;
    }

    // modes 1/2: hi/lo split epilogue with optional rmsnorm.
    // For mode 1 the K/V decision (colb < 1024) is uniform across the block:
    // each block covers a 128-col span that never straddles the 1024 boundary.
    const bool needNorm = (mode == 2) || (colb < 1024);
    float rr[4][2] = {{1.f,1.f},{1.f,1.f},{1.f,1.f},{1.f,1.f}};
    if (needNorm) {
        __syncthreads();    // mainloop smem reads done across warps
        #pragma unroll
        for (int mt = 0; mt < 4; ++mt) {
            float s0 = 0.f, s1 = 0.f;
            #pragma unroll
            for (int nt = 0; nt < 4; ++nt) {
                s0 += acc[mt][nt][0] * acc[mt][nt][0] + acc[mt][nt][1] * acc[mt][nt][1];
                s1 += acc[mt][nt][2] * acc[mt][nt][2] + acc[mt][nt][3] * acc[mt][nt][3];
            }
            s0 += __shfl_xor_sync(0xffffffffu, s0, 1);
            s0 += __shfl_xor_sync(0xffffffffu, s0, 2);
            s1 += __shfl_xor_sync(0xffffffffu, s1, 1);
            s1 += __shfl_xor_sync(0xffffffffu, s1, 2);
            if ((lane & 3) == 0) { sred[wid][mt][0][g] = s0; sred[wid][mt][1][g] = s1; }
        }
        __syncthreads();
        const int pw = wid ^ 2;   // partner warp covering the other 32 cols of the 64-chunk
        const float sb = (mode == 2) ? 0.125f : 1.0f;
        #pragma unroll
        for (int mt = 0; mt < 4; ++mt) {
            float t0 = sred[wid][mt][0][g] + sred[pw][mt][0][g];
            float t1 = sred[wid][mt][1][g] + sred[pw][mt][1][g];
            rr[mt][0] = sb / fmaxf(sqrtf(t0) * 0.125f, 1e-8f);
            rr[mt][1] = sb / fmaxf(sqrtf(t1) * 0.125f, 1e-8f);
        }
    }

    __half *Dh, *Dl;
    int cofs;
    size_t drow_base;
    if (mode == 1) {
        if (colb < 1024) { Dh = P0h; Dl = P0l; cofs = 0; }
        else             { Dh = P1h; Dl = P1l; cofs = 1024; }
        const int b0 = rowb / R;
        drow_base = (size_t)b0 * L_TOT + roff + (rowb - b0 * R);
    } else {
        Dh = P0h; Dl = P0l; cofs = 0;
        drow_base = (size_t)rowb;
    }

    #pragma unroll
    for (int mt = 0; mt < 4; ++mt) {
        #pragma unroll
        for (int nt = 0; nt < 4; ++nt) {
            const int col = colb + nt * 8 + c2;
            float ga = 1.f, gb = 1.f;
            if (needNorm) { ga = gamma[col & 63]; gb = gamma[(col + 1) & 63]; }
            const float v0 = acc[mt][nt][0] * rr[mt][0] * ga;
            const float v1 = acc[mt][nt][1] * rr[mt][0] * gb;
            const float v2 = acc[mt][nt][2] * rr[mt][1] * ga;
            const float v3 = acc[mt][nt][3] * rr[mt][1] * gb;
            const size_t prow = drow_base + mt * 16 + g;
            const size_t d0 = prow * D_INR + (col - cofs);
            const size_t d1 = (prow + 8) * D_INR + (col - cofs);
            __half h0 = __float2half_rn(v0), h1 = __float2half_rn(v1);
            __half h2 = __float2half_rn(v2), h3 = __float2half_rn(v3);
            *(uint32_t*)(Dh + d0) = pack_h(h0, h1);
            *(uint32_t*)(Dh + d1) = pack_h(h2, h3);
            *(uint32_t*)(Dl + d0) = pack_h(__float2half_rn(v0 - __half2float(h0)),
                                           __float2half_rn(v1 - __half2float(h1)));
            *(uint32_t*)(Dl + d1) = pack_h(__float2half_rn(v2 - __half2float(h2)),
                                           __float2half_rn(v3 - __half2float(h3)));
        }
    }
}

// ---------------- weight hi/lo split ----------------
__global__ void wsplit_kernel(const float4* __restrict__ W, uint32_t* __restrict__ Wh,
                              uint32_t* __restrict__ Wl, int n4) {
    int i = blockIdx.x * blockDim.x + threadIdx.x;
    if (i >= n4) return;
    float4 v = W[i];
    __half h0 = __float2half_rn(v.x), h1 = __float2half_rn(v.y);
    __half h2 = __float2half_rn(v.z), h3 = __float2half_rn(v.w);
    __half l0 = __float2half_rn(v.x - __half2float(h0));
    __half l1 = __float2half_rn(v.y - __half2float(h1));
    __half l2 = __float2half_rn(v.z - __half2float(h2));
    __half l3 = __float2half_rn(v.w - __half2float(h3));
    Wh[i * 2]     = pack_h(h0, h1); Wh[i * 2 + 1] = pack_h(h2, h3);
    Wl[i * 2]     = pack_h(l0, l1); Wl[i * 2 + 1] = pack_h(l2, l3);
}

// ---------------- layernorm -> fp16 ----------------
__global__ void layernorm_kernel(const float* __restrict__ in, __half* __restrict__ out,
                                 const float* __restrict__ g, const float* __restrict__ b,
                                 int C) {
    const int row = blockIdx.x;
    const float* x = in + (size_t)row * C;
    __half* y = out + (size_t)row * C;
    float s = 0.f, ss = 0.f;
    for (int i = threadIdx.x; i < C; i += blockDim.x) {
        float v = x[i]; s += v; ss += v * v;
    }
    __shared__ float red[2][32];
    #pragma unroll
    for (int o = 16; o; o >>= 1) {
        s  += __shfl_xor_sync(0xffffffffu, s,  o);
        ss += __shfl_xor_sync(0xffffffffu, ss, o);
    }
    int warp = threadIdx.x >> 5, lane = threadIdx.x & 31;
    if (lane == 0) { red[0][warp] = s; red[1][warp] = ss; }
    __syncthreads();
    int nw = blockDim.x >> 5;
    if (warp == 0) {
        s  = (lane < nw) ? red[0][lane] : 0.f;
        ss = (lane < nw) ? red[1][lane] : 0.f;
        #pragma unroll
        for (int o = 16; o; o >>= 1) {
            s  += __shfl_xor_sync(0xffffffffu, s,  o);
            ss += __shfl_xor_sync(0xffffffffu, ss, o);
        }
        if (lane == 0) { red[0][0] = s; red[1][0] = ss; }
    }
    __syncthreads();
    float invC = 1.f / (float)C;
    float mu  = red[0][0] * invC;
    float var = red[1][0] * invC - mu * mu;
    float rs  = rsqrtf(var + 1e-5f);
    for (int i = threadIdx.x; i < C; i += blockDim.x)
        y[i] = __float2half_rn((x[i] - mu) * rs * g[i] + b[i]);
}

// =======================================================================
// flash attention: QTILE=64, 128 threads, fp16 hi/lo 3-product (proven R8)
// =======================================================================
#define QTILE 64
#define LDA 72
#define AST_BYTES 37376
#define ATT_SMEM (18432 + 2 * AST_BYTES)

__device__ __forceinline__ void att_stage_copy(
    uint32_t sb, const __half* __restrict__ Kh, const __half* __restrict__ Kl,
    const __half* __restrict__ Vh, const __half* __restrict__ Vl,
    const int* __restrict__ mask, size_t grow0, int hoff,
    int in_x, int mrow0, int tid) {
    #pragma unroll
    for (int i = 0; i < 16; ++i) {
        const int plane = i >> 2;
        const int sub = ((i & 3) << 7) + tid;
        const int row = sub >> 3, ch = sub & 7;
        const __half* base = (plane == 0) ? Kh : (plane == 1) ? Kl : (plane == 2) ? Vh : Vl;
        const __half* src = base + (grow0 + row) * (size_t)D_INR + hoff + ch * 8;
        const uint32_t dst = sb + (uint32_t)(plane * 9216 + row * 144 + ch * 16);
        CP_ASYNC16(dst, src);
    }
    if (in_x && tid < 16)
        CP_ASYNC16(sb + 36864 + tid * 16, mask + mrow0 + tid * 4);
}

__global__ void __launch_bounds__(128, 2) attn_mma_kernel(
    const __half* __restrict__ Qhp, const __half* __restrict__ Qlp,
    const __half* __restrict__ Khp, const __half* __restrict__ Klp,
    const __half* __restrict__ Vhp, const __half* __restrict__ Vlp,
    const int* __restrict__ mask, __half* __restrict__ out) {
    extern __shared__ __align__(16) char asmem[];
    const uint32_t u0 = smem_u32(asmem);
    const uint32_t uQh = u0, uQl = u0 + 9216;
    const uint32_t uST = u0 + 18432;

    const int qt = blockIdx.x, h = blockIdx.y, b = blockIdx.z;
    const int tid = threadIdx.x, lane = tid & 31, wid = tid >> 5;
    const int hoff = h * DH;
    const size_t qrow0 = (size_t)(b * M_LAT + qt * QTILE);
    const size_t brow0 = (size_t)b * L_TOT;

    #pragma unroll
    for (int i = 0; i < 8; ++i) {
        const int plane = i >> 2;
        const int sub = ((i & 3) << 7) + tid;
        const int row = sub >> 3, ch = sub & 7;
        const __half* src = (plane ? Qlp : Qhp) + (qrow0 + row) * (size_t)D_INR + hoff + ch * 8;
        const uint32_t dst = (plane ? uQl : uQh) + (uint32_t)(row * 144 + ch * 16);
        CP_ASYNC16(dst, src);
    }
    CP_COMMIT();
    att_stage_copy(uST, Khp, Klp, Vhp, Vlp, mask, brow0, hoff, 1, b * N_X, tid);
    CP_COMMIT();
    CP_WAIT(1);
    __syncthreads();

    const int a_m = (lane & 7) + ((lane >> 3) & 1) * 8;
    const int a_k = (lane >> 4) * 8;
    uint32_t qh[4][4], ql[4][4];
    #pragma unroll
    for (int kc = 0; kc < 4; ++kc) {
        uint32_t off = (uint32_t)((wid * 16 + a_m) * LDA + kc * 16 + a_k) * 2;
        LDMX4(qh[kc][0], qh[kc][1], qh[kc][2], qh[kc][3], uQh + off);
        LDMX4(ql[kc][0], ql[kc][1], ql[kc][2], ql[kc][3], uQl + off);
    }

    float m0 = -3.0e38f, m8 = -3.0e38f, l0 = 0.f, l8 = 0.f;
    float O[8][4];
    #pragma unroll
    for (int i = 0; i < 8; ++i)
        #pragma unroll
        for (int j = 0; j < 4; ++j) O[i][j] = 0.f;

    const int b_n = (lane & 7) + (lane >> 4) * 8;
    const int b_k = ((lane >> 3) & 1) * 8;
    const int v_r = a_m;
    const int v_c = (lane >> 4) * 8;
    const int cq = (lane & 3) * 2;

    const int NT = L_TOT / 64;
    for (int t = 0; t < NT; ++t) {
        const int j0 = t * 64;
        const bool in_x = (j0 < N_X);
        __syncthreads();
        if (t + 1 < NT) {
            const int j1 = j0 + 64;
            att_stage_copy(uST + (uint32_t)((t + 1) & 1) * AST_BYTES,
                           Khp, Klp, Vhp, Vlp, mask, brow0 + j1, hoff,
                           (j1 < N_X) ? 1 : 0, b * N_X + j1, tid);
        }
        CP_COMMIT();
        CP_WAIT(1);
        __syncthreads();

        const uint32_t sb = uST + (uint32_t)(t & 1) * AST_BYTES;
        const uint32_t uKh = sb, uKl = sb + 9216, uVh = sb + 18432, uVl = sb + 27648;
        const int* mi = (const int*)(asmem + (18432 + (size_t)(t & 1) * AST_BYTES + 36864));

        float S[8][4];
        #pragma unroll
        for (int i = 0; i < 8; ++i) { S[i][0] = S[i][1] = S[i][2] = S[i][3] = 0.f; }
        #pragma unroll
        for (int kc = 0; kc < 4; ++kc) {
            #pragma unroll
            for (int ng = 0; ng < 4; ++ng) {
                uint32_t kh4[4], kl4[4];
                uint32_t off = (uint32_t)((ng * 16 + b_n) * LDA + kc * 16 + b_k) * 2;
                LDMX4(kh4[0], kh4[1], kh4[2], kh4[3], uKh + off);
                LDMX4(kl4[0], kl4[1], kl4[2], kl4[3], uKl + off);
                MMA_F16(S[2 * ng],     qh[kc], kh4[0], kh4[1]);
                MMA_F16(S[2 * ng],     qh[kc], kl4[0], kl4[1]);
                MMA_F16(S[2 * ng],     ql[kc], kh4[0], kh4[1]);
                MMA_F16(S[2 * ng + 1], qh[kc], kh4[2], kh4[3]);
                MMA_F16(S[2 * ng + 1], qh[kc], kl4[2], kl4[3]);
                MMA_F16(S[2 * ng + 1], ql[kc], kh4[2], kh4[3]);
            }
        }
        if (in_x) {
            #pragma unroll
            for (int nt = 0; nt < 8; ++nt) {
                float a0 = mi[nt * 8 + cq]     ? 0.f : -3.0e38f;
                float a1 = mi[nt * 8 + cq + 1] ? 0.f : -3.0e38f;
                S[nt][0] += a0; S[nt][1] += a1; S[nt][2] += a0; S[nt][3] += a1;
            }
        }
        float mx0 = -3.0e38f, mx8 = -3.0e38f;
        #pragma unroll
        for (int nt = 0; nt < 8; ++nt) {
            mx0 = fmaxf(mx0, fmaxf(S[nt][0], S[nt][1]));
            mx8 = fmaxf(mx8, fmaxf(S[nt][2], S[nt][3]));
        }
        mx0 = fmaxf(mx0, __shfl_xor_sync(0xffffffffu, mx0, 1));
        mx0 = fmaxf(mx0, __shfl_xor_sync(0xffffffffu, mx0, 2));
        mx8 = fmaxf(mx8, __shfl_xor_sync(0xffffffffu, mx8, 1));
        mx8 = fmaxf(mx8, __shfl_xor_sync(0xffffffffu, mx8, 2));
        float mn0 = fmaxf(m0, mx0), mn8 = fmaxf(m8, mx8);
        float c0r = __expf(m0 - mn0), c8r = __expf(m8 - mn8);
        m0 = mn0; m8 = mn8;
        float rs0 = 0.f, rs8 = 0.f;
        uint32_t ph[4][4], pl[4][4];
        #pragma unroll
        for (int nt = 0; nt < 8; ++nt) {
            float p0 = __expf(S[nt][0] - m0), p1 = __expf(S[nt][1] - m0);
            float p2 = __expf(S[nt][2] - m8), p3 = __expf(S[nt][3] - m8);
            rs0 += p0 + p1; rs8 += p2 + p3;
            __half h0 = __float2half_rn(p0), h1 = __float2half_rn(p1);
            __half h2 = __float2half_rn(p2), h3 = __float2half_rn(p3);
            uint32_t hA = pack_h(h0, h1), hB = pack_h(h2, h3);
            uint32_t lA = pack_h(__float2half_rn(p0 - __half2float(h0)),
                                 __float2half_rn(p1 - __half2float(h1)));
            uint32_t lB = pack_h(__float2half_rn(p2 - __half2float(h2)),
                                 __float2half_rn(p3 - __half2float(h3)));
            const int kcI = nt >> 1, ap = (nt & 1) * 2;
            ph[kcI][ap] = hA; ph[kcI][ap + 1] = hB;
            pl[kcI][ap] = lA; pl[kcI][ap + 1] = lB;
        }
        rs0 += __shfl_xor_sync(0xffffffffu, rs0, 1);
        rs0 += __shfl_xor_sync(0xffffffffu, rs0, 2);
        rs8 += __shfl_xor_sync(0xffffffffu, rs8, 1);
        rs8 += __shfl_xor_sync(0xffffffffu, rs8, 2);
        l0 = l0 * c0r + rs0;
        l8 = l8 * c8r + rs8;
        #pragma unroll
        for (int dt = 0; dt < 8; ++dt) {
            O[dt][0] *= c0r; O[dt][1] *= c0r;
            O[dt][2] *= c8r; O[dt][3] *= c8r;
        }
        #pragma unroll
        for (int kc = 0; kc < 4; ++kc) {
            #pragma unroll
            for (int dg = 0; dg < 4; ++dg) {
                uint32_t vh4[4], vl4[4];
                uint32_t off = (uint32_t)((kc * 16 + v_r) * LDA + dg * 16 + v_c) * 2;
                LDMX4T(vh4[0], vh4[1], vh4[2], vh4[3], uVh + off);
                LDMX4T(vl4[0], vl4[1], vl4[2], vl4[3], uVl + off);
                MMA_F16(O[2 * dg],     ph[kc], vh4[0], vh4[1]);
                MMA_F16(O[2 * dg],     ph[kc], vl4[0], vl4[1]);
                MMA_F16(O[2 * dg],     pl[kc], vh4[0], vh4[1]);
                MMA_F16(O[2 * dg + 1], ph[kc], vh4[2], vh4[3]);
                MMA_F16(O[2 * dg + 1], ph[kc], vl4[2], vl4[3]);
                MMA_F16(O[2 * dg + 1], pl[kc], vh4[2], vh4[3]);
            }
        }
    }

    const float inv0 = 1.f / l0, inv8 = 1.f / l8;
    const int g = lane >> 2;
    __half* ob = out + ((size_t)(b * M_LAT + qt * QTILE + wid * 16 + g)) * D_INR + hoff;
    #pragma unroll
    for (int dt = 0; dt < 8; ++dt) {
        int col = dt * 8 + cq;
        *(__half2*)(ob + col) = __floats2half2_rn(O[dt][0] * inv0, O[dt][1] * inv0);
        *(__half2*)(ob + (size_t)8 * D_INR + col) = __floats2half2_rn(O[dt][2] * inv8, O[dt][3] * inv8);
    }
}

// ---------------- launch ----------------
extern "C" void kernel_launch(void* const* d_in, const int* in_sizes, int n_in,
                              void* d_out, int out_size) {
    const float* x      = (const float*)d_in[0];
    const float* lat    = (const float*)d_in[1];
    const int*   mask   = (const int*)  d_in[2];
    const float* ln_x_g = (const float*)d_in[3];
    const float* ln_x_b = (const float*)d_in[4];
    const float* ln_l_g = (const float*)d_in[5];
    const float* ln_l_b = (const float*)d_in[6];
    const float* qn_g   = (const float*)d_in[7];
    const float* kn_g   = (const float*)d_in[8];
    const float* Wq     = (const float*)d_in[9];
    const float* Wkv    = (const float*)d_in[10];
    const float* Wlkv   = (const float*)d_in[11];
    const float* Wo     = (const float*)d_in[12];
    const float* bo     = (const float*)d_in[13];
    float* outp = (float*)d_out;

    __half *xnh, *lnh, *atth, *wqh, *wql, *wkvh, *wkvl, *wlkvh, *wlkvl, *woh, *wol;
    __half *Khp, *Klp, *Vhp, *Vlp, *Qhp, *Qlp;
    cudaGetSymbolAddress((void**)&xnh,  g_xn_h);
    cudaGetSymbolAddress((void**)&lnh,  g_ln_h);
    cudaGetSymbolAddress((void**)&atth, g_att_h);
    cudaGetSymbolAddress((void**)&wqh,  g_wq_h);   cudaGetSymbolAddress((void**)&wql,  g_wq_l);
    cudaGetSymbolAddress((void**)&wkvh, g_wkv_h);  cudaGetSymbolAddress((void**)&wkvl, g_wkv_l);
    cudaGetSymbolAddress((void**)&wlkvh,g_wlkv_h); cudaGetSymbolAddress((void**)&wlkvl,g_wlkv_l);
    cudaGetSymbolAddress((void**)&woh,  g_wo_h);   cudaGetSymbolAddress((void**)&wol,  g_wo_l);
    cudaGetSymbolAddress((void**)&Khp,  g_Kh);     cudaGetSymbolAddress((void**)&Klp,  g_Kl);
    cudaGetSymbolAddress((void**)&Vhp,  g_Vh);     cudaGetSymbolAddress((void**)&Vlp,  g_Vl);
    cudaGetSymbolAddress((void**)&Qhp,  g_Qh);     cudaGetSymbolAddress((void**)&Qlp,  g_Ql);

    cudaFuncSetAttribute(gemm_mma_kernel, cudaFuncAttributeMaxDynamicSharedMemorySize, GEMM_SMEM);
    cudaFuncSetAttribute(attn_mma_kernel, cudaFuncAttributeMaxDynamicSharedMemorySize, ATT_SMEM);

    cudaStream_t s2;
    cudaStreamCreateWithFlags(&s2, cudaStreamNonBlocking);
    cudaEvent_t evF, evJ;
    cudaEventCreateWithFlags(&evF, cudaEventDisableTiming);
    cudaEventCreateWithFlags(&evJ, cudaEventDisableTiming);
    cudaEventRecord(evF, 0);
    cudaStreamWaitEvent(s2, evF, 0);

    // ---- stream 0 (x branch): layernorm x -> wsplit Wkv -> kv GEMM (fused kv split) ----
    layernorm_kernel<<<B_ * N_X, 256>>>(x, xnh, ln_x_g, ln_x_b, D_IN);
    wsplit_kernel<<<(2 * D_INR * D_IN / 4 + 255) / 256, 256>>>(
        (const float4*)Wkv, (uint32_t*)wkvh, (uint32_t*)wkvl, 2 * D_INR * D_IN / 4);
    {
        dim3 g((2 * D_INR) / 128, (B_ * N_X) / 128);
        gemm_mma_kernel<<<g, 256, GEMM_SMEM>>>(xnh, wkvh, wkvl, nullptr, nullptr, kn_g,
                                               Khp, Klp, Vhp, Vlp,
                                               B_ * N_X, 2 * D_INR, D_IN, N_X, 0, 1);
    }

    // ---- stream s2 (lat branch) ----
    layernorm_kernel<<<B_ * M_LAT, 256, 0, s2>>>(lat, lnh, ln_l_g, ln_l_b, D_LAT);
    wsplit_kernel<<<(D_INR * D_LAT / 4 + 255) / 256, 256, 0, s2>>>(
        (const float4*)Wq, (uint32_t*)wqh, (uint32_t*)wql, D_INR * D_LAT / 4);
    wsplit_kernel<<<(2 * D_INR * D_LAT / 4 + 255) / 256, 256, 0, s2>>>(
        (const float4*)Wlkv, (uint32_t*)wlkvh, (uint32_t*)wlkvl, 2 * D_INR * D_LAT / 4);
    wsplit_kernel<<<(D_LAT * D_INR / 4 + 255) / 256, 256, 0, s2>>>(
        (const float4*)Wo, (uint32_t*)woh, (uint32_t*)wol, D_LAT * D_INR / 4);
    {
        dim3 g(D_INR / 128, (B_ * M_LAT) / 128);
        gemm_mma_kernel<<<g, 256, GEMM_SMEM, s2>>>(lnh, wqh, wql, nullptr, nullptr, qn_g,
                                                   Qhp, Qlp, nullptr, nullptr,
                                                   B_ * M_LAT, D_INR, D_LAT, M_LAT, 0, 2);
    }
    {
        dim3 g((2 * D_INR) / 128, (B_ * M_LAT) / 128);
        gemm_mma_kernel<<<g, 256, GEMM_SMEM, s2>>>(lnh, wlkvh, wlkvl, nullptr, nullptr, kn_g,
                                                   Khp, Klp, Vhp, Vlp,
                                                   B_ * M_LAT, 2 * D_INR, D_LAT, M_LAT, N_X, 1);
    }

    // ---- join ----
    cudaEventRecord(evJ, s2);
    cudaStreamWaitEvent(0, evJ, 0);

    // ---- stream 0: attention -> output projection ----
    {
        dim3 g(M_LAT / QTILE, HEADS, B_);
        attn_mma_kernel<<<g, 128, ATT_SMEM>>>(Qhp, Qlp, Khp, Klp, Vhp, Vlp, mask, atth);
    }
    {
        dim3 g(D_LAT / 128, (B_ * M_LAT) / 128);
        gemm_mma_kernel<<<g, 256, GEMM_SMEM>>>(atth, woh, wol, bo, outp, nullptr,
                                               nullptr, nullptr, nullptr, nullptr,
                                               B_ * M_LAT, D_LAT, D_INR, 0, 0, 0);
    }
}

// round 11
// speedup vs baseline: 4.5564x; 1.0464x over previous
#include <cuda_runtime.h>
#include <cuda_bf16.h>
#include <cuda_fp16.h>
#include <cstdint>
#include <cstddef>

// ---------------- problem constants ----------------
#define B_    4
#define N_X   4096
#define M_LAT 512
#define D_IN  768
#define D_LAT 1024
#define D_INR 1024
#define HEADS 16
#define DH    64
#define L_TOT (N_X + M_LAT)   // 4608

// ---------------- scratch (no allocs allowed) ----------------
__device__ __half g_xn_h [(size_t)B_ * N_X  * D_IN ];
__device__ __half g_ln_h [(size_t)B_ * M_LAT * D_LAT];
__device__ __half g_att_h[(size_t)B_ * M_LAT * D_INR];
__device__ __half g_wq_h [(size_t)D_INR * D_LAT],      g_wq_l [(size_t)D_INR * D_LAT];
__device__ __half g_wkv_h[(size_t)2 * D_INR * D_IN],   g_wkv_l[(size_t)2 * D_INR * D_IN];
__device__ __half g_wlkv_h[(size_t)2 * D_INR * D_LAT], g_wlkv_l[(size_t)2 * D_INR * D_LAT];
__device__ __half g_wo_h [(size_t)D_LAT * D_INR],      g_wo_l [(size_t)D_LAT * D_INR];
__device__ __half g_Kh[(size_t)B_ * L_TOT * D_INR], g_Kl[(size_t)B_ * L_TOT * D_INR];
__device__ __half g_Vh[(size_t)B_ * L_TOT * D_INR], g_Vl[(size_t)B_ * L_TOT * D_INR];
__device__ __half g_Qh[(size_t)B_ * M_LAT * D_INR], g_Ql[(size_t)B_ * M_LAT * D_INR];

__device__ __forceinline__ uint32_t smem_u32(const void* p) {
    uint32_t a;
    asm("{ .reg .u64 t; cvta.to.shared.u64 t, %1; cvt.u32.u64 %0, t; }" : "=r"(a) : "l"(p));
    return a;
}
__device__ __forceinline__ uint32_t pack_h(__half a, __half b) {
    return ((uint32_t)__half_as_ushort(b) << 16) | __half_as_ushort(a);
}

#define LDMX4(r0_, r1_, r2_, r3_, addr_) \
    asm volatile("ldmatrix.sync.aligned.m8n8.x4.shared.b16 {%0,%1,%2,%3}, [%4];" \
        : "=r"(r0_), "=r"(r1_), "=r"(r2_), "=r"(r3_) : "r"(addr_))
#define LDMX4T(r0_, r1_, r2_, r3_, addr_) \
    asm volatile("ldmatrix.sync.aligned.m8n8.x4.trans.shared.b16 {%0,%1,%2,%3}, [%4];" \
        : "=r"(r0_), "=r"(r1_), "=r"(r2_), "=r"(r3_) : "r"(addr_))
#define MMA_F16(c_, a_, b0_, b1_) \
    asm volatile("mma.sync.aligned.m16n8k16.row.col.f32.f16.f16.f32 " \
        "{%0,%1,%2,%3}, {%4,%5,%6,%7}, {%8,%9}, {%0,%1,%2,%3};" \
        : "+f"((c_)[0]), "+f"((c_)[1]), "+f"((c_)[2]), "+f"((c_)[3]) \
        : "r"((a_)[0]), "r"((a_)[1]), "r"((a_)[2]), "r"((a_)[3]), "r"(b0_), "r"(b1_))
#define CP_ASYNC8(dst_, src_) \
    asm volatile("cp.async.ca.shared.global [%0], [%1], 8;" :: "r"(dst_), "l"(src_) : "memory")
#define CP_ASYNC16(dst_, src_) \
    asm volatile("cp.async.cg.shared.global [%0], [%1], 16;" :: "r"(dst_), "l"(src_) : "memory")
#define CP_COMMIT() asm volatile("cp.async.commit_group;" ::: "memory")
#define CP_WAIT(n_)  asm volatile("cp.async.wait_group %0;" :: "n"(n_) : "memory")

// =======================================================================
// fp16 2-product GEMM, cp.async 4-stage, fused epilogues.
// MMA products issued as full h-pass then l-pass: 16 independent accs
// between dependent MMAs on the same accumulator.
// =======================================================================
#define LDSB 40
#define GT_BYTES (128 * LDSB * 2)
#define STAGE_BYTES (3 * GT_BYTES)
#define NSTAGE 4
#define GEMM_SMEM (NSTAGE * STAGE_BYTES)

__device__ __forceinline__ void copy_stage(const __half* __restrict__ A,
                                           const __half* __restrict__ Wh,
                                           const __half* __restrict__ Wl,
                                           int K, int k0, uint32_t base, int tid) {
    const int chunk = tid & 7, row0 = tid >> 3;
    #pragma unroll
    for (int p = 0; p < 4; ++p) {
        const int r = row0 + p * 32;
        const uint32_t d = base + (uint32_t)(r * 80 + chunk * 8);
        const size_t s = (size_t)r * K + k0 + chunk * 4;
        CP_ASYNC8(d,                A + s);
        CP_ASYNC8(d + GT_BYTES,     Wh + s);
        CP_ASYNC8(d + 2 * GT_BYTES, Wl + s);
    }
}

__global__ void __launch_bounds__(256, 1) gemm_mma_kernel(
    const __half* __restrict__ A, const __half* __restrict__ Wh,
    const __half* __restrict__ Wl, const float* __restrict__ bias,
    float* __restrict__ C, const float* __restrict__ gamma,
    __half* __restrict__ P0h, __half* __restrict__ P0l,
    __half* __restrict__ P1h, __half* __restrict__ P1l,
    int M, int N, int K, int R, int roff, int mode) {
    extern __shared__ __align__(16) char gsm[];
    __shared__ float sred[8][4][2][8];
    const uint32_t u0 = smem_u32(gsm);
    const int tid = threadIdx.x;
    const int lane = tid & 31, wid = tid >> 5;
    const int warp_m = wid & 1, warp_n = wid >> 1;

    const __half* Ag  = A  + (size_t)blockIdx.y * 128 * K;
    const __half* Whg = Wh + (size_t)blockIdx.x * 128 * K;
    const __half* Wlg = Wl + (size_t)blockIdx.x * 128 * K;

    const int a_m = (lane & 7) + ((lane >> 3) & 1) * 8;
    const int a_k = (lane >> 4) * 8;
    const int b_n = (lane & 7) + (lane >> 4) * 8;
    const int b_k = ((lane >> 3) & 1) * 8;

    float acc[4][4][4];
    #pragma unroll
    for (int i = 0; i < 4; i++)
        #pragma unroll
        for (int j = 0; j < 4; j++)
            #pragma unroll
            for (int t = 0; t < 4; t++) acc[i][j][t] = 0.f;

    const int NK = K / 32;
    #pragma unroll
    for (int s = 0; s < NSTAGE - 1; ++s) {
        if (s < NK) copy_stage(Ag, Whg, Wlg, K, s * 32, u0 + s * STAGE_BYTES, tid);
        CP_COMMIT();
    }

    for (int c = 0; c < NK; ++c) {
        CP_WAIT(NSTAGE - 2);
        __syncthreads();
        const uint32_t co = (uint32_t)(c % NSTAGE) * STAGE_BYTES;
        const uint32_t uA = u0 + co, uBh = u0 + co + GT_BYTES, uBl = u0 + co + 2 * GT_BYTES;
        #pragma unroll
        for (int ks = 0; ks < 2; ++ks) {
            uint32_t ah[4][4], bh[2][4], bl[2][4];
            #pragma unroll
            for (int mt = 0; mt < 4; ++mt) {
                uint32_t off = (uint32_t)((warp_m * 64 + mt * 16 + a_m) * LDSB + ks * 16 + a_k) * 2;
                LDMX4(ah[mt][0], ah[mt][1], ah[mt][2], ah[mt][3], uA + off);
            }
            #pragma unroll
            for (int np = 0; np < 2; ++np) {
                uint32_t off = (uint32_t)((warp_n * 32 + np * 16 + b_n) * LDSB + ks * 16 + b_k) * 2;
                LDMX4(bh[np][0], bh[np][1], bh[np][2], bh[np][3], uBh + off);
                LDMX4(bl[np][0], bl[np][1], bl[np][2], bl[np][3], uBl + off);
            }
            // h-pass: 16 independent accumulators
            #pragma unroll
            for (int mt = 0; mt < 4; ++mt)
                #pragma unroll
                for (int nt = 0; nt < 4; ++nt) {
                    const int np = nt >> 1, sel = (nt & 1) * 2;
                    MMA_F16(acc[mt][nt], ah[mt], bh[np][sel], bh[np][sel + 1]);
                }
            // l-pass
            #pragma unroll
            for (int mt = 0; mt < 4; ++mt)
                #pragma unroll
                for (int nt = 0; nt < 4; ++nt) {
                    const int np = nt >> 1, sel = (nt & 1) * 2;
                    MMA_F16(acc[mt][nt], ah[mt], bl[np][sel], bl[np][sel + 1]);
                }
        }
        if (c + NSTAGE - 1 < NK)
            copy_stage(Ag, Whg, Wlg, K, (c + NSTAGE - 1) * 32,
                       u0 + (uint32_t)((c + NSTAGE - 1) % NSTAGE) * STAGE_BYTES, tid);
        CP_COMMIT();
    }

    const int g = lane >> 2, c2 = (lane & 3) * 2;
    const int rowb = blockIdx.y * 128 + warp_m * 64;
    const int colb = blockIdx.x * 128 + warp_n * 32;

    if (mode == 0) {
        #pragma unroll
        for (int mt = 0; mt < 4; ++mt) {
            #pragma unroll
            for (int nt = 0; nt < 4; ++nt) {
                int row = rowb + mt * 16 + g;
                int col = colb + nt * 8 + c2;
                float b0 = 0.f, b1 = 0.f;
                if (bias) { b0 = bias[col]; b1 = bias[col + 1]; }
                *(float2*)(C + (size_t)row * N + col) =
                    make_float2(acc[mt][nt][0] + b0, acc[mt][nt][1] + b1);
                *(float2*)(C + (size_t)(row + 8) * N + col) =
                    make_float2(acc[mt][nt][2] + b0, acc[mt][nt][3] + b1);
            }
        }
        return;
    }

    // modes 1/2: hi/lo split epilogue with optional rmsnorm (uniform per block).
    const bool needNorm = (mode == 2) || (colb < 1024);
    float rr[4][2] = {{1.f,1.f},{1.f,1.f},{1.f,1.f},{1.f,1.f}};
    if (needNorm) {
        __syncthreads();
        #pragma unroll
        for (int mt = 0; mt < 4; ++mt) {
            float s0 = 0.f, s1 = 0.f;
            #pragma unroll
            for (int nt = 0; nt < 4; ++nt) {
                s0 += acc[mt][nt][0] * acc[mt][nt][0] + acc[mt][nt][1] * acc[mt][nt][1];
                s1 += acc[mt][nt][2] * acc[mt][nt][2] + acc[mt][nt][3] * acc[mt][nt][3];
            }
            s0 += __shfl_xor_sync(0xffffffffu, s0, 1);
            s0 += __shfl_xor_sync(0xffffffffu, s0, 2);
            s1 += __shfl_xor_sync(0xffffffffu, s1, 1);
            s1 += __shfl_xor_sync(0xffffffffu, s1, 2);
            if ((lane & 3) == 0) { sred[wid][mt][0][g] = s0; sred[wid][mt][1][g] = s1; }
        }
        __syncthreads();
        const int pw = wid ^ 2;
        const float sb = (mode == 2) ? 0.125f : 1.0f;
        #pragma unroll
        for (int mt = 0; mt < 4; ++mt) {
            float t0 = sred[wid][mt][0][g] + sred[pw][mt][0][g];
            float t1 = sred[wid][mt][1][g] + sred[pw][mt][1][g];
            rr[mt][0] = sb / fmaxf(sqrtf(t0) * 0.125f, 1e-8f);
            rr[mt][1] = sb / fmaxf(sqrtf(t1) * 0.125f, 1e-8f);
        }
    }

    __half *Dh, *Dl;
    int cofs;
    size_t drow_base;
    if (mode == 1) {
        if (colb < 1024) { Dh = P0h; Dl = P0l; cofs = 0; }
        else             { Dh = P1h; Dl = P1l; cofs = 1024; }
        const int b0 = rowb / R;
        drow_base = (size_t)b0 * L_TOT + roff + (rowb - b0 * R);
    } else {
        Dh = P0h; Dl = P0l; cofs = 0;
        drow_base = (size_t)rowb;
    }

    #pragma unroll
    for (int mt = 0; mt < 4; ++mt) {
        #pragma unroll
        for (int nt = 0; nt < 4; ++nt) {
            const int col = colb + nt * 8 + c2;
            float ga = 1.f, gb = 1.f;
            if (needNorm) { ga = gamma[col & 63]; gb = gamma[(col + 1) & 63]; }
            const float v0 = acc[mt][nt][0] * rr[mt][0] * ga;
            const float v1 = acc[mt][nt][1] * rr[mt][0] * gb;
            const float v2 = acc[mt][nt][2] * rr[mt][1] * ga;
            const float v3 = acc[mt][nt][3] * rr[mt][1] * gb;
            const size_t prow = drow_base + mt * 16 + g;
            const size_t d0 = prow * D_INR + (col - cofs);
            const size_t d1 = (prow + 8) * D_INR + (col - cofs);
            __half h0 = __float2half_rn(v0), h1 = __float2half_rn(v1);
            __half h2 = __float2half_rn(v2), h3 = __float2half_rn(v3);
            *(uint32_t*)(Dh + d0) = pack_h(h0, h1);
            *(uint32_t*)(Dh + d1) = pack_h(h2, h3);
            *(uint32_t*)(Dl + d0) = pack_h(__float2half_rn(v0 - __half2float(h0)),
                                           __float2half_rn(v1 - __half2float(h1)));
            *(uint32_t*)(Dl + d1) = pack_h(__float2half_rn(v2 - __half2float(h2)),
                                           __float2half_rn(v3 - __half2float(h3)));
        }
    }
}

// ---------------- weight hi/lo split ----------------
__global__ void wsplit_kernel(const float4* __restrict__ W, uint32_t* __restrict__ Wh,
                              uint32_t* __restrict__ Wl, int n4) {
    int i = blockIdx.x * blockDim.x + threadIdx.x;
    if (i >= n4) return;
    float4 v = W[i];
    __half h0 = __float2half_rn(v.x), h1 = __float2half_rn(v.y);
    __half h2 = __float2half_rn(v.z), h3 = __float2half_rn(v.w);
    __half l0 = __float2half_rn(v.x - __half2float(h0));
    __half l1 = __float2half_rn(v.y - __half2float(h1));
    __half l2 = __float2half_rn(v.z - __half2float(h2));
    __half l3 = __float2half_rn(v.w - __half2float(h3));
    Wh[i * 2]     = pack_h(h0, h1); Wh[i * 2 + 1] = pack_h(h2, h3);
    Wl[i * 2]     = pack_h(l0, l1); Wl[i * 2 + 1] = pack_h(l2, l3);
}

// ---------------- layernorm -> fp16 ----------------
__global__ void layernorm_kernel(const float* __restrict__ in, __half* __restrict__ out,
                                 const float* __restrict__ g, const float* __restrict__ b,
                                 int C) {
    const int row = blockIdx.x;
    const float* x = in + (size_t)row * C;
    __half* y = out + (size_t)row * C;
    float s = 0.f, ss = 0.f;
    for (int i = threadIdx.x; i < C; i += blockDim.x) {
        float v = x[i]; s += v; ss += v * v;
    }
    __shared__ float red[2][32];
    #pragma unroll
    for (int o = 16; o; o >>= 1) {
        s  += __shfl_xor_sync(0xffffffffu, s,  o);
        ss += __shfl_xor_sync(0xffffffffu, ss, o);
    }
    int warp = threadIdx.x >> 5, lane = threadIdx.x & 31;
    if (lane == 0) { red[0][warp] = s; red[1][warp] = ss; }
    __syncthreads();
    int nw = blockDim.x >> 5;
    if (warp == 0) {
        s  = (lane < nw) ? red[0][lane] : 0.f;
        ss = (lane < nw) ? red[1][lane] : 0.f;
        #pragma unroll
        for (int o = 16; o; o >>= 1) {
            s  += __shfl_xor_sync(0xffffffffu, s,  o);
            ss += __shfl_xor_sync(0xffffffffu, ss, o);
        }
        if (lane == 0) { red[0][0] = s; red[1][0] = ss; }
    }
    __syncthreads();
    float invC = 1.f / (float)C;
    float mu  = red[0][0] * invC;
    float var = red[1][0] * invC - mu * mu;
    float rs  = rsqrtf(var + 1e-5f);
    for (int i = threadIdx.x; i < C; i += blockDim.x)
        y[i] = __float2half_rn((x[i] - mu) * rs * g[i] + b[i]);
}

// =======================================================================
// flash attention: QTILE=64, 128 threads, 2 CTAs/SM.
// QK 3-product (exp-sensitive), PV 2-product (P fp16-rounded).
// MMA pairs alternate accumulators (dep distance 2).
// =======================================================================
#define QTILE 64
#define LDA 72
#define AST_BYTES 37376
#define ATT_SMEM (18432 + 2 * AST_BYTES)

__device__ __forceinline__ void att_stage_copy(
    uint32_t sb, const __half* __restrict__ Kh, const __half* __restrict__ Kl,
    const __half* __restrict__ Vh, const __half* __restrict__ Vl,
    const int* __restrict__ mask, size_t grow0, int hoff,
    int in_x, int mrow0, int tid) {
    #pragma unroll
    for (int i = 0; i < 16; ++i) {
        const int plane = i >> 2;
        const int sub = ((i & 3) << 7) + tid;
        const int row = sub >> 3, ch = sub & 7;
        const __half* base = (plane == 0) ? Kh : (plane == 1) ? Kl : (plane == 2) ? Vh : Vl;
        const __half* src = base + (grow0 + row) * (size_t)D_INR + hoff + ch * 8;
        const uint32_t dst = sb + (uint32_t)(plane * 9216 + row * 144 + ch * 16);
        CP_ASYNC16(dst, src);
    }
    if (in_x && tid < 16)
        CP_ASYNC16(sb + 36864 + tid * 16, mask + mrow0 + tid * 4);
}

__global__ void __launch_bounds__(128, 2) attn_mma_kernel(
    const __half* __restrict__ Qhp, const __half* __restrict__ Qlp,
    const __half* __restrict__ Khp, const __half* __restrict__ Klp,
    const __half* __restrict__ Vhp, const __half* __restrict__ Vlp,
    const int* __restrict__ mask, __half* __restrict__ out) {
    extern __shared__ __align__(16) char asmem[];
    const uint32_t u0 = smem_u32(asmem);
    const uint32_t uQh = u0, uQl = u0 + 9216;
    const uint32_t uST = u0 + 18432;

    const int qt = blockIdx.x, h = blockIdx.y, b = blockIdx.z;
    const int tid = threadIdx.x, lane = tid & 31, wid = tid >> 5;
    const int hoff = h * DH;
    const size_t qrow0 = (size_t)(b * M_LAT + qt * QTILE);
    const size_t brow0 = (size_t)b * L_TOT;

    #pragma unroll
    for (int i = 0; i < 8; ++i) {
        const int plane = i >> 2;
        const int sub = ((i & 3) << 7) + tid;
        const int row = sub >> 3, ch = sub & 7;
        const __half* src = (plane ? Qlp : Qhp) + (qrow0 + row) * (size_t)D_INR + hoff + ch * 8;
        const uint32_t dst = (plane ? uQl : uQh) + (uint32_t)(row * 144 + ch * 16);
        CP_ASYNC16(dst, src);
    }
    CP_COMMIT();
    att_stage_copy(uST, Khp, Klp, Vhp, Vlp, mask, brow0, hoff, 1, b * N_X, tid);
    CP_COMMIT();
    CP_WAIT(1);
    __syncthreads();

    const int a_m = (lane & 7) + ((lane >> 3) & 1) * 8;
    const int a_k = (lane >> 4) * 8;
    uint32_t qh[4][4], ql[4][4];
    #pragma unroll
    for (int kc = 0; kc < 4; ++kc) {
        uint32_t off = (uint32_t)((wid * 16 + a_m) * LDA + kc * 16 + a_k) * 2;
        LDMX4(qh[kc][0], qh[kc][1], qh[kc][2], qh[kc][3], uQh + off);
        LDMX4(ql[kc][0], ql[kc][1], ql[kc][2], ql[kc][3], uQl + off);
    }

    float m0 = -3.0e38f, m8 = -3.0e38f, l0 = 0.f, l8 = 0.f;
    float O[8][4];
    #pragma unroll
    for (int i = 0; i < 8; ++i)
        #pragma unroll
        for (int j = 0; j < 4; ++j) O[i][j] = 0.f;

    const int b_n = (lane & 7) + (lane >> 4) * 8;
    const int b_k = ((lane >> 3) & 1) * 8;
    const int v_r = a_m;
    const int v_c = (lane >> 4) * 8;
    const int cq = (lane & 3) * 2;

    const int NT = L_TOT / 64;
    for (int t = 0; t < NT; ++t) {
        const int j0 = t * 64;
        const bool in_x = (j0 < N_X);
        __syncthreads();
        if (t + 1 < NT) {
            const int j1 = j0 + 64;
            att_stage_copy(uST + (uint32_t)((t + 1) & 1) * AST_BYTES,
                           Khp, Klp, Vhp, Vlp, mask, brow0 + j1, hoff,
                           (j1 < N_X) ? 1 : 0, b * N_X + j1, tid);
        }
        CP_COMMIT();
        CP_WAIT(1);
        __syncthreads();

        const uint32_t sb = uST + (uint32_t)(t & 1) * AST_BYTES;
        const uint32_t uKh = sb, uKl = sb + 9216, uVh = sb + 18432, uVl = sb + 27648;
        const int* mi = (const int*)(asmem + (18432 + (size_t)(t & 1) * AST_BYTES + 36864));

        float S[8][4];
        #pragma unroll
        for (int i = 0; i < 8; ++i) { S[i][0] = S[i][1] = S[i][2] = S[i][3] = 0.f; }
        #pragma unroll
        for (int kc = 0; kc < 4; ++kc) {
            #pragma unroll
            for (int ng = 0; ng < 4; ++ng) {
                uint32_t kh4[4], kl4[4];
                uint32_t off = (uint32_t)((ng * 16 + b_n) * LDA + kc * 16 + b_k) * 2;
                LDMX4(kh4[0], kh4[1], kh4[2], kh4[3], uKh + off);
                LDMX4(kl4[0], kl4[1], kl4[2], kl4[3], uKl + off);
                // alternate accumulators: dep distance 2
                MMA_F16(S[2 * ng],     qh[kc], kh4[0], kh4[1]);
                MMA_F16(S[2 * ng + 1], qh[kc], kh4[2], kh4[3]);
                MMA_F16(S[2 * ng],     qh[kc], kl4[0], kl4[1]);
                MMA_F16(S[2 * ng + 1], qh[kc], kl4[2], kl4[3]);
                MMA_F16(S[2 * ng],     ql[kc], kh4[0], kh4[1]);
                MMA_F16(S[2 * ng + 1], ql[kc], kh4[2], kh4[3]);
            }
        }
        if (in_x) {
            #pragma unroll
            for (int nt = 0; nt < 8; ++nt) {
                float a0 = mi[nt * 8 + cq]     ? 0.f : -3.0e38f;
                float a1 = mi[nt * 8 + cq + 1] ? 0.f : -3.0e38f;
                S[nt][0] += a0; S[nt][1] += a1; S[nt][2] += a0; S[nt][3] += a1;
            }
        }
        float mx0 = -3.0e38f, mx8 = -3.0e38f;
        #pragma unroll
        for (int nt = 0; nt < 8; ++nt) {
            mx0 = fmaxf(mx0, fmaxf(S[nt][0], S[nt][1]));
            mx8 = fmaxf(mx8, fmaxf(S[nt][2], S[nt][3]));
        }
        mx0 = fmaxf(mx0, __shfl_xor_sync(0xffffffffu, mx0, 1));
        mx0 = fmaxf(mx0, __shfl_xor_sync(0xffffffffu, mx0, 2));
        mx8 = fmaxf(mx8, __shfl_xor_sync(0xffffffffu, mx8, 1));
        mx8 = fmaxf(mx8, __shfl_xor_sync(0xffffffffu, mx8, 2));
        float mn0 = fmaxf(m0, mx0), mn8 = fmaxf(m8, mx8);
        float c0r = __expf(m0 - mn0), c8r = __expf(m8 - mn8);
        m0 = mn0; m8 = mn8;
        float rs0 = 0.f, rs8 = 0.f;
        uint32_t ph[4][4];
        #pragma unroll
        for (int nt = 0; nt < 8; ++nt) {
            float p0 = __expf(S[nt][0] - m0), p1 = __expf(S[nt][1] - m0);
            float p2 = __expf(S[nt][2] - m8), p3 = __expf(S[nt][3] - m8);
            rs0 += p0 + p1; rs8 += p2 + p3;
            const int kcI = nt >> 1, ap = (nt & 1) * 2;
            ph[kcI][ap]     = pack_h(__float2half_rn(p0), __float2half_rn(p1));
            ph[kcI][ap + 1] = pack_h(__float2half_rn(p2), __float2half_rn(p3));
        }
        rs0 += __shfl_xor_sync(0xffffffffu, rs0, 1);
        rs0 += __shfl_xor_sync(0xffffffffu, rs0, 2);
        rs8 += __shfl_xor_sync(0xffffffffu, rs8, 1);
        rs8 += __shfl_xor_sync(0xffffffffu, rs8, 2);
        l0 = l0 * c0r + rs0;
        l8 = l8 * c8r + rs8;
        #pragma unroll
        for (int dt = 0; dt < 8; ++dt) {
            O[dt][0] *= c0r; O[dt][1] *= c0r;
            O[dt][2] *= c8r; O[dt][3] *= c8r;
        }
        // O += P(h) @ (Vh + Vl)  — 2-product, alternate accumulators
        #pragma unroll
        for (int kc = 0; kc < 4; ++kc) {
            #pragma unroll
            for (int dg = 0; dg < 4; ++dg) {
                uint32_t vh4[4], vl4[4];
                uint32_t off = (uint32_t)((kc * 16 + v_r) * LDA + dg * 16 + v_c) * 2;
                LDMX4T(vh4[0], vh4[1], vh4[2], vh4[3], uVh + off);
                LDMX4T(vl4[0], vl4[1], vl4[2], vl4[3], uVl + off);
                MMA_F16(O[2 * dg],     ph[kc], vh4[0], vh4[1]);
                MMA_F16(O[2 * dg + 1], ph[kc], vh4[2], vh4[3]);
                MMA_F16(O[2 * dg],     ph[kc], vl4[0], vl4[1]);
                MMA_F16(O[2 * dg + 1], ph[kc], vl4[2], vl4[3]);
            }
        }
    }

    const float inv0 = 1.f / l0, inv8 = 1.f / l8;
    const int g = lane >> 2;
    __half* ob = out + ((size_t)(b * M_LAT + qt * QTILE + wid * 16 + g)) * D_INR + hoff;
    #pragma unroll
    for (int dt = 0; dt < 8; ++dt) {
        int col = dt * 8 + cq;
        *(__half2*)(ob + col) = __floats2half2_rn(O[dt][0] * inv0, O[dt][1] * inv0);
        *(__half2*)(ob + (size_t)8 * D_INR + col) = __floats2half2_rn(O[dt][2] * inv8, O[dt][3] * inv8);
    }
}

// ---------------- launch ----------------
extern "C" void kernel_launch(void* const* d_in, const int* in_sizes, int n_in,
                              void* d_out, int out_size) {
    const float* x      = (const float*)d_in[0];
    const float* lat    = (const float*)d_in[1];
    const int*   mask   = (const int*)  d_in[2];
    const float* ln_x_g = (const float*)d_in[3];
    const float* ln_x_b = (const float*)d_in[4];
    const float* ln_l_g = (const float*)d_in[5];
    const float* ln_l_b = (const float*)d_in[6];
    const float* qn_g   = (const float*)d_in[7];
    const float* kn_g   = (const float*)d_in[8];
    const float* Wq     = (const float*)d_in[9];
    const float* Wkv    = (const float*)d_in[10];
    const float* Wlkv   = (const float*)d_in[11];
    const float* Wo     = (const float*)d_in[12];
    const float* bo     = (const float*)d_in[13];
    float* outp = (float*)d_out;

    __half *xnh, *lnh, *atth, *wqh, *wql, *wkvh, *wkvl, *wlkvh, *wlkvl, *woh, *wol;
    __half *Khp, *Klp, *Vhp, *Vlp, *Qhp, *Qlp;
    cudaGetSymbolAddress((void**)&xnh,  g_xn_h);
    cudaGetSymbolAddress((void**)&lnh,  g_ln_h);
    cudaGetSymbolAddress((void**)&atth, g_att_h);
    cudaGetSymbolAddress((void**)&wqh,  g_wq_h);   cudaGetSymbolAddress((void**)&wql,  g_wq_l);
    cudaGetSymbolAddress((void**)&wkvh, g_wkv_h);  cudaGetSymbolAddress((void**)&wkvl, g_wkv_l);
    cudaGetSymbolAddress((void**)&wlkvh,g_wlkv_h); cudaGetSymbolAddress((void**)&wlkvl,g_wlkv_l);
    cudaGetSymbolAddress((void**)&woh,  g_wo_h);   cudaGetSymbolAddress((void**)&wol,  g_wo_l);
    cudaGetSymbolAddress((void**)&Khp,  g_Kh);     cudaGetSymbolAddress((void**)&Klp,  g_Kl);
    cudaGetSymbolAddress((void**)&Vhp,  g_Vh);     cudaGetSymbolAddress((void**)&Vlp,  g_Vl);
    cudaGetSymbolAddress((void**)&Qhp,  g_Qh);     cudaGetSymbolAddress((void**)&Qlp,  g_Ql);

    cudaFuncSetAttribute(gemm_mma_kernel, cudaFuncAttributeMaxDynamicSharedMemorySize, GEMM_SMEM);
    cudaFuncSetAttribute(attn_mma_kernel, cudaFuncAttributeMaxDynamicSharedMemorySize, ATT_SMEM);

    cudaStream_t s2;
    cudaStreamCreateWithFlags(&s2, cudaStreamNonBlocking);
    cudaEvent_t evF, evJ;
    cudaEventCreateWithFlags(&evF, cudaEventDisableTiming);
    cudaEventCreateWithFlags(&evJ, cudaEventDisableTiming);
    cudaEventRecord(evF, 0);
    cudaStreamWaitEvent(s2, evF, 0);

    // ---- stream 0 (x branch) ----
    layernorm_kernel<<<B_ * N_X, 256>>>(x, xnh, ln_x_g, ln_x_b, D_IN);
    wsplit_kernel<<<(2 * D_INR * D_IN / 4 + 255) / 256, 256>>>(
        (const float4*)Wkv, (uint32_t*)wkvh, (uint32_t*)wkvl, 2 * D_INR * D_IN / 4);
    {
        dim3 g((2 * D_INR) / 128, (B_ * N_X) / 128);
        gemm_mma_kernel<<<g, 256, GEMM_SMEM>>>(xnh, wkvh, wkvl, nullptr, nullptr, kn_g,
                                               Khp, Klp, Vhp, Vlp,
                                               B_ * N_X, 2 * D_INR, D_IN, N_X, 0, 1);
    }

    // ---- stream s2 (lat branch) ----
    layernorm_kernel<<<B_ * M_LAT, 256, 0, s2>>>(lat, lnh, ln_l_g, ln_l_b, D_LAT);
    wsplit_kernel<<<(D_INR * D_LAT / 4 + 255) / 256, 256, 0, s2>>>(
        (const float4*)Wq, (uint32_t*)wqh, (uint32_t*)wql, D_INR * D_LAT / 4);
    wsplit_kernel<<<(2 * D_INR * D_LAT / 4 + 255) / 256, 256, 0, s2>>>(
        (const float4*)Wlkv, (uint32_t*)wlkvh, (uint32_t*)wlkvl, 2 * D_INR * D_LAT / 4);
    wsplit_kernel<<<(D_LAT * D_INR / 4 + 255) / 256, 256, 0, s2>>>(
        (const float4*)Wo, (uint32_t*)woh, (uint32_t*)wol, D_LAT * D_INR / 4);
    {
        dim3 g(D_INR / 128, (B_ * M_LAT) / 128);
        gemm_mma_kernel<<<g, 256, GEMM_SMEM, s2>>>(lnh, wqh, wql, nullptr, nullptr, qn_g,
                                                   Qhp, Qlp, nullptr, nullptr,
                                                   B_ * M_LAT, D_INR, D_LAT, M_LAT, 0, 2);
    }
    {
        dim3 g((2 * D_INR) / 128, (B_ * M_LAT) / 128);
        gemm_mma_kernel<<<g, 256, GEMM_SMEM, s2>>>(lnh, wlkvh, wlkvl, nullptr, nullptr, kn_g,
                                                   Khp, Klp, Vhp, Vlp,
                                                   B_ * M_LAT, 2 * D_INR, D_LAT, M_LAT, N_X, 1);
    }

    // ---- join ----
    cudaEventRecord(evJ, s2);
    cudaStreamWaitEvent(0, evJ, 0);

    // ---- stream 0: attention -> output projection ----
    {
        dim3 g(M_LAT / QTILE, HEADS, B_);
        attn_mma_kernel<<<g, 128, ATT_SMEM>>>(Qhp, Qlp, Khp, Klp, Vhp, Vlp, mask, atth);
    }
    {
        dim3 g(D_LAT / 128, (B_ * M_LAT) / 128);
        gemm_mma_kernel<<<g, 256, GEMM_SMEM>>>(atth, woh, wol, bo, outp, nullptr,
                                               nullptr, nullptr, nullptr, nullptr,
                                               B_ * M_LAT, D_LAT, D_INR, 0, 0, 0);
    }
}